// round 4
// baseline (speedup 1.0000x reference)
#include <cuda_runtime.h>

#define S_LEN 2048
#define EMB   1024
#define NH    16
#define HD    64
#define BATCH 2
#define ROWS  (BATCH * S_LEN)   // 4096
#define PITCH 68                // smem row pitch (floats) to dodge bank conflicts

// Scratch (allocation-free rule: __device__ globals)
__device__ float g_q[ROWS * EMB];
__device__ float g_k[ROWS * EMB];
__device__ float g_v[ROWS * EMB];
__device__ float g_att[ROWS * EMB];

// ---------------------------------------------------------------------------
// C[4096,1024] = A[4096,1024] @ W[1024,1024] (+ optional bias)
// 64x64 block tile, K-tile 16, 256 threads, 4x4 microtile.
// ---------------------------------------------------------------------------
__global__ void __launch_bounds__(256) gemm64(const float* __restrict__ A,
                                              const float* __restrict__ W,
                                              const float* __restrict__ bias,
                                              float* __restrict__ C)
{
    __shared__ float As[16][64];   // transposed A tile: As[k][m]
    __shared__ float Ws[16][64];   // Ws[k][n]

    const int tid = threadIdx.x;
    const int tx  = tid & 15, ty = tid >> 4;
    const int row0 = blockIdx.y * 64, col0 = blockIdx.x * 64;

    const int am = tid >> 2;             // 0..63
    const int ak = (tid & 3) << 2;       // 0,4,8,12
    const int wk = tid >> 4;             // 0..15
    const int wn = (tid & 15) << 2;      // 0..60

    float acc[4][4] = {};

    for (int k0 = 0; k0 < EMB; k0 += 16) {
        float4 av = *(const float4*)(A + (size_t)(row0 + am) * EMB + k0 + ak);
        As[ak + 0][am] = av.x;
        As[ak + 1][am] = av.y;
        As[ak + 2][am] = av.z;
        As[ak + 3][am] = av.w;
        *(float4*)&Ws[wk][wn] = *(const float4*)(W + (size_t)(k0 + wk) * EMB + col0 + wn);
        __syncthreads();

        #pragma unroll
        for (int k = 0; k < 16; k++) {
            float4 a4 = *(float4*)&As[k][ty << 2];
            float4 b4 = *(float4*)&Ws[k][tx << 2];
            float ar[4] = {a4.x, a4.y, a4.z, a4.w};
            float br[4] = {b4.x, b4.y, b4.z, b4.w};
            #pragma unroll
            for (int i = 0; i < 4; i++)
                #pragma unroll
                for (int j = 0; j < 4; j++)
                    acc[i][j] = fmaf(ar[i], br[j], acc[i][j]);
        }
        __syncthreads();
    }

    #pragma unroll
    for (int i = 0; i < 4; i++) {
        #pragma unroll
        for (int j = 0; j < 4; j++) {
            float v = acc[i][j];
            if (bias) v += bias[col0 + (tx << 2) + j];
            C[(size_t)(row0 + (ty << 2) + i) * EMB + col0 + (tx << 2) + j] = v;
        }
    }
}

// ---------------------------------------------------------------------------
// Flash attention, causal. One block = one (batch, head, 64-row q tile).
// Q/K/V layout: [B*S, H*D] row-major (straight out of QKV GEMMs).
// Online softmax; K tiles only up to the diagonal (causal tile skipping).
// ---------------------------------------------------------------------------
__global__ void __launch_bounds__(256) flash64(const float* __restrict__ Q,
                                               const float* __restrict__ K,
                                               const float* __restrict__ V,
                                               float* __restrict__ O)
{
    extern __shared__ float sm[];
    float* Qs = sm;                     // [64][PITCH]
    float* Ks = sm + 64 * PITCH;
    float* Vs = sm + 2 * 64 * PITCH;
    float* Ps = sm + 3 * 64 * PITCH;

    const int tid = threadIdx.x;
    const int tx  = tid & 15, ty = tid >> 4;
    const int tx4 = tx << 2, ty4 = ty << 2;
    const int qt = blockIdx.x;           // 0..31
    const int h  = blockIdx.y;           // 0..15
    const int b  = blockIdx.z;           // 0..1
    const int q0 = qt * 64;
    const size_t base = ((size_t)b * S_LEN) * EMB + (size_t)h * HD;

    // Load Q tile (64x64 floats) as float4
    #pragma unroll
    for (int it = 0; it < 4; it++) {
        int idx = tid + it * 256;            // float4 index 0..1023
        int r = idx >> 4, c4 = (idx & 15) << 2;
        *(float4*)&Qs[r * PITCH + c4] =
            *(const float4*)(Q + base + (size_t)(q0 + r) * EMB + c4);
    }

    float m[4], l[4], o[4][4];
    #pragma unroll
    for (int i = 0; i < 4; i++) {
        m[i] = -1e30f; l[i] = 0.f;
        #pragma unroll
        for (int j = 0; j < 4; j++) o[i][j] = 0.f;
    }

    for (int kt = 0; kt <= qt; kt++) {
        const int k0 = kt * 64;
        __syncthreads();   // protect Ks/Vs/Ps from prior-iter readers; orders Qs on iter 0
        #pragma unroll
        for (int it = 0; it < 4; it++) {
            int idx = tid + it * 256;
            int r = idx >> 4, c4 = (idx & 15) << 2;
            *(float4*)&Ks[r * PITCH + c4] =
                *(const float4*)(K + base + (size_t)(k0 + r) * EMB + c4);
            *(float4*)&Vs[r * PITCH + c4] =
                *(const float4*)(V + base + (size_t)(k0 + r) * EMB + c4);
        }
        __syncthreads();

        // S = Q K^T for this tile (4x4 per thread)
        float s[4][4] = {};
        #pragma unroll 4
        for (int d4 = 0; d4 < 64; d4 += 4) {
            float4 qv[4], kv[4];
            #pragma unroll
            for (int i = 0; i < 4; i++) qv[i] = *(float4*)&Qs[(ty4 + i) * PITCH + d4];
            #pragma unroll
            for (int j = 0; j < 4; j++) kv[j] = *(float4*)&Ks[(tx4 + j) * PITCH + d4];
            #pragma unroll
            for (int i = 0; i < 4; i++)
                #pragma unroll
                for (int j = 0; j < 4; j++)
                    s[i][j] += qv[i].x * kv[j].x + qv[i].y * kv[j].y +
                               qv[i].z * kv[j].z + qv[i].w * kv[j].w;
        }

        // scale + causal mask
        #pragma unroll
        for (int i = 0; i < 4; i++)
            #pragma unroll
            for (int j = 0; j < 4; j++) {
                float sv = s[i][j] * 0.125f;   // 1/sqrt(64)
                if (k0 + tx4 + j > q0 + ty4 + i) sv = -1e30f;
                s[i][j] = sv;
            }

        // online softmax per row (row stats shared across the 16 tx lanes)
        #pragma unroll
        for (int i = 0; i < 4; i++) {
            float rm = fmaxf(fmaxf(s[i][0], s[i][1]), fmaxf(s[i][2], s[i][3]));
            #pragma unroll
            for (int off = 8; off > 0; off >>= 1)
                rm = fmaxf(rm, __shfl_xor_sync(0xffffffffu, rm, off, 16));
            float mn   = fmaxf(m[i], rm);
            float corr = __expf(m[i] - mn);
            float rs = 0.f;
            #pragma unroll
            for (int j = 0; j < 4; j++) {
                float p = __expf(s[i][j] - mn);
                s[i][j] = p;
                rs += p;
            }
            #pragma unroll
            for (int off = 8; off > 0; off >>= 1)
                rs += __shfl_xor_sync(0xffffffffu, rs, off, 16);
            l[i] = l[i] * corr + rs;
            m[i] = mn;
            #pragma unroll
            for (int j = 0; j < 4; j++) o[i][j] *= corr;
        }

        // stage P to smem for the P@V product
        #pragma unroll
        for (int i = 0; i < 4; i++)
            *(float4*)&Ps[(ty4 + i) * PITCH + tx4] =
                make_float4(s[i][0], s[i][1], s[i][2], s[i][3]);
        __syncthreads();

        // O += P @ V
        #pragma unroll 4
        for (int c = 0; c < 64; c++) {
            float4 vv = *(float4*)&Vs[c * PITCH + tx4];
            float pv[4];
            #pragma unroll
            for (int i = 0; i < 4; i++) pv[i] = Ps[(ty4 + i) * PITCH + c];
            #pragma unroll
            for (int i = 0; i < 4; i++) {
                o[i][0] = fmaf(pv[i], vv.x, o[i][0]);
                o[i][1] = fmaf(pv[i], vv.y, o[i][1]);
                o[i][2] = fmaf(pv[i], vv.z, o[i][2]);
                o[i][3] = fmaf(pv[i], vv.w, o[i][3]);
            }
        }
    }

    // normalize + write out ([B*S, H*D] layout, ready for the out-proj GEMM)
    #pragma unroll
    for (int i = 0; i < 4; i++) {
        float inv = 1.f / l[i];
        *(float4*)(O + base + (size_t)(q0 + ty4 + i) * EMB + tx4) =
            make_float4(o[i][0] * inv, o[i][1] * inv, o[i][2] * inv, o[i][3] * inv);
    }
}

// ---------------------------------------------------------------------------
extern "C" void kernel_launch(void* const* d_in, const int* in_sizes, int n_in,
                              void* d_out, int out_size)
{
    (void)in_sizes; (void)n_in; (void)out_size;
    const float* x  = (const float*)d_in[0];
    const float* Wq = (const float*)d_in[1];
    const float* Wk = (const float*)d_in[2];
    const float* Wv = (const float*)d_in[3];
    const float* Wp = (const float*)d_in[4];
    const float* bp = (const float*)d_in[5];
    float* out = (float*)d_out;

    float *q, *k, *v, *att;
    cudaGetSymbolAddress((void**)&q,   g_q);
    cudaGetSymbolAddress((void**)&k,   g_k);
    cudaGetSymbolAddress((void**)&v,   g_v);
    cudaGetSymbolAddress((void**)&att, g_att);

    const int smem_bytes = 4 * 64 * PITCH * (int)sizeof(float);  // 69632
    cudaFuncSetAttribute(flash64, cudaFuncAttributeMaxDynamicSharedMemorySize, smem_bytes);

    dim3 gg(EMB / 64, ROWS / 64);          // (16, 64)
    gemm64<<<gg, 256>>>(x, Wq, nullptr, q);
    gemm64<<<gg, 256>>>(x, Wk, nullptr, k);
    gemm64<<<gg, 256>>>(x, Wv, nullptr, v);

    dim3 gf(S_LEN / 64, NH, BATCH);        // (32, 16, 2)
    flash64<<<gf, 256, smem_bytes>>>(q, k, v, att);

    gemm64<<<gg, 256>>>(att, Wp, bp, out);
}

// round 8
// speedup vs baseline: 1.4651x; 1.4651x over previous
#include <cuda_runtime.h>
#include <cuda_bf16.h>
#include <cstdint>

#define S_LEN 2048
#define EMB   1024
#define NH    16
#define HD    64
#define BATCH 2
#define ROWS  (BATCH * S_LEN)   // 4096
#define PITCH 68

// ---------------------------------------------------------------------------
// Scratch (__device__ globals: allocation-free rule)
// ---------------------------------------------------------------------------
__device__ float g_q[ROWS * EMB];
__device__ float g_k[ROWS * EMB];
__device__ float g_v[ROWS * EMB];
__device__ float g_att[ROWS * EMB];

__device__ __nv_bfloat16 g_xh[ROWS * EMB], g_xl[ROWS * EMB];   // split x
__device__ __nv_bfloat16 g_ah[ROWS * EMB], g_al[ROWS * EMB];   // split att
__device__ __nv_bfloat16 g_wqh[EMB * EMB], g_wql[EMB * EMB];   // W^T splits
__device__ __nv_bfloat16 g_wkh[EMB * EMB], g_wkl[EMB * EMB];
__device__ __nv_bfloat16 g_wvh[EMB * EMB], g_wvl[EMB * EMB];
__device__ __nv_bfloat16 g_wph[EMB * EMB], g_wpl[EMB * EMB];

// ---------------------------------------------------------------------------
// Generic-PTX helpers (NO tcgen05/TMEM: harness PTX target is family sm_103)
// ---------------------------------------------------------------------------
__device__ __forceinline__ uint32_t smem_u32(const void* p) {
    uint32_t a;
    asm("{ .reg .u64 t; cvta.to.shared.u64 t, %1; cvt.u32.u64 %0, t; }" : "=r"(a) : "l"(p));
    return a;
}

#define LDSM_X4(r, a)                                                          \
    asm volatile("ldmatrix.sync.aligned.m8n8.x4.shared.b16 {%0,%1,%2,%3}, [%4];" \
                 : "=r"((r)[0]), "=r"((r)[1]), "=r"((r)[2]), "=r"((r)[3])      \
                 : "r"(a))

#define MMA16816(d, a, b)                                                      \
    asm volatile("mma.sync.aligned.m16n8k16.row.col.f32.bf16.bf16.f32 "        \
                 "{%0,%1,%2,%3}, {%4,%5,%6,%7}, {%8,%9}, {%0,%1,%2,%3};"       \
                 : "+f"((d)[0]), "+f"((d)[1]), "+f"((d)[2]), "+f"((d)[3])      \
                 : "r"((a)[0]), "r"((a)[1]), "r"((a)[2]), "r"((a)[3]),         \
                   "r"((b)[0]), "r"((b)[1]))

#define CP_ASYNC16(saddr, gaddr)                                               \
    asm volatile("cp.async.cg.shared.global [%0], [%1], 16;"                   \
                 :: "r"(saddr), "l"(gaddr))
#define CP_COMMIT()  asm volatile("cp.async.commit_group;" ::: "memory")
#define CP_WAIT0()   asm volatile("cp.async.wait_group 0;" ::: "memory")

// ---------------------------------------------------------------------------
// Split fp32 -> bf16 hi + bf16 lo
// ---------------------------------------------------------------------------
__global__ void __launch_bounds__(256) split_bf16(const float* __restrict__ s,
                                                  __nv_bfloat16* __restrict__ hi,
                                                  __nv_bfloat16* __restrict__ lo)
{
    int i = (blockIdx.x * 256 + threadIdx.x) * 2;
    float2 v = *(const float2*)(s + i);
    __nv_bfloat16 h0 = __float2bfloat16_rn(v.x);
    __nv_bfloat16 l0 = __float2bfloat16_rn(v.x - __bfloat162float(h0));
    __nv_bfloat16 h1 = __float2bfloat16_rn(v.y);
    __nv_bfloat16 l1 = __float2bfloat16_rn(v.y - __bfloat162float(h1));
    __nv_bfloat162 ph; ph.x = h0; ph.y = h1;
    __nv_bfloat162 pl; pl.x = l0; pl.y = l1;
    *(__nv_bfloat162*)(hi + i) = ph;
    *(__nv_bfloat162*)(lo + i) = pl;
}

// ---------------------------------------------------------------------------
// W[K,N] -> W^T[N,K] with bf16 hi/lo split
// ---------------------------------------------------------------------------
__global__ void __launch_bounds__(256) transpose_split(const float* __restrict__ W,
                                                       __nv_bfloat16* __restrict__ Th,
                                                       __nv_bfloat16* __restrict__ Tl)
{
    __shared__ float t[32][33];
    int n0 = blockIdx.x * 32, k0 = blockIdx.y * 32;
    int tx = threadIdx.x & 31, ty = threadIdx.x >> 5;
    #pragma unroll
    for (int i = 0; i < 32; i += 8)
        t[ty + i][tx] = W[(size_t)(k0 + ty + i) * EMB + n0 + tx];
    __syncthreads();
    #pragma unroll
    for (int i = 0; i < 32; i += 8) {
        float v = t[tx][ty + i];
        __nv_bfloat16 h = __float2bfloat16_rn(v);
        __nv_bfloat16 l = __float2bfloat16_rn(v - __bfloat162float(h));
        size_t o = (size_t)(n0 + ty + i) * EMB + k0 + tx;
        Th[o] = h;
        Tl[o] = l;
    }
}

// ---------------------------------------------------------------------------
// HMMA GEMM: C[4096,1024] = A @ W.  A [M,K] row-major bf16 hi/lo,
// B = W^T [N,K] row-major bf16 hi/lo (".col" operand directly).
// 128x128 CTA tile, BK=32, 8 warps in 2(m) x 4(n), warp tile 64x32.
// cp.async double-buffered smem; 3-term split MMA (hh + hl + lh), fp32 acc.
// ---------------------------------------------------------------------------
#define BK      32
#define NKT     (EMB / BK)            // 32
#define TPITCH  80                    // bytes per 64B row (conflict-free ldmatrix)
#define TILE_B  (128 * TPITCH)        // 10240
#define AH_OFF  0
#define AL_OFF  (TILE_B)
#define BH_OFF  (2 * TILE_B)
#define BL_OFF  (3 * TILE_B)
#define STAGE_B (4 * TILE_B)          // 40960
#define GEMM_SMEM (2 * STAGE_B)       // 81920

__device__ __forceinline__ void stage_load(uint32_t sb,
                                           const __nv_bfloat16* __restrict__ Ahi,
                                           const __nv_bfloat16* __restrict__ Alo,
                                           const __nv_bfloat16* __restrict__ Bhi,
                                           const __nv_bfloat16* __restrict__ Blo,
                                           int row0, int col0, int k0, int tid)
{
    // each tile: 128 rows x 32 bf16 (64B). 512 x 16B chunks, 2 per thread.
    #pragma unroll
    for (int it = 0; it < 2; it++) {
        int idx = it * 256 + tid;
        int row = idx >> 2, c = idx & 3;
        size_t goff = (size_t)row * EMB + k0 + c * 8;
        uint32_t soff = (uint32_t)(row * TPITCH + c * 16);
        CP_ASYNC16(sb + AH_OFF + soff, Ahi + (size_t)row0 * EMB + goff);
        CP_ASYNC16(sb + AL_OFF + soff, Alo + (size_t)row0 * EMB + goff);
        CP_ASYNC16(sb + BH_OFF + soff, Bhi + (size_t)col0 * EMB + goff);
        CP_ASYNC16(sb + BL_OFF + soff, Blo + (size_t)col0 * EMB + goff);
    }
}

__global__ void __launch_bounds__(256) gemm_mma(const __nv_bfloat16* __restrict__ Ahi,
                                                const __nv_bfloat16* __restrict__ Alo,
                                                const __nv_bfloat16* __restrict__ Bhi,
                                                const __nv_bfloat16* __restrict__ Blo,
                                                const float* __restrict__ bias,
                                                float* __restrict__ C)
{
    extern __shared__ char dynsm[];
    const uint32_t smbase = smem_u32(dynsm);

    const int tid  = threadIdx.x;
    const int lane = tid & 31;
    const int warp = tid >> 5;
    const int wm   = warp & 1;        // 0..1  (64 rows each)
    const int wn   = warp >> 1;       // 0..3  (32 cols each)
    const int row0 = blockIdx.y * 128;
    const int col0 = blockIdx.x * 128;

    float acc[4][4][4];
    #pragma unroll
    for (int i = 0; i < 4; i++)
        #pragma unroll
        for (int j = 0; j < 4; j++)
            #pragma unroll
            for (int r = 0; r < 4; r++) acc[i][j][r] = 0.f;

    // per-lane ldmatrix base offsets (row = lane&15, khalf = lane>>4)
    const uint32_t lmA = (uint32_t)((wm * 64 + (lane & 15)) * TPITCH + ((lane >> 4) << 4));
    const uint32_t lmB = (uint32_t)((wn * 32 + (lane & 15)) * TPITCH + ((lane >> 4) << 4));

    // prologue
    stage_load(smbase, Ahi, Alo, Bhi, Blo, row0, col0, 0, tid);
    CP_COMMIT();

    #pragma unroll 1
    for (int t = 0; t < NKT; t++) {
        const uint32_t sb = smbase + (uint32_t)(t & 1) * STAGE_B;
        CP_WAIT0();
        __syncthreads();
        if (t + 1 < NKT) {
            stage_load(smbase + (uint32_t)((t + 1) & 1) * STAGE_B,
                       Ahi, Alo, Bhi, Blo, row0, col0, (t + 1) * BK, tid);
            CP_COMMIT();
        }

        #pragma unroll
        for (int ks = 0; ks < 2; ks++) {
            const uint32_t ko = (uint32_t)(ks * 32);
            uint32_t ah[4][4], al[4][4];
            #pragma unroll
            for (int mf = 0; mf < 4; mf++) {
                LDSM_X4(ah[mf], sb + AH_OFF + lmA + (uint32_t)(mf * 16 * TPITCH) + ko);
                LDSM_X4(al[mf], sb + AL_OFF + lmA + (uint32_t)(mf * 16 * TPITCH) + ko);
            }
            uint32_t bh[4][2], bl[4][2];
            #pragma unroll
            for (int ng = 0; ng < 2; ng++) {
                uint32_t tmp[4];
                LDSM_X4(tmp, sb + BH_OFF + lmB + (uint32_t)(ng * 16 * TPITCH) + ko);
                bh[2 * ng][0] = tmp[0]; bh[2 * ng + 1][0] = tmp[1];
                bh[2 * ng][1] = tmp[2]; bh[2 * ng + 1][1] = tmp[3];
                LDSM_X4(tmp, sb + BL_OFF + lmB + (uint32_t)(ng * 16 * TPITCH) + ko);
                bl[2 * ng][0] = tmp[0]; bl[2 * ng + 1][0] = tmp[1];
                bl[2 * ng][1] = tmp[2]; bl[2 * ng + 1][1] = tmp[3];
            }
            #pragma unroll
            for (int mf = 0; mf < 4; mf++)
                #pragma unroll
                for (int nf = 0; nf < 4; nf++) {
                    MMA16816(acc[mf][nf], ah[mf], bh[nf]);   // hi*hi
                    MMA16816(acc[mf][nf], ah[mf], bl[nf]);   // hi*lo
                    MMA16816(acc[mf][nf], al[mf], bh[nf]);   // lo*hi
                }
        }
    }

    // epilogue: write fp32 accumulators
    #pragma unroll
    for (int mf = 0; mf < 4; mf++) {
        #pragma unroll
        for (int nf = 0; nf < 4; nf++) {
            int r  = row0 + wm * 64 + mf * 16 + (lane >> 2);
            int cb = col0 + wn * 32 + nf * 8 + (lane & 3) * 2;
            float b0 = 0.f, b1 = 0.f;
            if (bias) { b0 = bias[cb]; b1 = bias[cb + 1]; }
            *(float2*)(C + (size_t)r * EMB + cb) =
                make_float2(acc[mf][nf][0] + b0, acc[mf][nf][1] + b1);
            *(float2*)(C + (size_t)(r + 8) * EMB + cb) =
                make_float2(acc[mf][nf][2] + b0, acc[mf][nf][3] + b1);
        }
    }
}

// ---------------------------------------------------------------------------
// Flash attention (unchanged passing baseline)
// ---------------------------------------------------------------------------
__global__ void __launch_bounds__(256) flash64(const float* __restrict__ Q,
                                               const float* __restrict__ K,
                                               const float* __restrict__ V,
                                               float* __restrict__ O)
{
    extern __shared__ float sm[];
    float* Qs = sm;
    float* Ks = sm + 64 * PITCH;
    float* Vs = sm + 2 * 64 * PITCH;
    float* Ps = sm + 3 * 64 * PITCH;

    const int tid = threadIdx.x;
    const int tx  = tid & 15, ty = tid >> 4;
    const int tx4 = tx << 2, ty4 = ty << 2;
    const int qt = blockIdx.x;
    const int h  = blockIdx.y;
    const int b  = blockIdx.z;
    const int q0 = qt * 64;
    const size_t base = ((size_t)b * S_LEN) * EMB + (size_t)h * HD;

    #pragma unroll
    for (int it = 0; it < 4; it++) {
        int idx = tid + it * 256;
        int r = idx >> 4, c4 = (idx & 15) << 2;
        *(float4*)&Qs[r * PITCH + c4] =
            *(const float4*)(Q + base + (size_t)(q0 + r) * EMB + c4);
    }

    float m[4], l[4], o[4][4];
    #pragma unroll
    for (int i = 0; i < 4; i++) {
        m[i] = -1e30f; l[i] = 0.f;
        #pragma unroll
        for (int j = 0; j < 4; j++) o[i][j] = 0.f;
    }

    for (int kt = 0; kt <= qt; kt++) {
        const int k0 = kt * 64;
        __syncthreads();
        #pragma unroll
        for (int it = 0; it < 4; it++) {
            int idx = tid + it * 256;
            int r = idx >> 4, c4 = (idx & 15) << 2;
            *(float4*)&Ks[r * PITCH + c4] =
                *(const float4*)(K + base + (size_t)(k0 + r) * EMB + c4);
            *(float4*)&Vs[r * PITCH + c4] =
                *(const float4*)(V + base + (size_t)(k0 + r) * EMB + c4);
        }
        __syncthreads();

        float s[4][4] = {};
        #pragma unroll 4
        for (int d4 = 0; d4 < 64; d4 += 4) {
            float4 qv[4], kv[4];
            #pragma unroll
            for (int i = 0; i < 4; i++) qv[i] = *(float4*)&Qs[(ty4 + i) * PITCH + d4];
            #pragma unroll
            for (int j = 0; j < 4; j++) kv[j] = *(float4*)&Ks[(tx4 + j) * PITCH + d4];
            #pragma unroll
            for (int i = 0; i < 4; i++)
                #pragma unroll
                for (int j = 0; j < 4; j++)
                    s[i][j] += qv[i].x * kv[j].x + qv[i].y * kv[j].y +
                               qv[i].z * kv[j].z + qv[i].w * kv[j].w;
        }

        #pragma unroll
        for (int i = 0; i < 4; i++)
            #pragma unroll
            for (int j = 0; j < 4; j++) {
                float sv = s[i][j] * 0.125f;
                if (k0 + tx4 + j > q0 + ty4 + i) sv = -1e30f;
                s[i][j] = sv;
            }

        #pragma unroll
        for (int i = 0; i < 4; i++) {
            float rm = fmaxf(fmaxf(s[i][0], s[i][1]), fmaxf(s[i][2], s[i][3]));
            #pragma unroll
            for (int off = 8; off > 0; off >>= 1)
                rm = fmaxf(rm, __shfl_xor_sync(0xffffffffu, rm, off, 16));
            float mn   = fmaxf(m[i], rm);
            float corr = __expf(m[i] - mn);
            float rs = 0.f;
            #pragma unroll
            for (int j = 0; j < 4; j++) {
                float p = __expf(s[i][j] - mn);
                s[i][j] = p;
                rs += p;
            }
            #pragma unroll
            for (int off = 8; off > 0; off >>= 1)
                rs += __shfl_xor_sync(0xffffffffu, rs, off, 16);
            l[i] = l[i] * corr + rs;
            m[i] = mn;
            #pragma unroll
            for (int j = 0; j < 4; j++) o[i][j] *= corr;
        }

        #pragma unroll
        for (int i = 0; i < 4; i++)
            *(float4*)&Ps[(ty4 + i) * PITCH + tx4] =
                make_float4(s[i][0], s[i][1], s[i][2], s[i][3]);
        __syncthreads();

        #pragma unroll 4
        for (int c = 0; c < 64; c++) {
            float4 vv = *(float4*)&Vs[c * PITCH + tx4];
            float pv[4];
            #pragma unroll
            for (int i = 0; i < 4; i++) pv[i] = Ps[(ty4 + i) * PITCH + c];
            #pragma unroll
            for (int i = 0; i < 4; i++) {
                o[i][0] = fmaf(pv[i], vv.x, o[i][0]);
                o[i][1] = fmaf(pv[i], vv.y, o[i][1]);
                o[i][2] = fmaf(pv[i], vv.z, o[i][2]);
                o[i][3] = fmaf(pv[i], vv.w, o[i][3]);
            }
        }
    }

    #pragma unroll
    for (int i = 0; i < 4; i++) {
        float inv = 1.f / l[i];
        *(float4*)(O + base + (size_t)(q0 + ty4 + i) * EMB + tx4) =
            make_float4(o[i][0] * inv, o[i][1] * inv, o[i][2] * inv, o[i][3] * inv);
    }
}

// ---------------------------------------------------------------------------
extern "C" void kernel_launch(void* const* d_in, const int* in_sizes, int n_in,
                              void* d_out, int out_size)
{
    (void)in_sizes; (void)n_in; (void)out_size;
    const float* x  = (const float*)d_in[0];
    const float* Wq = (const float*)d_in[1];
    const float* Wk = (const float*)d_in[2];
    const float* Wv = (const float*)d_in[3];
    const float* Wp = (const float*)d_in[4];
    const float* bp = (const float*)d_in[5];
    float* out = (float*)d_out;

    float *q, *k, *v, *att;
    cudaGetSymbolAddress((void**)&q,   g_q);
    cudaGetSymbolAddress((void**)&k,   g_k);
    cudaGetSymbolAddress((void**)&v,   g_v);
    cudaGetSymbolAddress((void**)&att, g_att);

    __nv_bfloat16 *xh, *xl, *ah, *al;
    __nv_bfloat16 *wqh, *wql, *wkh, *wkl, *wvh, *wvl, *wph, *wpl;
    cudaGetSymbolAddress((void**)&xh,  g_xh);  cudaGetSymbolAddress((void**)&xl,  g_xl);
    cudaGetSymbolAddress((void**)&ah,  g_ah);  cudaGetSymbolAddress((void**)&al,  g_al);
    cudaGetSymbolAddress((void**)&wqh, g_wqh); cudaGetSymbolAddress((void**)&wql, g_wql);
    cudaGetSymbolAddress((void**)&wkh, g_wkh); cudaGetSymbolAddress((void**)&wkl, g_wkl);
    cudaGetSymbolAddress((void**)&wvh, g_wvh); cudaGetSymbolAddress((void**)&wvl, g_wvl);
    cudaGetSymbolAddress((void**)&wph, g_wph); cudaGetSymbolAddress((void**)&wpl, g_wpl);

    const int flash_smem = 4 * 64 * PITCH * (int)sizeof(float);   // 69632
    cudaFuncSetAttribute(flash64, cudaFuncAttributeMaxDynamicSharedMemorySize, flash_smem);
    cudaFuncSetAttribute(gemm_mma, cudaFuncAttributeMaxDynamicSharedMemorySize, GEMM_SMEM);

    // 1. split activations + transpose-split weights
    split_bf16<<<ROWS * EMB / 512, 256>>>(x, xh, xl);
    dim3 gt(EMB / 32, EMB / 32);
    transpose_split<<<gt, 256>>>(Wq, wqh, wql);
    transpose_split<<<gt, 256>>>(Wk, wkh, wkl);
    transpose_split<<<gt, 256>>>(Wv, wvh, wvl);
    transpose_split<<<gt, 256>>>(Wp, wph, wpl);

    // 2. QKV projections on tensor cores (HMMA)
    dim3 gg(EMB / 128, ROWS / 128);    // (8, 32)
    gemm_mma<<<gg, 256, GEMM_SMEM>>>(xh, xl, wqh, wql, nullptr, q);
    gemm_mma<<<gg, 256, GEMM_SMEM>>>(xh, xl, wkh, wkl, nullptr, k);
    gemm_mma<<<gg, 256, GEMM_SMEM>>>(xh, xl, wvh, wvl, nullptr, v);

    // 3. causal flash attention (fp32 SIMT)
    dim3 gf(S_LEN / 64, NH, BATCH);
    flash64<<<gf, 256, flash_smem>>>(q, k, v, att);

    // 4. output projection on tensor cores
    split_bf16<<<ROWS * EMB / 512, 256>>>(att, ah, al);
    gemm_mma<<<gg, 256, GEMM_SMEM>>>(ah, al, wph, wpl, bp, out);
}

// round 9
// speedup vs baseline: 3.0090x; 2.0538x over previous
#include <cuda_runtime.h>
#include <cuda_bf16.h>
#include <cstdint>

#define S_LEN 2048
#define EMB   1024
#define NH    16
#define HD    64
#define BATCH 2
#define ROWS  (BATCH * S_LEN)   // 4096

// ---------------------------------------------------------------------------
// Scratch (__device__ globals: allocation-free rule)
// ---------------------------------------------------------------------------
__device__ __nv_bfloat16 g_xh[ROWS * EMB], g_xl[ROWS * EMB];   // split x
__device__ __nv_bfloat16 g_qh[ROWS * EMB], g_ql[ROWS * EMB];   // Q hi/lo
__device__ __nv_bfloat16 g_kh[ROWS * EMB], g_kl[ROWS * EMB];   // K hi/lo
__device__ __nv_bfloat16 g_vh[ROWS * EMB], g_vl[ROWS * EMB];   // V hi/lo
__device__ __nv_bfloat16 g_ah[ROWS * EMB], g_al[ROWS * EMB];   // att hi/lo
__device__ __nv_bfloat16 g_wqh[EMB * EMB], g_wql[EMB * EMB];   // W^T splits
__device__ __nv_bfloat16 g_wkh[EMB * EMB], g_wkl[EMB * EMB];
__device__ __nv_bfloat16 g_wvh[EMB * EMB], g_wvl[EMB * EMB];
__device__ __nv_bfloat16 g_wph[EMB * EMB], g_wpl[EMB * EMB];

// ---------------------------------------------------------------------------
// Generic-PTX helpers (NO tcgen05/TMEM: harness PTX target is family sm_103)
// ---------------------------------------------------------------------------
__device__ __forceinline__ uint32_t smem_u32(const void* p) {
    uint32_t a;
    asm("{ .reg .u64 t; cvta.to.shared.u64 t, %1; cvt.u32.u64 %0, t; }" : "=r"(a) : "l"(p));
    return a;
}

#define LDSM_X4(r, a)                                                          \
    asm volatile("ldmatrix.sync.aligned.m8n8.x4.shared.b16 {%0,%1,%2,%3}, [%4];" \
                 : "=r"((r)[0]), "=r"((r)[1]), "=r"((r)[2]), "=r"((r)[3])      \
                 : "r"(a))

#define LDSM_X4_T(r, a)                                                        \
    asm volatile("ldmatrix.sync.aligned.m8n8.x4.trans.shared.b16 {%0,%1,%2,%3}, [%4];" \
                 : "=r"((r)[0]), "=r"((r)[1]), "=r"((r)[2]), "=r"((r)[3])      \
                 : "r"(a))

#define MMA16816(d, a, b)                                                      \
    asm volatile("mma.sync.aligned.m16n8k16.row.col.f32.bf16.bf16.f32 "        \
                 "{%0,%1,%2,%3}, {%4,%5,%6,%7}, {%8,%9}, {%0,%1,%2,%3};"       \
                 : "+f"((d)[0]), "+f"((d)[1]), "+f"((d)[2]), "+f"((d)[3])      \
                 : "r"((a)[0]), "r"((a)[1]), "r"((a)[2]), "r"((a)[3]),         \
                   "r"((b)[0]), "r"((b)[1]))

#define CP_ASYNC16(saddr, gaddr)                                               \
    asm volatile("cp.async.cg.shared.global [%0], [%1], 16;"                   \
                 :: "r"(saddr), "l"(gaddr))
#define CP_COMMIT()  asm volatile("cp.async.commit_group;" ::: "memory")
#define CP_WAIT0()   asm volatile("cp.async.wait_group 0;" ::: "memory")

// split two floats -> packed bf16x2 hi + packed bf16x2 lo
__device__ __forceinline__ void split2(float p0, float p1, uint32_t& hi, uint32_t& lo) {
    __nv_bfloat16 h0 = __float2bfloat16_rn(p0);
    __nv_bfloat16 h1 = __float2bfloat16_rn(p1);
    __nv_bfloat16 l0 = __float2bfloat16_rn(p0 - __bfloat162float(h0));
    __nv_bfloat16 l1 = __float2bfloat16_rn(p1 - __bfloat162float(h1));
    __nv_bfloat162 H; H.x = h0; H.y = h1;
    __nv_bfloat162 L; L.x = l0; L.y = l1;
    hi = *(uint32_t*)&H; lo = *(uint32_t*)&L;
}

// ---------------------------------------------------------------------------
// Split fp32 -> bf16 hi + bf16 lo (for input x)
// ---------------------------------------------------------------------------
__global__ void __launch_bounds__(256) split_bf16(const float* __restrict__ s,
                                                  __nv_bfloat16* __restrict__ hi,
                                                  __nv_bfloat16* __restrict__ lo)
{
    int i = (blockIdx.x * 256 + threadIdx.x) * 2;
    float2 v = *(const float2*)(s + i);
    uint32_t h, l;
    split2(v.x, v.y, h, l);
    *(uint32_t*)(hi + i) = h;
    *(uint32_t*)(lo + i) = l;
}

// ---------------------------------------------------------------------------
// W[K,N] -> W^T[N,K] with bf16 hi/lo split
// ---------------------------------------------------------------------------
__global__ void __launch_bounds__(256) transpose_split(const float* __restrict__ W,
                                                       __nv_bfloat16* __restrict__ Th,
                                                       __nv_bfloat16* __restrict__ Tl)
{
    __shared__ float t[32][33];
    int n0 = blockIdx.x * 32, k0 = blockIdx.y * 32;
    int tx = threadIdx.x & 31, ty = threadIdx.x >> 5;
    #pragma unroll
    for (int i = 0; i < 32; i += 8)
        t[ty + i][tx] = W[(size_t)(k0 + ty + i) * EMB + n0 + tx];
    __syncthreads();
    #pragma unroll
    for (int i = 0; i < 32; i += 8) {
        float v = t[tx][ty + i];
        __nv_bfloat16 h = __float2bfloat16_rn(v);
        __nv_bfloat16 l = __float2bfloat16_rn(v - __bfloat162float(h));
        size_t o = (size_t)(n0 + ty + i) * EMB + k0 + tx;
        Th[o] = h;
        Tl[o] = l;
    }
}

// ---------------------------------------------------------------------------
// HMMA GEMM: C = A @ W. 128x128 CTA tile, BK=32, 8 warps (2m x 4n), 64x32 warp
// tile, cp.async double buffer, 3-term hi/lo split MMA, fp32 acc.
// Epilogue: either fp32 C (+bias) or direct bf16 hi/lo split (Ch/Cl).
// ---------------------------------------------------------------------------
#define BK      32
#define NKT     (EMB / BK)            // 32
#define TPITCH  80
#define TILE_B  (128 * TPITCH)
#define AH_OFF  0
#define AL_OFF  (TILE_B)
#define BH_OFF  (2 * TILE_B)
#define BL_OFF  (3 * TILE_B)
#define STAGE_B (4 * TILE_B)
#define GEMM_SMEM (2 * STAGE_B)       // 81920

__device__ __forceinline__ void stage_load(uint32_t sb,
                                           const __nv_bfloat16* __restrict__ Ahi,
                                           const __nv_bfloat16* __restrict__ Alo,
                                           const __nv_bfloat16* __restrict__ Bhi,
                                           const __nv_bfloat16* __restrict__ Blo,
                                           int row0, int col0, int k0, int tid)
{
    #pragma unroll
    for (int it = 0; it < 2; it++) {
        int idx = it * 256 + tid;
        int row = idx >> 2, c = idx & 3;
        size_t goff = (size_t)row * EMB + k0 + c * 8;
        uint32_t soff = (uint32_t)(row * TPITCH + c * 16);
        CP_ASYNC16(sb + AH_OFF + soff, Ahi + (size_t)row0 * EMB + goff);
        CP_ASYNC16(sb + AL_OFF + soff, Alo + (size_t)row0 * EMB + goff);
        CP_ASYNC16(sb + BH_OFF + soff, Bhi + (size_t)col0 * EMB + goff);
        CP_ASYNC16(sb + BL_OFF + soff, Blo + (size_t)col0 * EMB + goff);
    }
}

__global__ void __launch_bounds__(256) gemm_mma(const __nv_bfloat16* __restrict__ Ahi,
                                                const __nv_bfloat16* __restrict__ Alo,
                                                const __nv_bfloat16* __restrict__ Bhi,
                                                const __nv_bfloat16* __restrict__ Blo,
                                                const float* __restrict__ bias,
                                                float* __restrict__ C,
                                                __nv_bfloat16* __restrict__ Ch,
                                                __nv_bfloat16* __restrict__ Cl)
{
    extern __shared__ char dynsm[];
    const uint32_t smbase = smem_u32(dynsm);

    const int tid  = threadIdx.x;
    const int lane = tid & 31;
    const int warp = tid >> 5;
    const int wm   = warp & 1;
    const int wn   = warp >> 1;
    const int row0 = blockIdx.y * 128;
    const int col0 = blockIdx.x * 128;

    float acc[4][4][4];
    #pragma unroll
    for (int i = 0; i < 4; i++)
        #pragma unroll
        for (int j = 0; j < 4; j++)
            #pragma unroll
            for (int r = 0; r < 4; r++) acc[i][j][r] = 0.f;

    const uint32_t lmA = (uint32_t)((wm * 64 + (lane & 15)) * TPITCH + ((lane >> 4) << 4));
    const uint32_t lmB = (uint32_t)((wn * 32 + (lane & 15)) * TPITCH + ((lane >> 4) << 4));

    stage_load(smbase, Ahi, Alo, Bhi, Blo, row0, col0, 0, tid);
    CP_COMMIT();

    #pragma unroll 1
    for (int t = 0; t < NKT; t++) {
        const uint32_t sb = smbase + (uint32_t)(t & 1) * STAGE_B;
        CP_WAIT0();
        __syncthreads();
        if (t + 1 < NKT) {
            stage_load(smbase + (uint32_t)((t + 1) & 1) * STAGE_B,
                       Ahi, Alo, Bhi, Blo, row0, col0, (t + 1) * BK, tid);
            CP_COMMIT();
        }

        #pragma unroll
        for (int ks = 0; ks < 2; ks++) {
            const uint32_t ko = (uint32_t)(ks * 32);
            uint32_t ah[4][4], al[4][4];
            #pragma unroll
            for (int mf = 0; mf < 4; mf++) {
                LDSM_X4(ah[mf], sb + AH_OFF + lmA + (uint32_t)(mf * 16 * TPITCH) + ko);
                LDSM_X4(al[mf], sb + AL_OFF + lmA + (uint32_t)(mf * 16 * TPITCH) + ko);
            }
            uint32_t bh[4][2], bl[4][2];
            #pragma unroll
            for (int ng = 0; ng < 2; ng++) {
                uint32_t tmp[4];
                LDSM_X4(tmp, sb + BH_OFF + lmB + (uint32_t)(ng * 16 * TPITCH) + ko);
                bh[2 * ng][0] = tmp[0]; bh[2 * ng + 1][0] = tmp[1];
                bh[2 * ng][1] = tmp[2]; bh[2 * ng + 1][1] = tmp[3];
                LDSM_X4(tmp, sb + BL_OFF + lmB + (uint32_t)(ng * 16 * TPITCH) + ko);
                bl[2 * ng][0] = tmp[0]; bl[2 * ng + 1][0] = tmp[1];
                bl[2 * ng][1] = tmp[2]; bl[2 * ng + 1][1] = tmp[3];
            }
            #pragma unroll
            for (int mf = 0; mf < 4; mf++)
                #pragma unroll
                for (int nf = 0; nf < 4; nf++) {
                    MMA16816(acc[mf][nf], ah[mf], bh[nf]);
                    MMA16816(acc[mf][nf], ah[mf], bl[nf]);
                    MMA16816(acc[mf][nf], al[mf], bh[nf]);
                }
        }
    }

    #pragma unroll
    for (int mf = 0; mf < 4; mf++) {
        #pragma unroll
        for (int nf = 0; nf < 4; nf++) {
            int r  = row0 + wm * 64 + mf * 16 + (lane >> 2);
            int cb = col0 + wn * 32 + nf * 8 + (lane & 3) * 2;
            if (Ch) {
                uint32_t h, l;
                split2(acc[mf][nf][0], acc[mf][nf][1], h, l);
                *(uint32_t*)(Ch + (size_t)r * EMB + cb) = h;
                *(uint32_t*)(Cl + (size_t)r * EMB + cb) = l;
                split2(acc[mf][nf][2], acc[mf][nf][3], h, l);
                *(uint32_t*)(Ch + (size_t)(r + 8) * EMB + cb) = h;
                *(uint32_t*)(Cl + (size_t)(r + 8) * EMB + cb) = l;
            } else {
                float b0 = 0.f, b1 = 0.f;
                if (bias) { b0 = bias[cb]; b1 = bias[cb + 1]; }
                *(float2*)(C + (size_t)r * EMB + cb) =
                    make_float2(acc[mf][nf][0] + b0, acc[mf][nf][1] + b1);
                *(float2*)(C + (size_t)(r + 8) * EMB + cb) =
                    make_float2(acc[mf][nf][2] + b0, acc[mf][nf][3] + b1);
            }
        }
    }
}

// ---------------------------------------------------------------------------
// Tensor-core causal flash attention.
// CTA: 128 q-rows x (b,h); 8 warps, warp = 16 q-rows. k-tile 64.
// Q/K/V bf16 hi/lo in [B*S, H*D] layout. Output: att hi/lo bf16 (same layout).
// S = QK^T via 3-term split MMA; softmax fp32 in regs; P split in regs;
// O += P@V via 3-term split MMA with ldmatrix.trans on V.
// ---------------------------------------------------------------------------
#define QP    144                      // smem row pitch bytes (72 bf16)
#define KVT   (64 * QP)                // one 64x64 bf16 tile
#define FLASH_SMEM (2 * 128 * QP + 2 * 4 * KVT)   // Qh+Ql + 2 stages x 4 tiles = 110592

__device__ __forceinline__ void kv_stage(uint32_t sb,
                                         const __nv_bfloat16* __restrict__ Kh,
                                         const __nv_bfloat16* __restrict__ Kl,
                                         const __nv_bfloat16* __restrict__ Vh,
                                         const __nv_bfloat16* __restrict__ Vl,
                                         size_t gbase, int k0, int tid)
{
    #pragma unroll
    for (int it = 0; it < 2; it++) {
        int idx = it * 256 + tid;
        int row = idx >> 3, c = idx & 7;
        size_t g = gbase + (size_t)(k0 + row) * EMB + c * 8;
        uint32_t so = (uint32_t)(row * QP + c * 16);
        CP_ASYNC16(sb + 0 * KVT + so, Kh + g);
        CP_ASYNC16(sb + 1 * KVT + so, Kl + g);
        CP_ASYNC16(sb + 2 * KVT + so, Vh + g);
        CP_ASYNC16(sb + 3 * KVT + so, Vl + g);
    }
}

__global__ void __launch_bounds__(256) flash_mma(
    const __nv_bfloat16* __restrict__ Qh, const __nv_bfloat16* __restrict__ Ql,
    const __nv_bfloat16* __restrict__ Kh, const __nv_bfloat16* __restrict__ Kl,
    const __nv_bfloat16* __restrict__ Vh, const __nv_bfloat16* __restrict__ Vl,
    __nv_bfloat16* __restrict__ Oh, __nv_bfloat16* __restrict__ Ol)
{
    extern __shared__ char dynsm[];
    const uint32_t sQh = smem_u32(dynsm);
    const uint32_t sQl = sQh + 128 * QP;
    const uint32_t sKV = sQl + 128 * QP;

    const int tid  = threadIdx.x;
    const int lane = tid & 31;
    const int warp = tid >> 5;
    const int qt = blockIdx.x, h = blockIdx.y, b = blockIdx.z;
    const int q0 = qt * 128;
    const int wrow = warp * 16;
    const size_t gbase = ((size_t)b * S_LEN) * EMB + (size_t)h * HD;

    // Q tiles (hi+lo) via cp.async
    #pragma unroll
    for (int it = 0; it < 4; it++) {
        int idx = it * 256 + tid;
        int row = idx >> 3, c = idx & 7;
        size_t g = gbase + (size_t)(q0 + row) * EMB + c * 8;
        uint32_t so = (uint32_t)(row * QP + c * 16);
        CP_ASYNC16(sQh + so, Qh + g);
        CP_ASYNC16(sQl + so, Ql + g);
    }
    kv_stage(sKV, Kh, Kl, Vh, Vl, gbase, 0, tid);
    CP_COMMIT();

    const int nkt = 2 * qt + 2;

    uint32_t qfh[4][4], qfl[4][4];
    float o[8][4];
    float m[2] = {-1e30f, -1e30f}, l[2] = {0.f, 0.f};
    #pragma unroll
    for (int nb = 0; nb < 8; nb++)
        #pragma unroll
        for (int j = 0; j < 4; j++) o[nb][j] = 0.f;

    #pragma unroll 1
    for (int kt = 0; kt < nkt; kt++) {
        CP_WAIT0();
        __syncthreads();
        if (kt == 0) {
            // load Q A-frags once (proven gemm pattern)
            #pragma unroll
            for (int kc = 0; kc < 4; kc++) {
                uint32_t aq = (uint32_t)((wrow + (lane & 15)) * QP + ((lane >> 4) << 4) + kc * 32);
                LDSM_X4(qfh[kc], sQh + aq);
                LDSM_X4(qfl[kc], sQl + aq);
            }
        }
        if (kt + 1 < nkt) {
            kv_stage(sKV + (uint32_t)((kt + 1) & 1) * 4 * KVT, Kh, Kl, Vh, Vl,
                     gbase, (kt + 1) * 64, tid);
            CP_COMMIT();
        }

        const int k0 = kt * 64;
        if (k0 > q0 + wrow + 15) continue;   // fully masked for this warp (after barrier!)

        const uint32_t sb = sKV + (uint32_t)(kt & 1) * 4 * KVT;

        // ---- S = Q K^T (3-term split) ----
        float s[8][4];
        #pragma unroll
        for (int nb = 0; nb < 8; nb++)
            #pragma unroll
            for (int j = 0; j < 4; j++) s[nb][j] = 0.f;

        #pragma unroll
        for (int g2 = 0; g2 < 4; g2++) {
            #pragma unroll
            for (int kc = 0; kc < 4; kc++) {
                uint32_t a = sb + (uint32_t)((g2 * 16 + (lane & 15)) * QP + ((lane >> 4) << 4) + kc * 32);
                uint32_t kh4[4], kl4[4];
                LDSM_X4(kh4, a);             // Kh tile
                LDSM_X4(kl4, a + KVT);       // Kl tile
                uint32_t bh0[2] = {kh4[0], kh4[2]}, bh1[2] = {kh4[1], kh4[3]};
                uint32_t bl0[2] = {kl4[0], kl4[2]}, bl1[2] = {kl4[1], kl4[3]};
                MMA16816(s[2 * g2],     qfh[kc], bh0);
                MMA16816(s[2 * g2],     qfh[kc], bl0);
                MMA16816(s[2 * g2],     qfl[kc], bh0);
                MMA16816(s[2 * g2 + 1], qfh[kc], bh1);
                MMA16816(s[2 * g2 + 1], qfh[kc], bl1);
                MMA16816(s[2 * g2 + 1], qfl[kc], bh1);
            }
        }

        // ---- scale + causal mask ----
        const bool partial = (k0 + 63 > q0 + wrow);
        const int rg = q0 + wrow + (lane >> 2);
        #pragma unroll
        for (int nb = 0; nb < 8; nb++) {
            int c0 = k0 + nb * 8 + 2 * (lane & 3);
            #pragma unroll
            for (int j = 0; j < 4; j++) {
                float sv = s[nb][j] * 0.125f;
                if (partial && (c0 + (j & 1)) > (rg + (j >> 1) * 8)) sv = -1e30f;
                s[nb][j] = sv;
            }
        }

        // ---- online softmax (fp32) ----
        #pragma unroll
        for (int hf = 0; hf < 2; hf++) {
            const int j0 = hf * 2;
            float rm = -1e30f;
            #pragma unroll
            for (int nb = 0; nb < 8; nb++)
                rm = fmaxf(rm, fmaxf(s[nb][j0], s[nb][j0 + 1]));
            rm = fmaxf(rm, __shfl_xor_sync(0xffffffffu, rm, 1));
            rm = fmaxf(rm, __shfl_xor_sync(0xffffffffu, rm, 2));
            float mn   = fmaxf(m[hf], rm);
            float corr = __expf(m[hf] - mn);
            float rs = 0.f;
            #pragma unroll
            for (int nb = 0; nb < 8; nb++) {
                float p0 = __expf(s[nb][j0] - mn);
                float p1 = __expf(s[nb][j0 + 1] - mn);
                s[nb][j0] = p0; s[nb][j0 + 1] = p1;
                rs += p0 + p1;
            }
            rs += __shfl_xor_sync(0xffffffffu, rs, 1);
            rs += __shfl_xor_sync(0xffffffffu, rs, 2);
            l[hf] = l[hf] * corr + rs;
            m[hf] = mn;
            #pragma unroll
            for (int nb = 0; nb < 8; nb++) { o[nb][j0] *= corr; o[nb][j0 + 1] *= corr; }
        }

        // ---- P -> bf16 hi/lo A-frags (S C-frag maps onto PV A-frag) ----
        uint32_t ph[4][4], pl[4][4];
        #pragma unroll
        for (int kc = 0; kc < 4; kc++)
            #pragma unroll
            for (int t = 0; t < 4; t++) {
                int nb = 2 * kc + (t >> 1);
                int j0 = (t & 1) * 2;
                split2(s[nb][j0], s[nb][j0 + 1], ph[kc][t], pl[kc][t]);
            }

        // ---- O += P V (3-term split, V via ldmatrix.trans) ----
        #pragma unroll
        for (int g2 = 0; g2 < 4; g2++) {
            #pragma unroll
            for (int kc = 0; kc < 4; kc++) {
                // trans addressing: storage [seq, dim]; virtual B = V^T [dim, seq]
                uint32_t a = sb + 2 * KVT +
                    (uint32_t)((kc * 16 + (lane & 7) + ((lane >> 4) << 3)) * QP +
                               g2 * 32 + ((lane >> 3) & 1) * 16);
                uint32_t vh4[4], vl4[4];
                LDSM_X4_T(vh4, a);           // Vh tile
                LDSM_X4_T(vl4, a + KVT);     // Vl tile
                uint32_t bh0[2] = {vh4[0], vh4[2]}, bh1[2] = {vh4[1], vh4[3]};
                uint32_t bl0[2] = {vl4[0], vl4[2]}, bl1[2] = {vl4[1], vl4[3]};
                MMA16816(o[2 * g2],     ph[kc], bh0);
                MMA16816(o[2 * g2],     ph[kc], bl0);
                MMA16816(o[2 * g2],     pl[kc], bh0);
                MMA16816(o[2 * g2 + 1], ph[kc], bh1);
                MMA16816(o[2 * g2 + 1], ph[kc], bl1);
                MMA16816(o[2 * g2 + 1], pl[kc], bh1);
            }
        }
    }

    // ---- normalize + write att hi/lo bf16 ----
    #pragma unroll
    for (int hf = 0; hf < 2; hf++) {
        float inv = 1.f / l[hf];
        int grow = q0 + wrow + (lane >> 2) + hf * 8;
        size_t rb = gbase + (size_t)grow * EMB + 2 * (lane & 3);
        #pragma unroll
        for (int nb = 0; nb < 8; nb++) {
            uint32_t hv, lv;
            split2(o[nb][hf * 2] * inv, o[nb][hf * 2 + 1] * inv, hv, lv);
            *(uint32_t*)(Oh + rb + nb * 8) = hv;
            *(uint32_t*)(Ol + rb + nb * 8) = lv;
        }
    }
}

// ---------------------------------------------------------------------------
extern "C" void kernel_launch(void* const* d_in, const int* in_sizes, int n_in,
                              void* d_out, int out_size)
{
    (void)in_sizes; (void)n_in; (void)out_size;
    const float* x  = (const float*)d_in[0];
    const float* Wq = (const float*)d_in[1];
    const float* Wk = (const float*)d_in[2];
    const float* Wv = (const float*)d_in[3];
    const float* Wp = (const float*)d_in[4];
    const float* bp = (const float*)d_in[5];
    float* out = (float*)d_out;

    __nv_bfloat16 *xh, *xl, *qh, *ql, *kh, *kl, *vh, *vl, *ah, *al;
    __nv_bfloat16 *wqh, *wql, *wkh, *wkl, *wvh, *wvl, *wph, *wpl;
    cudaGetSymbolAddress((void**)&xh,  g_xh);  cudaGetSymbolAddress((void**)&xl,  g_xl);
    cudaGetSymbolAddress((void**)&qh,  g_qh);  cudaGetSymbolAddress((void**)&ql,  g_ql);
    cudaGetSymbolAddress((void**)&kh,  g_kh);  cudaGetSymbolAddress((void**)&kl,  g_kl);
    cudaGetSymbolAddress((void**)&vh,  g_vh);  cudaGetSymbolAddress((void**)&vl,  g_vl);
    cudaGetSymbolAddress((void**)&ah,  g_ah);  cudaGetSymbolAddress((void**)&al,  g_al);
    cudaGetSymbolAddress((void**)&wqh, g_wqh); cudaGetSymbolAddress((void**)&wql, g_wql);
    cudaGetSymbolAddress((void**)&wkh, g_wkh); cudaGetSymbolAddress((void**)&wkl, g_wkl);
    cudaGetSymbolAddress((void**)&wvh, g_wvh); cudaGetSymbolAddress((void**)&wvl, g_wvl);
    cudaGetSymbolAddress((void**)&wph, g_wph); cudaGetSymbolAddress((void**)&wpl, g_wpl);

    cudaFuncSetAttribute(gemm_mma,  cudaFuncAttributeMaxDynamicSharedMemorySize, GEMM_SMEM);
    cudaFuncSetAttribute(flash_mma, cudaFuncAttributeMaxDynamicSharedMemorySize, FLASH_SMEM);

    // 1. split input + transpose-split weights
    split_bf16<<<ROWS * EMB / 512, 256>>>(x, xh, xl);
    dim3 gt(EMB / 32, EMB / 32);
    transpose_split<<<gt, 256>>>(Wq, wqh, wql);
    transpose_split<<<gt, 256>>>(Wk, wkh, wkl);
    transpose_split<<<gt, 256>>>(Wv, wvh, wvl);
    transpose_split<<<gt, 256>>>(Wp, wph, wpl);

    // 2. QKV projections -> direct bf16 hi/lo epilogue (no fp32 round trip)
    dim3 gg(EMB / 128, ROWS / 128);    // (8, 32)
    gemm_mma<<<gg, 256, GEMM_SMEM>>>(xh, xl, wqh, wql, nullptr, nullptr, qh, ql);
    gemm_mma<<<gg, 256, GEMM_SMEM>>>(xh, xl, wkh, wkl, nullptr, nullptr, kh, kl);
    gemm_mma<<<gg, 256, GEMM_SMEM>>>(xh, xl, wvh, wvl, nullptr, nullptr, vh, vl);

    // 3. tensor-core causal flash attention -> att hi/lo bf16
    dim3 gf(S_LEN / 128, NH, BATCH);   // (16, 16, 2)
    flash_mma<<<gf, 256, FLASH_SMEM>>>(qh, ql, kh, kl, vh, vl, ah, al);

    // 4. output projection (fp32 out + bias)
    gemm_mma<<<gg, 256, GEMM_SMEM>>>(ah, al, wph, wpl, bp, out, nullptr, nullptr);
}

// round 10
// speedup vs baseline: 3.0185x; 1.0031x over previous
#include <cuda_runtime.h>
#include <cuda_bf16.h>
#include <cstdint>

#define S_LEN 2048
#define EMB   1024
#define NH    16
#define HD    64
#define BATCH 2
#define ROWS  (BATCH * S_LEN)   // 4096

// ---------------------------------------------------------------------------
// Scratch (__device__ globals: allocation-free rule)
// ---------------------------------------------------------------------------
__device__ __nv_bfloat16 g_xh[ROWS * EMB], g_xl[ROWS * EMB];   // split x
__device__ __nv_bfloat16 g_qh[ROWS * EMB], g_ql[ROWS * EMB];   // Q hi/lo
__device__ __nv_bfloat16 g_kh[ROWS * EMB], g_kl[ROWS * EMB];   // K hi/lo
__device__ __nv_bfloat16 g_vh[ROWS * EMB], g_vl[ROWS * EMB];   // V hi/lo
__device__ __nv_bfloat16 g_ah[ROWS * EMB], g_al[ROWS * EMB];   // att hi/lo
__device__ __nv_bfloat16 g_wqh[EMB * EMB], g_wql[EMB * EMB];   // W^T splits
__device__ __nv_bfloat16 g_wkh[EMB * EMB], g_wkl[EMB * EMB];
__device__ __nv_bfloat16 g_wvh[EMB * EMB], g_wvl[EMB * EMB];
__device__ __nv_bfloat16 g_wph[EMB * EMB], g_wpl[EMB * EMB];

// ---------------------------------------------------------------------------
// Generic-PTX helpers (NO tcgen05/TMEM: harness PTX target is family sm_103)
// ---------------------------------------------------------------------------
__device__ __forceinline__ uint32_t smem_u32(const void* p) {
    uint32_t a;
    asm("{ .reg .u64 t; cvta.to.shared.u64 t, %1; cvt.u32.u64 %0, t; }" : "=r"(a) : "l"(p));
    return a;
}

#define LDSM_X4(r, a)                                                          \
    asm volatile("ldmatrix.sync.aligned.m8n8.x4.shared.b16 {%0,%1,%2,%3}, [%4];" \
                 : "=r"((r)[0]), "=r"((r)[1]), "=r"((r)[2]), "=r"((r)[3])      \
                 : "r"(a))

#define LDSM_X4_T(r, a)                                                        \
    asm volatile("ldmatrix.sync.aligned.m8n8.x4.trans.shared.b16 {%0,%1,%2,%3}, [%4];" \
                 : "=r"((r)[0]), "=r"((r)[1]), "=r"((r)[2]), "=r"((r)[3])      \
                 : "r"(a))

#define MMA16816(d, a, b)                                                      \
    asm volatile("mma.sync.aligned.m16n8k16.row.col.f32.bf16.bf16.f32 "        \
                 "{%0,%1,%2,%3}, {%4,%5,%6,%7}, {%8,%9}, {%0,%1,%2,%3};"       \
                 : "+f"((d)[0]), "+f"((d)[1]), "+f"((d)[2]), "+f"((d)[3])      \
                 : "r"((a)[0]), "r"((a)[1]), "r"((a)[2]), "r"((a)[3]),         \
                   "r"((b)[0]), "r"((b)[1]))

// b-frag pair helpers (extract the two n8 fragments from an x4 ldsm)
#define MMA_B0(d, a, t)                                                        \
    { uint32_t _b[2] = {(t)[0], (t)[2]}; MMA16816(d, a, _b); }
#define MMA_B1(d, a, t)                                                        \
    { uint32_t _b[2] = {(t)[1], (t)[3]}; MMA16816(d, a, _b); }

#define CP_ASYNC16(saddr, gaddr)                                               \
    asm volatile("cp.async.cg.shared.global [%0], [%1], 16;"                   \
                 :: "r"(saddr), "l"(gaddr))
#define CP_COMMIT()  asm volatile("cp.async.commit_group;" ::: "memory")
#define CP_WAIT0()   asm volatile("cp.async.wait_group 0;" ::: "memory")

// split two floats -> packed bf16x2 hi + packed bf16x2 lo
__device__ __forceinline__ void split2(float p0, float p1, uint32_t& hi, uint32_t& lo) {
    __nv_bfloat16 h0 = __float2bfloat16_rn(p0);
    __nv_bfloat16 h1 = __float2bfloat16_rn(p1);
    __nv_bfloat16 l0 = __float2bfloat16_rn(p0 - __bfloat162float(h0));
    __nv_bfloat16 l1 = __float2bfloat16_rn(p1 - __bfloat162float(h1));
    __nv_bfloat162 H; H.x = h0; H.y = h1;
    __nv_bfloat162 L; L.x = l0; L.y = l1;
    hi = *(uint32_t*)&H; lo = *(uint32_t*)&L;
}

// ---------------------------------------------------------------------------
// Split fp32 -> bf16 hi + bf16 lo (for input x)
// ---------------------------------------------------------------------------
__global__ void __launch_bounds__(256) split_bf16(const float* __restrict__ s,
                                                  __nv_bfloat16* __restrict__ hi,
                                                  __nv_bfloat16* __restrict__ lo)
{
    int i = (blockIdx.x * 256 + threadIdx.x) * 2;
    float2 v = *(const float2*)(s + i);
    uint32_t h, l;
    split2(v.x, v.y, h, l);
    *(uint32_t*)(hi + i) = h;
    *(uint32_t*)(lo + i) = l;
}

// ---------------------------------------------------------------------------
// 4x fused: W[K,N] -> W^T[N,K] bf16 hi/lo split (z selects matrix)
// ---------------------------------------------------------------------------
struct TPtrs {
    const float* W[4];
    __nv_bfloat16* Th[4];
    __nv_bfloat16* Tl[4];
};

__global__ void __launch_bounds__(256) transpose_split4(TPtrs p)
{
    __shared__ float t[32][33];
    const float* W = p.W[blockIdx.z];
    __nv_bfloat16* Th = p.Th[blockIdx.z];
    __nv_bfloat16* Tl = p.Tl[blockIdx.z];
    int n0 = blockIdx.x * 32, k0 = blockIdx.y * 32;
    int tx = threadIdx.x & 31, ty = threadIdx.x >> 5;
    #pragma unroll
    for (int i = 0; i < 32; i += 8)
        t[ty + i][tx] = W[(size_t)(k0 + ty + i) * EMB + n0 + tx];
    __syncthreads();
    #pragma unroll
    for (int i = 0; i < 32; i += 8) {
        float v = t[tx][ty + i];
        __nv_bfloat16 h = __float2bfloat16_rn(v);
        __nv_bfloat16 l = __float2bfloat16_rn(v - __bfloat162float(h));
        size_t o = (size_t)(n0 + ty + i) * EMB + k0 + tx;
        Th[o] = h;
        Tl[o] = l;
    }
}

// ---------------------------------------------------------------------------
// HMMA GEMM: C = A @ W. 128x128 CTA tile, BK=32, 8 warps (2m x 4n), 64x32 warp
// tile, cp.async double buffer, 3-term hi/lo split MMA, fp32 acc.
// MMA ordering is TERM-MAJOR: all 16 MMAs of a term hit distinct accumulators
// (no back-to-back RAW on the same C-frag).
// ---------------------------------------------------------------------------
#define BK      32
#define NKT     (EMB / BK)            // 32
#define TPITCH  80
#define TILE_B  (128 * TPITCH)
#define AH_OFF  0
#define AL_OFF  (TILE_B)
#define BH_OFF  (2 * TILE_B)
#define BL_OFF  (3 * TILE_B)
#define STAGE_B (4 * TILE_B)
#define GEMM_SMEM (2 * STAGE_B)       // 81920

__device__ __forceinline__ void stage_load(uint32_t sb,
                                           const __nv_bfloat16* __restrict__ Ahi,
                                           const __nv_bfloat16* __restrict__ Alo,
                                           const __nv_bfloat16* __restrict__ Bhi,
                                           const __nv_bfloat16* __restrict__ Blo,
                                           int row0, int col0, int k0, int tid)
{
    #pragma unroll
    for (int it = 0; it < 2; it++) {
        int idx = it * 256 + tid;
        int row = idx >> 2, c = idx & 3;
        size_t goff = (size_t)row * EMB + k0 + c * 8;
        uint32_t soff = (uint32_t)(row * TPITCH + c * 16);
        CP_ASYNC16(sb + AH_OFF + soff, Ahi + (size_t)row0 * EMB + goff);
        CP_ASYNC16(sb + AL_OFF + soff, Alo + (size_t)row0 * EMB + goff);
        CP_ASYNC16(sb + BH_OFF + soff, Bhi + (size_t)col0 * EMB + goff);
        CP_ASYNC16(sb + BL_OFF + soff, Blo + (size_t)col0 * EMB + goff);
    }
}

__global__ void __launch_bounds__(256) gemm_mma(const __nv_bfloat16* __restrict__ Ahi,
                                                const __nv_bfloat16* __restrict__ Alo,
                                                const __nv_bfloat16* __restrict__ Bhi,
                                                const __nv_bfloat16* __restrict__ Blo,
                                                const float* __restrict__ bias,
                                                float* __restrict__ C,
                                                __nv_bfloat16* __restrict__ Ch,
                                                __nv_bfloat16* __restrict__ Cl)
{
    extern __shared__ char dynsm[];
    const uint32_t smbase = smem_u32(dynsm);

    const int tid  = threadIdx.x;
    const int lane = tid & 31;
    const int warp = tid >> 5;
    const int wm   = warp & 1;
    const int wn   = warp >> 1;
    const int row0 = blockIdx.y * 128;
    const int col0 = blockIdx.x * 128;

    float acc[4][4][4];
    #pragma unroll
    for (int i = 0; i < 4; i++)
        #pragma unroll
        for (int j = 0; j < 4; j++)
            #pragma unroll
            for (int r = 0; r < 4; r++) acc[i][j][r] = 0.f;

    const uint32_t lmA = (uint32_t)((wm * 64 + (lane & 15)) * TPITCH + ((lane >> 4) << 4));
    const uint32_t lmB = (uint32_t)((wn * 32 + (lane & 15)) * TPITCH + ((lane >> 4) << 4));

    stage_load(smbase, Ahi, Alo, Bhi, Blo, row0, col0, 0, tid);
    CP_COMMIT();

    #pragma unroll 1
    for (int t = 0; t < NKT; t++) {
        const uint32_t sb = smbase + (uint32_t)(t & 1) * STAGE_B;
        CP_WAIT0();
        __syncthreads();
        if (t + 1 < NKT) {
            stage_load(smbase + (uint32_t)((t + 1) & 1) * STAGE_B,
                       Ahi, Alo, Bhi, Blo, row0, col0, (t + 1) * BK, tid);
            CP_COMMIT();
        }

        #pragma unroll
        for (int ks = 0; ks < 2; ks++) {
            const uint32_t ko = (uint32_t)(ks * 32);
            uint32_t ah[4][4], al[4][4];
            #pragma unroll
            for (int mf = 0; mf < 4; mf++) {
                LDSM_X4(ah[mf], sb + AH_OFF + lmA + (uint32_t)(mf * 16 * TPITCH) + ko);
                LDSM_X4(al[mf], sb + AL_OFF + lmA + (uint32_t)(mf * 16 * TPITCH) + ko);
            }
            uint32_t bh[4][2], bl[4][2];
            #pragma unroll
            for (int ng = 0; ng < 2; ng++) {
                uint32_t tmp[4];
                LDSM_X4(tmp, sb + BH_OFF + lmB + (uint32_t)(ng * 16 * TPITCH) + ko);
                bh[2 * ng][0] = tmp[0]; bh[2 * ng + 1][0] = tmp[1];
                bh[2 * ng][1] = tmp[2]; bh[2 * ng + 1][1] = tmp[3];
                LDSM_X4(tmp, sb + BL_OFF + lmB + (uint32_t)(ng * 16 * TPITCH) + ko);
                bl[2 * ng][0] = tmp[0]; bl[2 * ng + 1][0] = tmp[1];
                bl[2 * ng][1] = tmp[2]; bl[2 * ng + 1][1] = tmp[3];
            }
            // term-major: 16 independent accumulators per term -> no RAW chains
            #pragma unroll
            for (int mf = 0; mf < 4; mf++)
                #pragma unroll
                for (int nf = 0; nf < 4; nf++)
                    MMA16816(acc[mf][nf], ah[mf], bh[nf]);   // hi*hi
            #pragma unroll
            for (int mf = 0; mf < 4; mf++)
                #pragma unroll
                for (int nf = 0; nf < 4; nf++)
                    MMA16816(acc[mf][nf], ah[mf], bl[nf]);   // hi*lo
            #pragma unroll
            for (int mf = 0; mf < 4; mf++)
                #pragma unroll
                for (int nf = 0; nf < 4; nf++)
                    MMA16816(acc[mf][nf], al[mf], bh[nf]);   // lo*hi
        }
    }

    #pragma unroll
    for (int mf = 0; mf < 4; mf++) {
        #pragma unroll
        for (int nf = 0; nf < 4; nf++) {
            int r  = row0 + wm * 64 + mf * 16 + (lane >> 2);
            int cb = col0 + wn * 32 + nf * 8 + (lane & 3) * 2;
            if (Ch) {
                uint32_t h, l;
                split2(acc[mf][nf][0], acc[mf][nf][1], h, l);
                *(uint32_t*)(Ch + (size_t)r * EMB + cb) = h;
                *(uint32_t*)(Cl + (size_t)r * EMB + cb) = l;
                split2(acc[mf][nf][2], acc[mf][nf][3], h, l);
                *(uint32_t*)(Ch + (size_t)(r + 8) * EMB + cb) = h;
                *(uint32_t*)(Cl + (size_t)(r + 8) * EMB + cb) = l;
            } else {
                float b0 = 0.f, b1 = 0.f;
                if (bias) { b0 = bias[cb]; b1 = bias[cb + 1]; }
                *(float2*)(C + (size_t)r * EMB + cb) =
                    make_float2(acc[mf][nf][0] + b0, acc[mf][nf][1] + b1);
                *(float2*)(C + (size_t)(r + 8) * EMB + cb) =
                    make_float2(acc[mf][nf][2] + b0, acc[mf][nf][3] + b1);
            }
        }
    }
}

// ---------------------------------------------------------------------------
// Tensor-core causal flash attention (term-major MMA ordering).
// CTA: 128 q-rows x (b,h); 8 warps, warp = 16 q-rows. k-tile 64.
// ---------------------------------------------------------------------------
#define QP    144
#define KVT   (64 * QP)
#define FLASH_SMEM (2 * 128 * QP + 2 * 4 * KVT)   // 110592

__device__ __forceinline__ void kv_stage(uint32_t sb,
                                         const __nv_bfloat16* __restrict__ Kh,
                                         const __nv_bfloat16* __restrict__ Kl,
                                         const __nv_bfloat16* __restrict__ Vh,
                                         const __nv_bfloat16* __restrict__ Vl,
                                         size_t gbase, int k0, int tid)
{
    #pragma unroll
    for (int it = 0; it < 2; it++) {
        int idx = it * 256 + tid;
        int row = idx >> 3, c = idx & 7;
        size_t g = gbase + (size_t)(k0 + row) * EMB + c * 8;
        uint32_t so = (uint32_t)(row * QP + c * 16);
        CP_ASYNC16(sb + 0 * KVT + so, Kh + g);
        CP_ASYNC16(sb + 1 * KVT + so, Kl + g);
        CP_ASYNC16(sb + 2 * KVT + so, Vh + g);
        CP_ASYNC16(sb + 3 * KVT + so, Vl + g);
    }
}

__global__ void __launch_bounds__(256) flash_mma(
    const __nv_bfloat16* __restrict__ Qh, const __nv_bfloat16* __restrict__ Ql,
    const __nv_bfloat16* __restrict__ Kh, const __nv_bfloat16* __restrict__ Kl,
    const __nv_bfloat16* __restrict__ Vh, const __nv_bfloat16* __restrict__ Vl,
    __nv_bfloat16* __restrict__ Oh, __nv_bfloat16* __restrict__ Ol)
{
    extern __shared__ char dynsm[];
    const uint32_t sQh = smem_u32(dynsm);
    const uint32_t sQl = sQh + 128 * QP;
    const uint32_t sKV = sQl + 128 * QP;

    const int tid  = threadIdx.x;
    const int lane = tid & 31;
    const int warp = tid >> 5;
    const int qt = gridDim.x - 1 - blockIdx.x;   // heaviest causal tiles first
    const int h = blockIdx.y, b = blockIdx.z;
    const int q0 = qt * 128;
    const int wrow = warp * 16;
    const size_t gbase = ((size_t)b * S_LEN) * EMB + (size_t)h * HD;

    #pragma unroll
    for (int it = 0; it < 4; it++) {
        int idx = it * 256 + tid;
        int row = idx >> 3, c = idx & 7;
        size_t g = gbase + (size_t)(q0 + row) * EMB + c * 8;
        uint32_t so = (uint32_t)(row * QP + c * 16);
        CP_ASYNC16(sQh + so, Qh + g);
        CP_ASYNC16(sQl + so, Ql + g);
    }
    kv_stage(sKV, Kh, Kl, Vh, Vl, gbase, 0, tid);
    CP_COMMIT();

    const int nkt = 2 * qt + 2;

    uint32_t qfh[4][4], qfl[4][4];
    float o[8][4];
    float m[2] = {-1e30f, -1e30f}, l[2] = {0.f, 0.f};
    #pragma unroll
    for (int nb = 0; nb < 8; nb++)
        #pragma unroll
        for (int j = 0; j < 4; j++) o[nb][j] = 0.f;

    #pragma unroll 1
    for (int kt = 0; kt < nkt; kt++) {
        CP_WAIT0();
        __syncthreads();
        if (kt == 0) {
            #pragma unroll
            for (int kc = 0; kc < 4; kc++) {
                uint32_t aq = (uint32_t)((wrow + (lane & 15)) * QP + ((lane >> 4) << 4) + kc * 32);
                LDSM_X4(qfh[kc], sQh + aq);
                LDSM_X4(qfl[kc], sQl + aq);
            }
        }
        if (kt + 1 < nkt) {
            kv_stage(sKV + (uint32_t)((kt + 1) & 1) * 4 * KVT, Kh, Kl, Vh, Vl,
                     gbase, (kt + 1) * 64, tid);
            CP_COMMIT();
        }

        const int k0 = kt * 64;
        if (k0 > q0 + wrow + 15) continue;   // fully masked for this warp (after barrier!)

        const uint32_t sb = sKV + (uint32_t)(kt & 1) * 4 * KVT;

        // ---- S = Q K^T (3-term split, term-major across 8 targets) ----
        float s[8][4];
        #pragma unroll
        for (int nb = 0; nb < 8; nb++)
            #pragma unroll
            for (int j = 0; j < 4; j++) s[nb][j] = 0.f;

        #pragma unroll
        for (int kc = 0; kc < 4; kc++) {
            uint32_t kh4[4][4], kl4[4][4];
            #pragma unroll
            for (int g2 = 0; g2 < 4; g2++) {
                uint32_t a = sb + (uint32_t)((g2 * 16 + (lane & 15)) * QP + ((lane >> 4) << 4) + kc * 32);
                LDSM_X4(kh4[g2], a);
                LDSM_X4(kl4[g2], a + KVT);
            }
            #pragma unroll
            for (int g2 = 0; g2 < 4; g2++) {            // 8 independent targets
                MMA_B0(s[2 * g2],     qfh[kc], kh4[g2]);
                MMA_B1(s[2 * g2 + 1], qfh[kc], kh4[g2]);
            }
            #pragma unroll
            for (int g2 = 0; g2 < 4; g2++) {
                MMA_B0(s[2 * g2],     qfh[kc], kl4[g2]);
                MMA_B1(s[2 * g2 + 1], qfh[kc], kl4[g2]);
            }
            #pragma unroll
            for (int g2 = 0; g2 < 4; g2++) {
                MMA_B0(s[2 * g2],     qfl[kc], kh4[g2]);
                MMA_B1(s[2 * g2 + 1], qfl[kc], kh4[g2]);
            }
        }

        // ---- scale + causal mask ----
        const bool partial = (k0 + 63 > q0 + wrow);
        const int rg = q0 + wrow + (lane >> 2);
        #pragma unroll
        for (int nb = 0; nb < 8; nb++) {
            int c0 = k0 + nb * 8 + 2 * (lane & 3);
            #pragma unroll
            for (int j = 0; j < 4; j++) {
                float sv = s[nb][j] * 0.125f;
                if (partial && (c0 + (j & 1)) > (rg + (j >> 1) * 8)) sv = -1e30f;
                s[nb][j] = sv;
            }
        }

        // ---- online softmax (fp32) ----
        #pragma unroll
        for (int hf = 0; hf < 2; hf++) {
            const int j0 = hf * 2;
            float rm = -1e30f;
            #pragma unroll
            for (int nb = 0; nb < 8; nb++)
                rm = fmaxf(rm, fmaxf(s[nb][j0], s[nb][j0 + 1]));
            rm = fmaxf(rm, __shfl_xor_sync(0xffffffffu, rm, 1));
            rm = fmaxf(rm, __shfl_xor_sync(0xffffffffu, rm, 2));
            float mn   = fmaxf(m[hf], rm);
            float corr = __expf(m[hf] - mn);
            float rs = 0.f;
            #pragma unroll
            for (int nb = 0; nb < 8; nb++) {
                float p0 = __expf(s[nb][j0] - mn);
                float p1 = __expf(s[nb][j0 + 1] - mn);
                s[nb][j0] = p0; s[nb][j0 + 1] = p1;
                rs += p0 + p1;
            }
            rs += __shfl_xor_sync(0xffffffffu, rs, 1);
            rs += __shfl_xor_sync(0xffffffffu, rs, 2);
            l[hf] = l[hf] * corr + rs;
            m[hf] = mn;
            #pragma unroll
            for (int nb = 0; nb < 8; nb++) { o[nb][j0] *= corr; o[nb][j0 + 1] *= corr; }
        }

        // ---- P -> bf16 hi/lo A-frags ----
        uint32_t ph[4][4], pl[4][4];
        #pragma unroll
        for (int kc = 0; kc < 4; kc++)
            #pragma unroll
            for (int t = 0; t < 4; t++) {
                int nb = 2 * kc + (t >> 1);
                int j0 = (t & 1) * 2;
                split2(s[nb][j0], s[nb][j0 + 1], ph[kc][t], pl[kc][t]);
            }

        // ---- O += P V (3-term split, term-major; V via ldmatrix.trans) ----
        #pragma unroll
        for (int kc = 0; kc < 4; kc++) {
            uint32_t vh4[4][4], vl4[4][4];
            #pragma unroll
            for (int g2 = 0; g2 < 4; g2++) {
                uint32_t a = sb + 2 * KVT +
                    (uint32_t)((kc * 16 + (lane & 7) + ((lane >> 4) << 3)) * QP +
                               g2 * 32 + ((lane >> 3) & 1) * 16);
                LDSM_X4_T(vh4[g2], a);
                LDSM_X4_T(vl4[g2], a + KVT);
            }
            #pragma unroll
            for (int g2 = 0; g2 < 4; g2++) {
                MMA_B0(o[2 * g2],     ph[kc], vh4[g2]);
                MMA_B1(o[2 * g2 + 1], ph[kc], vh4[g2]);
            }
            #pragma unroll
            for (int g2 = 0; g2 < 4; g2++) {
                MMA_B0(o[2 * g2],     ph[kc], vl4[g2]);
                MMA_B1(o[2 * g2 + 1], ph[kc], vl4[g2]);
            }
            #pragma unroll
            for (int g2 = 0; g2 < 4; g2++) {
                MMA_B0(o[2 * g2],     pl[kc], vh4[g2]);
                MMA_B1(o[2 * g2 + 1], pl[kc], vh4[g2]);
            }
        }
    }

    // ---- normalize + write att hi/lo bf16 ----
    #pragma unroll
    for (int hf = 0; hf < 2; hf++) {
        float inv = 1.f / l[hf];
        int grow = q0 + wrow + (lane >> 2) + hf * 8;
        size_t rb = gbase + (size_t)grow * EMB + 2 * (lane & 3);
        #pragma unroll
        for (int nb = 0; nb < 8; nb++) {
            uint32_t hv, lv;
            split2(o[nb][hf * 2] * inv, o[nb][hf * 2 + 1] * inv, hv, lv);
            *(uint32_t*)(Oh + rb + nb * 8) = hv;
            *(uint32_t*)(Ol + rb + nb * 8) = lv;
        }
    }
}

// ---------------------------------------------------------------------------
extern "C" void kernel_launch(void* const* d_in, const int* in_sizes, int n_in,
                              void* d_out, int out_size)
{
    (void)in_sizes; (void)n_in; (void)out_size;
    const float* x  = (const float*)d_in[0];
    const float* Wq = (const float*)d_in[1];
    const float* Wk = (const float*)d_in[2];
    const float* Wv = (const float*)d_in[3];
    const float* Wp = (const float*)d_in[4];
    const float* bp = (const float*)d_in[5];
    float* out = (float*)d_out;

    __nv_bfloat16 *xh, *xl, *qh, *ql, *kh, *kl, *vh, *vl, *ah, *al;
    __nv_bfloat16 *wqh, *wql, *wkh, *wkl, *wvh, *wvl, *wph, *wpl;
    cudaGetSymbolAddress((void**)&xh,  g_xh);  cudaGetSymbolAddress((void**)&xl,  g_xl);
    cudaGetSymbolAddress((void**)&qh,  g_qh);  cudaGetSymbolAddress((void**)&ql,  g_ql);
    cudaGetSymbolAddress((void**)&kh,  g_kh);  cudaGetSymbolAddress((void**)&kl,  g_kl);
    cudaGetSymbolAddress((void**)&vh,  g_vh);  cudaGetSymbolAddress((void**)&vl,  g_vl);
    cudaGetSymbolAddress((void**)&ah,  g_ah);  cudaGetSymbolAddress((void**)&al,  g_al);
    cudaGetSymbolAddress((void**)&wqh, g_wqh); cudaGetSymbolAddress((void**)&wql, g_wql);
    cudaGetSymbolAddress((void**)&wkh, g_wkh); cudaGetSymbolAddress((void**)&wkl, g_wkl);
    cudaGetSymbolAddress((void**)&wvh, g_wvh); cudaGetSymbolAddress((void**)&wvl, g_wvl);
    cudaGetSymbolAddress((void**)&wph, g_wph); cudaGetSymbolAddress((void**)&wpl, g_wpl);

    cudaFuncSetAttribute(gemm_mma,  cudaFuncAttributeMaxDynamicSharedMemorySize, GEMM_SMEM);
    cudaFuncSetAttribute(flash_mma, cudaFuncAttributeMaxDynamicSharedMemorySize, FLASH_SMEM);

    // 1. split input + transpose-split weights (single fused launch)
    split_bf16<<<ROWS * EMB / 512, 256>>>(x, xh, xl);
    TPtrs tp;
    tp.W[0] = Wq; tp.Th[0] = wqh; tp.Tl[0] = wql;
    tp.W[1] = Wk; tp.Th[1] = wkh; tp.Tl[1] = wkl;
    tp.W[2] = Wv; tp.Th[2] = wvh; tp.Tl[2] = wvl;
    tp.W[3] = Wp; tp.Th[3] = wph; tp.Tl[3] = wpl;
    dim3 gt(EMB / 32, EMB / 32, 4);
    transpose_split4<<<gt, 256>>>(tp);

    // 2. QKV projections -> direct bf16 hi/lo epilogue
    dim3 gg(EMB / 128, ROWS / 128);    // (8, 32)
    gemm_mma<<<gg, 256, GEMM_SMEM>>>(xh, xl, wqh, wql, nullptr, nullptr, qh, ql);
    gemm_mma<<<gg, 256, GEMM_SMEM>>>(xh, xl, wkh, wkl, nullptr, nullptr, kh, kl);
    gemm_mma<<<gg, 256, GEMM_SMEM>>>(xh, xl, wvh, wvl, nullptr, nullptr, vh, vl);

    // 3. tensor-core causal flash attention -> att hi/lo bf16
    dim3 gf(S_LEN / 128, NH, BATCH);   // (16, 16, 2)
    flash_mma<<<gf, 256, FLASH_SMEM>>>(qh, ql, kh, kl, vh, vl, ah, al);

    // 4. output projection (fp32 out + bias)
    gemm_mma<<<gg, 256, GEMM_SMEM>>>(ah, al, wph, wpl, bp, out, nullptr, nullptr);
}

// round 13
// speedup vs baseline: 3.0600x; 1.0138x over previous
#include <cuda_runtime.h>
#include <cuda_bf16.h>
#include <cstdint>

#define S_LEN 2048
#define EMB   1024
#define NH    16
#define HD    64
#define BATCH 2
#define ROWS  (BATCH * S_LEN)   // 4096

// ---------------------------------------------------------------------------
// Scratch (__device__ globals: allocation-free rule)
// ---------------------------------------------------------------------------
__device__ __nv_bfloat16 g_xh[ROWS * EMB], g_xl[ROWS * EMB];   // split x
__device__ __nv_bfloat16 g_qh[ROWS * EMB], g_ql[ROWS * EMB];   // Q hi/lo
__device__ __nv_bfloat16 g_kh[ROWS * EMB], g_kl[ROWS * EMB];   // K hi/lo
__device__ __nv_bfloat16 g_vh[ROWS * EMB], g_vl[ROWS * EMB];   // V hi/lo
__device__ __nv_bfloat16 g_ah[ROWS * EMB], g_al[ROWS * EMB];   // att hi/lo
__device__ __nv_bfloat16 g_wqh[EMB * EMB], g_wql[EMB * EMB];   // W^T splits
__device__ __nv_bfloat16 g_wkh[EMB * EMB], g_wkl[EMB * EMB];
__device__ __nv_bfloat16 g_wvh[EMB * EMB], g_wvl[EMB * EMB];
__device__ __nv_bfloat16 g_wph[EMB * EMB], g_wpl[EMB * EMB];

// ---------------------------------------------------------------------------
// Generic-PTX helpers (NO tcgen05/TMEM: harness PTX target is family sm_103)
// ---------------------------------------------------------------------------
__device__ __forceinline__ uint32_t smem_u32(const void* p) {
    uint32_t a;
    asm("{ .reg .u64 t; cvta.to.shared.u64 t, %1; cvt.u32.u64 %0, t; }" : "=r"(a) : "l"(p));
    return a;
}

#define LDSM_X4(r, a)                                                          \
    asm volatile("ldmatrix.sync.aligned.m8n8.x4.shared.b16 {%0,%1,%2,%3}, [%4];" \
                 : "=r"((r)[0]), "=r"((r)[1]), "=r"((r)[2]), "=r"((r)[3])      \
                 : "r"(a))

#define LDSM_X4_T(r, a)                                                        \
    asm volatile("ldmatrix.sync.aligned.m8n8.x4.trans.shared.b16 {%0,%1,%2,%3}, [%4];" \
                 : "=r"((r)[0]), "=r"((r)[1]), "=r"((r)[2]), "=r"((r)[3])      \
                 : "r"(a))

#define MMA16816(d, a, b)                                                      \
    asm volatile("mma.sync.aligned.m16n8k16.row.col.f32.bf16.bf16.f32 "        \
                 "{%0,%1,%2,%3}, {%4,%5,%6,%7}, {%8,%9}, {%0,%1,%2,%3};"       \
                 : "+f"((d)[0]), "+f"((d)[1]), "+f"((d)[2]), "+f"((d)[3])      \
                 : "r"((a)[0]), "r"((a)[1]), "r"((a)[2]), "r"((a)[3]),         \
                   "r"((b)[0]), "r"((b)[1]))

// b-frag pair helpers (extract the two n8 fragments from an x4 ldsm)
#define MMA_B0(d, a, t)                                                        \
    { uint32_t _b[2] = {(t)[0], (t)[2]}; MMA16816(d, a, _b); }
#define MMA_B1(d, a, t)                                                        \
    { uint32_t _b[2] = {(t)[1], (t)[3]}; MMA16816(d, a, _b); }

#define CP_ASYNC16(saddr, gaddr)                                               \
    asm volatile("cp.async.cg.shared.global [%0], [%1], 16;"                   \
                 :: "r"(saddr), "l"(gaddr))
#define CP_COMMIT()  asm volatile("cp.async.commit_group;" ::: "memory")
#define CP_WAIT0()   asm volatile("cp.async.wait_group 0;" ::: "memory")

// split two floats -> packed bf16x2 hi + packed bf16x2 lo
__device__ __forceinline__ void split2(float p0, float p1, uint32_t& hi, uint32_t& lo) {
    __nv_bfloat16 h0 = __float2bfloat16_rn(p0);
    __nv_bfloat16 h1 = __float2bfloat16_rn(p1);
    __nv_bfloat16 l0 = __float2bfloat16_rn(p0 - __bfloat162float(h0));
    __nv_bfloat16 l1 = __float2bfloat16_rn(p1 - __bfloat162float(h1));
    __nv_bfloat162 H; H.x = h0; H.y = h1;
    __nv_bfloat162 L; L.x = l0; L.y = l1;
    hi = *(uint32_t*)&H; lo = *(uint32_t*)&L;
}

// ---------------------------------------------------------------------------
// Split fp32 -> bf16 hi + bf16 lo (for input x)
// ---------------------------------------------------------------------------
__global__ void __launch_bounds__(256) split_bf16(const float* __restrict__ s,
                                                  __nv_bfloat16* __restrict__ hi,
                                                  __nv_bfloat16* __restrict__ lo)
{
    int i = (blockIdx.x * 256 + threadIdx.x) * 2;
    float2 v = *(const float2*)(s + i);
    uint32_t h, l;
    split2(v.x, v.y, h, l);
    *(uint32_t*)(hi + i) = h;
    *(uint32_t*)(lo + i) = l;
}

// ---------------------------------------------------------------------------
// 4x fused: W[K,N] -> W^T[N,K] bf16 hi/lo split (z selects matrix)
// ---------------------------------------------------------------------------
struct TPtrs {
    const float* W[4];
    __nv_bfloat16* Th[4];
    __nv_bfloat16* Tl[4];
};

__global__ void __launch_bounds__(256) transpose_split4(TPtrs p)
{
    __shared__ float t[32][33];
    const float* W = p.W[blockIdx.z];
    __nv_bfloat16* Th = p.Th[blockIdx.z];
    __nv_bfloat16* Tl = p.Tl[blockIdx.z];
    int n0 = blockIdx.x * 32, k0 = blockIdx.y * 32;
    int tx = threadIdx.x & 31, ty = threadIdx.x >> 5;
    #pragma unroll
    for (int i = 0; i < 32; i += 8)
        t[ty + i][tx] = W[(size_t)(k0 + ty + i) * EMB + n0 + tx];
    __syncthreads();
    #pragma unroll
    for (int i = 0; i < 32; i += 8) {
        float v = t[tx][ty + i];
        __nv_bfloat16 h = __float2bfloat16_rn(v);
        __nv_bfloat16 l = __float2bfloat16_rn(v - __bfloat162float(h));
        size_t o = (size_t)(n0 + ty + i) * EMB + k0 + tx;
        Th[o] = h;
        Tl[o] = l;
    }
}

// ---------------------------------------------------------------------------
// HMMA GEMM: C = A @ W. 128x128 CTA tile, BK=32, 8 warps (2m x 4n), 64x32 warp
// tile, cp.async double buffer, 3-term hi/lo split MMA, fp32 acc.
// Inner loop is SOFTWARE-PIPELINED: A-frags stream through a ping-pong buffer,
// each ldsm pair hidden under the 12 MMAs of the previous mf group.
// ---------------------------------------------------------------------------
#define BK      32
#define NKT     (EMB / BK)            // 32
#define TPITCH  80
#define TILE_B  (128 * TPITCH)
#define AH_OFF  0
#define AL_OFF  (TILE_B)
#define BH_OFF  (2 * TILE_B)
#define BL_OFF  (3 * TILE_B)
#define STAGE_B (4 * TILE_B)
#define GEMM_SMEM (2 * STAGE_B)       // 81920

__device__ __forceinline__ void stage_load(uint32_t sb,
                                           const __nv_bfloat16* __restrict__ Ahi,
                                           const __nv_bfloat16* __restrict__ Alo,
                                           const __nv_bfloat16* __restrict__ Bhi,
                                           const __nv_bfloat16* __restrict__ Blo,
                                           int row0, int col0, int k0, int tid)
{
    #pragma unroll
    for (int it = 0; it < 2; it++) {
        int idx = it * 256 + tid;
        int row = idx >> 2, c = idx & 3;
        size_t goff = (size_t)row * EMB + k0 + c * 8;
        uint32_t soff = (uint32_t)(row * TPITCH + c * 16);
        CP_ASYNC16(sb + AH_OFF + soff, Ahi + (size_t)row0 * EMB + goff);
        CP_ASYNC16(sb + AL_OFF + soff, Alo + (size_t)row0 * EMB + goff);
        CP_ASYNC16(sb + BH_OFF + soff, Bhi + (size_t)col0 * EMB + goff);
        CP_ASYNC16(sb + BL_OFF + soff, Blo + (size_t)col0 * EMB + goff);
    }
}

__global__ void __launch_bounds__(256) gemm_mma(const __nv_bfloat16* __restrict__ Ahi,
                                                const __nv_bfloat16* __restrict__ Alo,
                                                const __nv_bfloat16* __restrict__ Bhi,
                                                const __nv_bfloat16* __restrict__ Blo,
                                                const float* __restrict__ bias,
                                                float* __restrict__ C,
                                                __nv_bfloat16* __restrict__ Ch,
                                                __nv_bfloat16* __restrict__ Cl)
{
    extern __shared__ char dynsm[];
    const uint32_t smbase = smem_u32(dynsm);

    const int tid  = threadIdx.x;
    const int lane = tid & 31;
    const int warp = tid >> 5;
    const int wm   = warp & 1;
    const int wn   = warp >> 1;
    const int row0 = blockIdx.y * 128;
    const int col0 = blockIdx.x * 128;

    float acc[4][4][4];
    #pragma unroll
    for (int i = 0; i < 4; i++)
        #pragma unroll
        for (int j = 0; j < 4; j++)
            #pragma unroll
            for (int r = 0; r < 4; r++) acc[i][j][r] = 0.f;

    const uint32_t lmA = (uint32_t)((wm * 64 + (lane & 15)) * TPITCH + ((lane >> 4) << 4));
    const uint32_t lmB = (uint32_t)((wn * 32 + (lane & 15)) * TPITCH + ((lane >> 4) << 4));

    stage_load(smbase, Ahi, Alo, Bhi, Blo, row0, col0, 0, tid);
    CP_COMMIT();

    #pragma unroll 1
    for (int t = 0; t < NKT; t++) {
        const uint32_t sb = smbase + (uint32_t)(t & 1) * STAGE_B;
        CP_WAIT0();
        __syncthreads();

        #pragma unroll
        for (int ks = 0; ks < 2; ks++) {
            const uint32_t ko = (uint32_t)(ks * 32);

            // B frags for the whole ks step
            uint32_t bh[4][2], bl[4][2];
            #pragma unroll
            for (int ng = 0; ng < 2; ng++) {
                uint32_t tmp[4];
                LDSM_X4(tmp, sb + BH_OFF + lmB + (uint32_t)(ng * 16 * TPITCH) + ko);
                bh[2 * ng][0] = tmp[0]; bh[2 * ng + 1][0] = tmp[1];
                bh[2 * ng][1] = tmp[2]; bh[2 * ng + 1][1] = tmp[3];
                LDSM_X4(tmp, sb + BL_OFF + lmB + (uint32_t)(ng * 16 * TPITCH) + ko);
                bl[2 * ng][0] = tmp[0]; bl[2 * ng + 1][0] = tmp[1];
                bl[2 * ng][1] = tmp[2]; bl[2 * ng + 1][1] = tmp[3];
            }

            // A frags ping-pong: prefetch mf+1 under the 12 MMAs of mf
            uint32_t ah[2][4], al[2][4];
            LDSM_X4(ah[0], sb + AH_OFF + lmA + ko);
            LDSM_X4(al[0], sb + AL_OFF + lmA + ko);
            #pragma unroll
            for (int mf = 0; mf < 4; mf++) {
                const int cur = mf & 1, nxt = cur ^ 1;
                if (mf < 3) {
                    LDSM_X4(ah[nxt], sb + AH_OFF + lmA + (uint32_t)((mf + 1) * 16 * TPITCH) + ko);
                    LDSM_X4(al[nxt], sb + AL_OFF + lmA + (uint32_t)((mf + 1) * 16 * TPITCH) + ko);
                }
                #pragma unroll
                for (int nf = 0; nf < 4; nf++)
                    MMA16816(acc[mf][nf], ah[cur], bh[nf]);   // hi*hi
                #pragma unroll
                for (int nf = 0; nf < 4; nf++)
                    MMA16816(acc[mf][nf], ah[cur], bl[nf]);   // hi*lo
                #pragma unroll
                for (int nf = 0; nf < 4; nf++)
                    MMA16816(acc[mf][nf], al[cur], bh[nf]);   // lo*hi
            }

            // de-burst the LSU: issue next-stage cp.async between the ks halves
            if (ks == 0 && t + 1 < NKT) {
                stage_load(smbase + (uint32_t)((t + 1) & 1) * STAGE_B,
                           Ahi, Alo, Bhi, Blo, row0, col0, (t + 1) * BK, tid);
                CP_COMMIT();
            }
        }
    }

    #pragma unroll
    for (int mf = 0; mf < 4; mf++) {
        #pragma unroll
        for (int nf = 0; nf < 4; nf++) {
            int r  = row0 + wm * 64 + mf * 16 + (lane >> 2);
            int cb = col0 + wn * 32 + nf * 8 + (lane & 3) * 2;
            if (Ch) {
                uint32_t h, l;
                split2(acc[mf][nf][0], acc[mf][nf][1], h, l);
                *(uint32_t*)(Ch + (size_t)r * EMB + cb) = h;
                *(uint32_t*)(Cl + (size_t)r * EMB + cb) = l;
                split2(acc[mf][nf][2], acc[mf][nf][3], h, l);
                *(uint32_t*)(Ch + (size_t)(r + 8) * EMB + cb) = h;
                *(uint32_t*)(Cl + (size_t)(r + 8) * EMB + cb) = l;
            } else {
                float b0 = 0.f, b1 = 0.f;
                if (bias) { b0 = bias[cb]; b1 = bias[cb + 1]; }
                *(float2*)(C + (size_t)r * EMB + cb) =
                    make_float2(acc[mf][nf][0] + b0, acc[mf][nf][1] + b1);
                *(float2*)(C + (size_t)(r + 8) * EMB + cb) =
                    make_float2(acc[mf][nf][2] + b0, acc[mf][nf][3] + b1);
            }
        }
    }
}

// ---------------------------------------------------------------------------
// Tensor-core causal flash attention (software-pipelined frag streams).
// CTA: 128 q-rows x (b,h); 8 warps, warp = 16 q-rows. k-tile 64.
// ---------------------------------------------------------------------------
#define QP    144
#define KVT   (64 * QP)
#define FLASH_SMEM (2 * 128 * QP + 2 * 4 * KVT)   // 110592

__device__ __forceinline__ void kv_stage(uint32_t sb,
                                         const __nv_bfloat16* __restrict__ Kh,
                                         const __nv_bfloat16* __restrict__ Kl,
                                         const __nv_bfloat16* __restrict__ Vh,
                                         const __nv_bfloat16* __restrict__ Vl,
                                         size_t gbase, int k0, int tid)
{
    #pragma unroll
    for (int it = 0; it < 2; it++) {
        int idx = it * 256 + tid;
        int row = idx >> 3, c = idx & 7;
        size_t g = gbase + (size_t)(k0 + row) * EMB + c * 8;
        uint32_t so = (uint32_t)(row * QP + c * 16);
        CP_ASYNC16(sb + 0 * KVT + so, Kh + g);
        CP_ASYNC16(sb + 1 * KVT + so, Kl + g);
        CP_ASYNC16(sb + 2 * KVT + so, Vh + g);
        CP_ASYNC16(sb + 3 * KVT + so, Vl + g);
    }
}

__global__ void __launch_bounds__(256) flash_mma(
    const __nv_bfloat16* __restrict__ Qh, const __nv_bfloat16* __restrict__ Ql,
    const __nv_bfloat16* __restrict__ Kh, const __nv_bfloat16* __restrict__ Kl,
    const __nv_bfloat16* __restrict__ Vh, const __nv_bfloat16* __restrict__ Vl,
    __nv_bfloat16* __restrict__ Oh, __nv_bfloat16* __restrict__ Ol)
{
    extern __shared__ char dynsm[];
    const uint32_t sQh = smem_u32(dynsm);
    const uint32_t sQl = sQh + 128 * QP;
    const uint32_t sKV = sQl + 128 * QP;

    const int tid  = threadIdx.x;
    const int lane = tid & 31;
    const int warp = tid >> 5;
    const int qt = gridDim.x - 1 - blockIdx.x;   // heaviest causal tiles first
    const int h = blockIdx.y, b = blockIdx.z;
    const int q0 = qt * 128;
    const int wrow = warp * 16;
    const size_t gbase = ((size_t)b * S_LEN) * EMB + (size_t)h * HD;

    #pragma unroll
    for (int it = 0; it < 4; it++) {
        int idx = it * 256 + tid;
        int row = idx >> 3, c = idx & 7;
        size_t g = gbase + (size_t)(q0 + row) * EMB + c * 8;
        uint32_t so = (uint32_t)(row * QP + c * 16);
        CP_ASYNC16(sQh + so, Qh + g);
        CP_ASYNC16(sQl + so, Ql + g);
    }
    kv_stage(sKV, Kh, Kl, Vh, Vl, gbase, 0, tid);
    CP_COMMIT();

    const int nkt = 2 * qt + 2;

    uint32_t qfh[4][4], qfl[4][4];
    float o[8][4];
    float m[2] = {-1e30f, -1e30f}, l[2] = {0.f, 0.f};
    #pragma unroll
    for (int nb = 0; nb < 8; nb++)
        #pragma unroll
        for (int j = 0; j < 4; j++) o[nb][j] = 0.f;

    #pragma unroll 1
    for (int kt = 0; kt < nkt; kt++) {
        CP_WAIT0();
        __syncthreads();
        if (kt == 0) {
            #pragma unroll
            for (int kc = 0; kc < 4; kc++) {
                uint32_t aq = (uint32_t)((wrow + (lane & 15)) * QP + ((lane >> 4) << 4) + kc * 32);
                LDSM_X4(qfh[kc], sQh + aq);
                LDSM_X4(qfl[kc], sQl + aq);
            }
        }
        if (kt + 1 < nkt) {
            kv_stage(sKV + (uint32_t)((kt + 1) & 1) * 4 * KVT, Kh, Kl, Vh, Vl,
                     gbase, (kt + 1) * 64, tid);
            CP_COMMIT();
        }

        const int k0 = kt * 64;
        if (k0 > q0 + wrow + 15) continue;   // fully masked for this warp (after barrier!)

        const uint32_t sb = sKV + (uint32_t)(kt & 1) * 4 * KVT;

        // ---- S = Q K^T : pipelined over 16 (kc,g2) steps, 2 ldsm + 6 MMA ----
        float s[8][4];
        #pragma unroll
        for (int nb = 0; nb < 8; nb++)
            #pragma unroll
            for (int j = 0; j < 4; j++) s[nb][j] = 0.f;

        {
            uint32_t kh[2][4], kl[2][4];
            uint32_t a0 = sb + (uint32_t)(((lane & 15)) * QP + ((lane >> 4) << 4));
            LDSM_X4(kh[0], a0);
            LDSM_X4(kl[0], a0 + KVT);
            #pragma unroll
            for (int idx = 0; idx < 16; idx++) {
                const int kc = idx >> 2, g2 = idx & 3;
                const int cur = idx & 1, nxt = cur ^ 1;
                if (idx < 15) {
                    const int kc1 = (idx + 1) >> 2, g21 = (idx + 1) & 3;
                    uint32_t a = sb + (uint32_t)((g21 * 16 + (lane & 15)) * QP +
                                                 ((lane >> 4) << 4) + kc1 * 32);
                    LDSM_X4(kh[nxt], a);
                    LDSM_X4(kl[nxt], a + KVT);
                }
                MMA_B0(s[2 * g2],     qfh[kc], kh[cur]);
                MMA_B1(s[2 * g2 + 1], qfh[kc], kh[cur]);
                MMA_B0(s[2 * g2],     qfh[kc], kl[cur]);
                MMA_B1(s[2 * g2 + 1], qfh[kc], kl[cur]);
                MMA_B0(s[2 * g2],     qfl[kc], kh[cur]);
                MMA_B1(s[2 * g2 + 1], qfl[kc], kh[cur]);
            }
        }

        // ---- scale + causal mask ----
        const bool partial = (k0 + 63 > q0 + wrow);
        const int rg = q0 + wrow + (lane >> 2);
        #pragma unroll
        for (int nb = 0; nb < 8; nb++) {
            int c0 = k0 + nb * 8 + 2 * (lane & 3);
            #pragma unroll
            for (int j = 0; j < 4; j++) {
                float sv = s[nb][j] * 0.125f;
                if (partial && (c0 + (j & 1)) > (rg + (j >> 1) * 8)) sv = -1e30f;
                s[nb][j] = sv;
            }
        }

        // ---- online softmax (fp32) ----
        #pragma unroll
        for (int hf = 0; hf < 2; hf++) {
            const int j0 = hf * 2;
            float rm = -1e30f;
            #pragma unroll
            for (int nb = 0; nb < 8; nb++)
                rm = fmaxf(rm, fmaxf(s[nb][j0], s[nb][j0 + 1]));
            rm = fmaxf(rm, __shfl_xor_sync(0xffffffffu, rm, 1));
            rm = fmaxf(rm, __shfl_xor_sync(0xffffffffu, rm, 2));
            float mn   = fmaxf(m[hf], rm);
            float corr = __expf(m[hf] - mn);
            float rs = 0.f;
            #pragma unroll
            for (int nb = 0; nb < 8; nb++) {
                float p0 = __expf(s[nb][j0] - mn);
                float p1 = __expf(s[nb][j0 + 1] - mn);
                s[nb][j0] = p0; s[nb][j0 + 1] = p1;
                rs += p0 + p1;
            }
            rs += __shfl_xor_sync(0xffffffffu, rs, 1);
            rs += __shfl_xor_sync(0xffffffffu, rs, 2);
            l[hf] = l[hf] * corr + rs;
            m[hf] = mn;
            #pragma unroll
            for (int nb = 0; nb < 8; nb++) { o[nb][j0] *= corr; o[nb][j0 + 1] *= corr; }
        }

        // ---- P -> bf16 hi/lo A-frags ----
        uint32_t ph[4][4], pl[4][4];
        #pragma unroll
        for (int kc = 0; kc < 4; kc++)
            #pragma unroll
            for (int t = 0; t < 4; t++) {
                int nb = 2 * kc + (t >> 1);
                int j0 = (t & 1) * 2;
                split2(s[nb][j0], s[nb][j0 + 1], ph[kc][t], pl[kc][t]);
            }

        // ---- O += P V : pipelined over 16 (kc,g2) steps, 2 trans-ldsm + 6 MMA ----
        {
            uint32_t vh[2][4], vl[2][4];
            uint32_t a0 = sb + 2 * KVT +
                (uint32_t)(((lane & 7) + ((lane >> 4) << 3)) * QP + ((lane >> 3) & 1) * 16);
            LDSM_X4_T(vh[0], a0);
            LDSM_X4_T(vl[0], a0 + KVT);
            #pragma unroll
            for (int idx = 0; idx < 16; idx++) {
                const int kc = idx >> 2, g2 = idx & 3;
                const int cur = idx & 1, nxt = cur ^ 1;
                if (idx < 15) {
                    const int kc1 = (idx + 1) >> 2, g21 = (idx + 1) & 3;
                    uint32_t a = sb + 2 * KVT +
                        (uint32_t)((kc1 * 16 + (lane & 7) + ((lane >> 4) << 3)) * QP +
                                   g21 * 32 + ((lane >> 3) & 1) * 16);
                    LDSM_X4_T(vh[nxt], a);
                    LDSM_X4_T(vl[nxt], a + KVT);
                }
                MMA_B0(o[2 * g2],     ph[kc], vh[cur]);
                MMA_B1(o[2 * g2 + 1], ph[kc], vh[cur]);
                MMA_B0(o[2 * g2],     ph[kc], vl[cur]);
                MMA_B1(o[2 * g2 + 1], ph[kc], vl[cur]);
                MMA_B0(o[2 * g2],     pl[kc], vh[cur]);
                MMA_B1(o[2 * g2 + 1], pl[kc], vh[cur]);
            }
        }
    }

    // ---- normalize + write att hi/lo bf16 ----
    #pragma unroll
    for (int hf = 0; hf < 2; hf++) {
        float inv = 1.f / l[hf];
        int grow = q0 + wrow + (lane >> 2) + hf * 8;
        size_t rb = gbase + (size_t)grow * EMB + 2 * (lane & 3);
        #pragma unroll
        for (int nb = 0; nb < 8; nb++) {
            uint32_t hv, lv;
            split2(o[nb][hf * 2] * inv, o[nb][hf * 2 + 1] * inv, hv, lv);
            *(uint32_t*)(Oh + rb + nb * 8) = hv;
            *(uint32_t*)(Ol + rb + nb * 8) = lv;
        }
    }
}

// ---------------------------------------------------------------------------
extern "C" void kernel_launch(void* const* d_in, const int* in_sizes, int n_in,
                              void* d_out, int out_size)
{
    (void)in_sizes; (void)n_in; (void)out_size;
    const float* x  = (const float*)d_in[0];
    const float* Wq = (const float*)d_in[1];
    const float* Wk = (const float*)d_in[2];
    const float* Wv = (const float*)d_in[3];
    const float* Wp = (const float*)d_in[4];
    const float* bp = (const float*)d_in[5];
    float* out = (float*)d_out;

    __nv_bfloat16 *xh, *xl, *qh, *ql, *kh, *kl, *vh, *vl, *ah, *al;
    __nv_bfloat16 *wqh, *wql, *wkh, *wkl, *wvh, *wvl, *wph, *wpl;
    cudaGetSymbolAddress((void**)&xh,  g_xh);  cudaGetSymbolAddress((void**)&xl,  g_xl);
    cudaGetSymbolAddress((void**)&qh,  g_qh);  cudaGetSymbolAddress((void**)&ql,  g_ql);
    cudaGetSymbolAddress((void**)&kh,  g_kh);  cudaGetSymbolAddress((void**)&kl,  g_kl);
    cudaGetSymbolAddress((void**)&vh,  g_vh);  cudaGetSymbolAddress((void**)&vl,  g_vl);
    cudaGetSymbolAddress((void**)&ah,  g_ah);  cudaGetSymbolAddress((void**)&al,  g_al);
    cudaGetSymbolAddress((void**)&wqh, g_wqh); cudaGetSymbolAddress((void**)&wql, g_wql);
    cudaGetSymbolAddress((void**)&wkh, g_wkh); cudaGetSymbolAddress((void**)&wkl, g_wkl);
    cudaGetSymbolAddress((void**)&wvh, g_wvh); cudaGetSymbolAddress((void**)&wvl, g_wvl);
    cudaGetSymbolAddress((void**)&wph, g_wph); cudaGetSymbolAddress((void**)&wpl, g_wpl);

    cudaFuncSetAttribute(gemm_mma,  cudaFuncAttributeMaxDynamicSharedMemorySize, GEMM_SMEM);
    cudaFuncSetAttribute(flash_mma, cudaFuncAttributeMaxDynamicSharedMemorySize, FLASH_SMEM);

    // 1. split input + transpose-split weights (single fused launch)
    split_bf16<<<ROWS * EMB / 512, 256>>>(x, xh, xl);
    TPtrs tp;
    tp.W[0] = Wq; tp.Th[0] = wqh; tp.Tl[0] = wql;
    tp.W[1] = Wk; tp.Th[1] = wkh; tp.Tl[1] = wkl;
    tp.W[2] = Wv; tp.Th[2] = wvh; tp.Tl[2] = wvl;
    tp.W[3] = Wp; tp.Th[3] = wph; tp.Tl[3] = wpl;
    dim3 gt(EMB / 32, EMB / 32, 4);
    transpose_split4<<<gt, 256>>>(tp);

    // 2. QKV projections -> direct bf16 hi/lo epilogue
    dim3 gg(EMB / 128, ROWS / 128);    // (8, 32)
    gemm_mma<<<gg, 256, GEMM_SMEM>>>(xh, xl, wqh, wql, nullptr, nullptr, qh, ql);
    gemm_mma<<<gg, 256, GEMM_SMEM>>>(xh, xl, wkh, wkl, nullptr, nullptr, kh, kl);
    gemm_mma<<<gg, 256, GEMM_SMEM>>>(xh, xl, wvh, wvl, nullptr, nullptr, vh, vl);

    // 3. tensor-core causal flash attention -> att hi/lo bf16
    dim3 gf(S_LEN / 128, NH, BATCH);   // (16, 16, 2)
    flash_mma<<<gf, 256, FLASH_SMEM>>>(qh, ql, kh, kl, vh, vl, ah, al);

    // 4. output projection (fp32 out + bias)
    gemm_mma<<<gg, 256, GEMM_SMEM>>>(ah, al, wph, wpl, bp, out, nullptr, nullptr);
}

// round 14
// speedup vs baseline: 3.1666x; 1.0348x over previous
#include <cuda_runtime.h>
#include <cuda_bf16.h>
#include <cstdint>

#define S_LEN 2048
#define EMB   1024
#define NH    16
#define HD    64
#define BATCH 2
#define ROWS  (BATCH * S_LEN)   // 4096

// ---------------------------------------------------------------------------
// Scratch (__device__ globals: allocation-free rule)
// ---------------------------------------------------------------------------
__device__ __nv_bfloat16 g_xh[ROWS * EMB], g_xl[ROWS * EMB];   // split x
__device__ __nv_bfloat16 g_qh[ROWS * EMB], g_ql[ROWS * EMB];   // Q hi/lo
__device__ __nv_bfloat16 g_kh[ROWS * EMB], g_kl[ROWS * EMB];   // K hi/lo
__device__ __nv_bfloat16 g_vh[ROWS * EMB], g_vl[ROWS * EMB];   // V hi/lo
__device__ __nv_bfloat16 g_ah[ROWS * EMB], g_al[ROWS * EMB];   // att hi/lo
__device__ __nv_bfloat16 g_wqh[EMB * EMB], g_wql[EMB * EMB];   // W^T splits
__device__ __nv_bfloat16 g_wkh[EMB * EMB], g_wkl[EMB * EMB];
__device__ __nv_bfloat16 g_wvh[EMB * EMB], g_wvl[EMB * EMB];
__device__ __nv_bfloat16 g_wph[EMB * EMB], g_wpl[EMB * EMB];

// ---------------------------------------------------------------------------
// Generic-PTX helpers (NO tcgen05/TMEM: harness PTX target is family sm_103)
// ---------------------------------------------------------------------------
__device__ __forceinline__ uint32_t smem_u32(const void* p) {
    uint32_t a;
    asm("{ .reg .u64 t; cvta.to.shared.u64 t, %1; cvt.u32.u64 %0, t; }" : "=r"(a) : "l"(p));
    return a;
}

#define LDSM_X4(r, a)                                                          \
    asm volatile("ldmatrix.sync.aligned.m8n8.x4.shared.b16 {%0,%1,%2,%3}, [%4];" \
                 : "=r"((r)[0]), "=r"((r)[1]), "=r"((r)[2]), "=r"((r)[3])      \
                 : "r"(a))

#define LDSM_X4_T(r, a)                                                        \
    asm volatile("ldmatrix.sync.aligned.m8n8.x4.trans.shared.b16 {%0,%1,%2,%3}, [%4];" \
                 : "=r"((r)[0]), "=r"((r)[1]), "=r"((r)[2]), "=r"((r)[3])      \
                 : "r"(a))

#define MMA16816(d, a, b)                                                      \
    asm volatile("mma.sync.aligned.m16n8k16.row.col.f32.bf16.bf16.f32 "        \
                 "{%0,%1,%2,%3}, {%4,%5,%6,%7}, {%8,%9}, {%0,%1,%2,%3};"       \
                 : "+f"((d)[0]), "+f"((d)[1]), "+f"((d)[2]), "+f"((d)[3])      \
                 : "r"((a)[0]), "r"((a)[1]), "r"((a)[2]), "r"((a)[3]),         \
                   "r"((b)[0]), "r"((b)[1]))

// b-frag pair helpers (extract the two n8 fragments from an x4 ldsm)
#define MMA_B0(d, a, t)                                                        \
    { uint32_t _b[2] = {(t)[0], (t)[2]}; MMA16816(d, a, _b); }
#define MMA_B1(d, a, t)                                                        \
    { uint32_t _b[2] = {(t)[1], (t)[3]}; MMA16816(d, a, _b); }

#define CP_ASYNC16(saddr, gaddr)                                               \
    asm volatile("cp.async.cg.shared.global [%0], [%1], 16;"                   \
                 :: "r"(saddr), "l"(gaddr))
#define CP_COMMIT()  asm volatile("cp.async.commit_group;" ::: "memory")
#define CP_WAIT0()   asm volatile("cp.async.wait_group 0;" ::: "memory")

// 128B-row XOR swizzle: 16B chunk index XOR (row & 7). Conflict-free for both
// 16B cp.async stores and ldmatrix reads (8 rows cover all 8 chunk columns).
#define SWZ128(row, chunk) ((uint32_t)(((row) << 7) + ((((chunk) ^ ((row) & 7)) & 7) << 4)))

// split two floats -> packed bf16x2 hi + packed bf16x2 lo
__device__ __forceinline__ void split2(float p0, float p1, uint32_t& hi, uint32_t& lo) {
    __nv_bfloat16 h0 = __float2bfloat16_rn(p0);
    __nv_bfloat16 h1 = __float2bfloat16_rn(p1);
    __nv_bfloat16 l0 = __float2bfloat16_rn(p0 - __bfloat162float(h0));
    __nv_bfloat16 l1 = __float2bfloat16_rn(p1 - __bfloat162float(h1));
    __nv_bfloat162 H; H.x = h0; H.y = h1;
    __nv_bfloat162 L; L.x = l0; L.y = l1;
    hi = *(uint32_t*)&H; lo = *(uint32_t*)&L;
}

// ---------------------------------------------------------------------------
// Split fp32 -> bf16 hi + bf16 lo (for input x)
// ---------------------------------------------------------------------------
__global__ void __launch_bounds__(256) split_bf16(const float* __restrict__ s,
                                                  __nv_bfloat16* __restrict__ hi,
                                                  __nv_bfloat16* __restrict__ lo)
{
    int i = (blockIdx.x * 256 + threadIdx.x) * 2;
    float2 v = *(const float2*)(s + i);
    uint32_t h, l;
    split2(v.x, v.y, h, l);
    *(uint32_t*)(hi + i) = h;
    *(uint32_t*)(lo + i) = l;
}

// ---------------------------------------------------------------------------
// 4x fused: W[K,N] -> W^T[N,K] bf16 hi/lo split (z selects matrix)
// ---------------------------------------------------------------------------
struct TPtrs {
    const float* W[4];
    __nv_bfloat16* Th[4];
    __nv_bfloat16* Tl[4];
};

__global__ void __launch_bounds__(256) transpose_split4(TPtrs p)
{
    __shared__ float t[32][33];
    const float* W = p.W[blockIdx.z];
    __nv_bfloat16* Th = p.Th[blockIdx.z];
    __nv_bfloat16* Tl = p.Tl[blockIdx.z];
    int n0 = blockIdx.x * 32, k0 = blockIdx.y * 32;
    int tx = threadIdx.x & 31, ty = threadIdx.x >> 5;
    #pragma unroll
    for (int i = 0; i < 32; i += 8)
        t[ty + i][tx] = W[(size_t)(k0 + ty + i) * EMB + n0 + tx];
    __syncthreads();
    #pragma unroll
    for (int i = 0; i < 32; i += 8) {
        float v = t[tx][ty + i];
        __nv_bfloat16 h = __float2bfloat16_rn(v);
        __nv_bfloat16 l = __float2bfloat16_rn(v - __bfloat162float(h));
        size_t o = (size_t)(n0 + ty + i) * EMB + k0 + tx;
        Th[o] = h;
        Tl[o] = l;
    }
}

// ---------------------------------------------------------------------------
// HMMA GEMM (unchanged proven version): 128x128 CTA tile, BK=32, 8 warps,
// cp.async double buffer, 3-term hi/lo split MMA, fp32 acc.
// ---------------------------------------------------------------------------
#define BK      32
#define NKT     (EMB / BK)            // 32
#define TPITCH  80
#define TILE_B  (128 * TPITCH)
#define AH_OFF  0
#define AL_OFF  (TILE_B)
#define BH_OFF  (2 * TILE_B)
#define BL_OFF  (3 * TILE_B)
#define STAGE_B (4 * TILE_B)
#define GEMM_SMEM (2 * STAGE_B)       // 81920

__device__ __forceinline__ void stage_load(uint32_t sb,
                                           const __nv_bfloat16* __restrict__ Ahi,
                                           const __nv_bfloat16* __restrict__ Alo,
                                           const __nv_bfloat16* __restrict__ Bhi,
                                           const __nv_bfloat16* __restrict__ Blo,
                                           int row0, int col0, int k0, int tid)
{
    #pragma unroll
    for (int it = 0; it < 2; it++) {
        int idx = it * 256 + tid;
        int row = idx >> 2, c = idx & 3;
        size_t goff = (size_t)row * EMB + k0 + c * 8;
        uint32_t soff = (uint32_t)(row * TPITCH + c * 16);
        CP_ASYNC16(sb + AH_OFF + soff, Ahi + (size_t)row0 * EMB + goff);
        CP_ASYNC16(sb + AL_OFF + soff, Alo + (size_t)row0 * EMB + goff);
        CP_ASYNC16(sb + BH_OFF + soff, Bhi + (size_t)col0 * EMB + goff);
        CP_ASYNC16(sb + BL_OFF + soff, Blo + (size_t)col0 * EMB + goff);
    }
}

__global__ void __launch_bounds__(256) gemm_mma(const __nv_bfloat16* __restrict__ Ahi,
                                                const __nv_bfloat16* __restrict__ Alo,
                                                const __nv_bfloat16* __restrict__ Bhi,
                                                const __nv_bfloat16* __restrict__ Blo,
                                                const float* __restrict__ bias,
                                                float* __restrict__ C,
                                                __nv_bfloat16* __restrict__ Ch,
                                                __nv_bfloat16* __restrict__ Cl)
{
    extern __shared__ char dynsm[];
    const uint32_t smbase = smem_u32(dynsm);

    const int tid  = threadIdx.x;
    const int lane = tid & 31;
    const int warp = tid >> 5;
    const int wm   = warp & 1;
    const int wn   = warp >> 1;
    const int row0 = blockIdx.y * 128;
    const int col0 = blockIdx.x * 128;

    float acc[4][4][4];
    #pragma unroll
    for (int i = 0; i < 4; i++)
        #pragma unroll
        for (int j = 0; j < 4; j++)
            #pragma unroll
            for (int r = 0; r < 4; r++) acc[i][j][r] = 0.f;

    const uint32_t lmA = (uint32_t)((wm * 64 + (lane & 15)) * TPITCH + ((lane >> 4) << 4));
    const uint32_t lmB = (uint32_t)((wn * 32 + (lane & 15)) * TPITCH + ((lane >> 4) << 4));

    stage_load(smbase, Ahi, Alo, Bhi, Blo, row0, col0, 0, tid);
    CP_COMMIT();

    #pragma unroll 1
    for (int t = 0; t < NKT; t++) {
        const uint32_t sb = smbase + (uint32_t)(t & 1) * STAGE_B;
        CP_WAIT0();
        __syncthreads();

        #pragma unroll
        for (int ks = 0; ks < 2; ks++) {
            const uint32_t ko = (uint32_t)(ks * 32);

            uint32_t bh[4][2], bl[4][2];
            #pragma unroll
            for (int ng = 0; ng < 2; ng++) {
                uint32_t tmp[4];
                LDSM_X4(tmp, sb + BH_OFF + lmB + (uint32_t)(ng * 16 * TPITCH) + ko);
                bh[2 * ng][0] = tmp[0]; bh[2 * ng + 1][0] = tmp[1];
                bh[2 * ng][1] = tmp[2]; bh[2 * ng + 1][1] = tmp[3];
                LDSM_X4(tmp, sb + BL_OFF + lmB + (uint32_t)(ng * 16 * TPITCH) + ko);
                bl[2 * ng][0] = tmp[0]; bl[2 * ng + 1][0] = tmp[1];
                bl[2 * ng][1] = tmp[2]; bl[2 * ng + 1][1] = tmp[3];
            }

            uint32_t ah[2][4], al[2][4];
            LDSM_X4(ah[0], sb + AH_OFF + lmA + ko);
            LDSM_X4(al[0], sb + AL_OFF + lmA + ko);
            #pragma unroll
            for (int mf = 0; mf < 4; mf++) {
                const int cur = mf & 1, nxt = cur ^ 1;
                if (mf < 3) {
                    LDSM_X4(ah[nxt], sb + AH_OFF + lmA + (uint32_t)((mf + 1) * 16 * TPITCH) + ko);
                    LDSM_X4(al[nxt], sb + AL_OFF + lmA + (uint32_t)((mf + 1) * 16 * TPITCH) + ko);
                }
                #pragma unroll
                for (int nf = 0; nf < 4; nf++)
                    MMA16816(acc[mf][nf], ah[cur], bh[nf]);   // hi*hi
                #pragma unroll
                for (int nf = 0; nf < 4; nf++)
                    MMA16816(acc[mf][nf], ah[cur], bl[nf]);   // hi*lo
                #pragma unroll
                for (int nf = 0; nf < 4; nf++)
                    MMA16816(acc[mf][nf], al[cur], bh[nf]);   // lo*hi
            }

            if (ks == 0 && t + 1 < NKT) {
                stage_load(smbase + (uint32_t)((t + 1) & 1) * STAGE_B,
                           Ahi, Alo, Bhi, Blo, row0, col0, (t + 1) * BK, tid);
                CP_COMMIT();
            }
        }
    }

    #pragma unroll
    for (int mf = 0; mf < 4; mf++) {
        #pragma unroll
        for (int nf = 0; nf < 4; nf++) {
            int r  = row0 + wm * 64 + mf * 16 + (lane >> 2);
            int cb = col0 + wn * 32 + nf * 8 + (lane & 3) * 2;
            if (Ch) {
                uint32_t h, l;
                split2(acc[mf][nf][0], acc[mf][nf][1], h, l);
                *(uint32_t*)(Ch + (size_t)r * EMB + cb) = h;
                *(uint32_t*)(Cl + (size_t)r * EMB + cb) = l;
                split2(acc[mf][nf][2], acc[mf][nf][3], h, l);
                *(uint32_t*)(Ch + (size_t)(r + 8) * EMB + cb) = h;
                *(uint32_t*)(Cl + (size_t)(r + 8) * EMB + cb) = l;
            } else {
                float b0 = 0.f, b1 = 0.f;
                if (bias) { b0 = bias[cb]; b1 = bias[cb + 1]; }
                *(float2*)(C + (size_t)r * EMB + cb) =
                    make_float2(acc[mf][nf][0] + b0, acc[mf][nf][1] + b1);
                *(float2*)(C + (size_t)(r + 8) * EMB + cb) =
                    make_float2(acc[mf][nf][2] + b0, acc[mf][nf][3] + b1);
            }
        }
    }
}

// ---------------------------------------------------------------------------
// Tensor-core causal flash attention — 64 KB smem (swizzled 128B rows, and the
// Q region is OVERLAID with KV stage 1: Q smem is dead after the one-time
// fragment load at kt=0). Target: 2 CTAs/SM (16 warps) for latency hiding.
// ---------------------------------------------------------------------------
#define KVT        8192                 // 64 rows x 128B
#define KVSTAGE    (4 * KVT)            // Kh,Kl,Vh,Vl = 32768
#define Q_OFF      KVSTAGE              // Q lives in stage-1's region
#define QHALF      16384                // 128 rows x 128B per Q half
#define FLASH_SMEM (2 * KVSTAGE)        // 65536

__device__ __forceinline__ void kv_stage(uint32_t sb,
                                         const __nv_bfloat16* __restrict__ Kh,
                                         const __nv_bfloat16* __restrict__ Kl,
                                         const __nv_bfloat16* __restrict__ Vh,
                                         const __nv_bfloat16* __restrict__ Vl,
                                         size_t gbase, int k0, int tid)
{
    #pragma unroll
    for (int it = 0; it < 2; it++) {
        int idx = it * 256 + tid;
        int row = idx >> 3, c = idx & 7;
        size_t g = gbase + (size_t)(k0 + row) * EMB + c * 8;
        uint32_t so = SWZ128(row, c);
        CP_ASYNC16(sb + 0 * KVT + so, Kh + g);
        CP_ASYNC16(sb + 1 * KVT + so, Kl + g);
        CP_ASYNC16(sb + 2 * KVT + so, Vh + g);
        CP_ASYNC16(sb + 3 * KVT + so, Vl + g);
    }
}

__global__ void __launch_bounds__(256, 2) flash_mma(
    const __nv_bfloat16* __restrict__ Qh, const __nv_bfloat16* __restrict__ Ql,
    const __nv_bfloat16* __restrict__ Kh, const __nv_bfloat16* __restrict__ Kl,
    const __nv_bfloat16* __restrict__ Vh, const __nv_bfloat16* __restrict__ Vl,
    __nv_bfloat16* __restrict__ Oh, __nv_bfloat16* __restrict__ Ol)
{
    extern __shared__ char dynsm[];
    const uint32_t smbase = smem_u32(dynsm);
    const uint32_t sQ = smbase + Q_OFF;

    const int tid  = threadIdx.x;
    const int lane = tid & 31;
    const int warp = tid >> 5;
    const int qt = gridDim.x - 1 - blockIdx.x;   // heaviest causal tiles first
    const int h = blockIdx.y, b = blockIdx.z;
    const int q0 = qt * 128;
    const int wrow = warp * 16;
    const size_t gbase = ((size_t)b * S_LEN) * EMB + (size_t)h * HD;

    // prologue: Q (into stage-1 region) + KV stage 0
    #pragma unroll
    for (int it = 0; it < 4; it++) {
        int idx = it * 256 + tid;
        int row = idx >> 3, c = idx & 7;
        size_t g = gbase + (size_t)(q0 + row) * EMB + c * 8;
        uint32_t so = SWZ128(row, c);
        CP_ASYNC16(sQ + so, Qh + g);
        CP_ASYNC16(sQ + QHALF + so, Ql + g);
    }
    kv_stage(smbase, Kh, Kl, Vh, Vl, gbase, 0, tid);
    CP_COMMIT();

    const int nkt = 2 * qt + 2;

    uint32_t qfh[4][4], qfl[4][4];
    float o[8][4];
    float m[2] = {-1e30f, -1e30f}, l[2] = {0.f, 0.f};
    #pragma unroll
    for (int nb = 0; nb < 8; nb++)
        #pragma unroll
        for (int j = 0; j < 4; j++) o[nb][j] = 0.f;

    #pragma unroll 1
    for (int kt = 0; kt < nkt; kt++) {
        CP_WAIT0();
        __syncthreads();
        if (kt == 0) {
            // one-time Q fragment load; Q smem is dead afterwards
            #pragma unroll
            for (int kc = 0; kc < 4; kc++) {
                uint32_t row = (uint32_t)(wrow + (lane & 15));
                uint32_t so = SWZ128(row, kc * 2 + (lane >> 4));
                LDSM_X4(qfh[kc], sQ + so);
                LDSM_X4(qfl[kc], sQ + QHALF + so);
            }
            __syncthreads();   // all Q reads complete before stage-1 overwrites it
        }
        if (kt + 1 < nkt) {
            kv_stage(smbase + (uint32_t)(((kt + 1) & 1)) * KVSTAGE, Kh, Kl, Vh, Vl,
                     gbase, (kt + 1) * 64, tid);
            CP_COMMIT();
        }

        const int k0 = kt * 64;
        if (k0 > q0 + wrow + 15) continue;   // fully masked for this warp (after barrier!)

        const uint32_t sb = smbase + (uint32_t)(kt & 1) * KVSTAGE;

        // ---- S = Q K^T : pipelined over 16 (kc,g2) steps, 2 ldsm + 6 MMA ----
        float s[8][4];
        #pragma unroll
        for (int nb = 0; nb < 8; nb++)
            #pragma unroll
            for (int j = 0; j < 4; j++) s[nb][j] = 0.f;

        {
            uint32_t kh[2][4], kl[2][4];
            {
                uint32_t row = (uint32_t)(lane & 15);
                uint32_t a0 = sb + SWZ128(row, (lane >> 4));
                LDSM_X4(kh[0], a0);
                LDSM_X4(kl[0], a0 + KVT);
            }
            #pragma unroll
            for (int idx = 0; idx < 16; idx++) {
                const int kc = idx >> 2, g2 = idx & 3;
                const int cur = idx & 1, nxt = cur ^ 1;
                if (idx < 15) {
                    const int kc1 = (idx + 1) >> 2, g21 = (idx + 1) & 3;
                    uint32_t row = (uint32_t)(g21 * 16 + (lane & 15));
                    uint32_t a = sb + SWZ128(row, kc1 * 2 + (lane >> 4));
                    LDSM_X4(kh[nxt], a);
                    LDSM_X4(kl[nxt], a + KVT);
                }
                MMA_B0(s[2 * g2],     qfh[kc], kh[cur]);
                MMA_B1(s[2 * g2 + 1], qfh[kc], kh[cur]);
                MMA_B0(s[2 * g2],     qfh[kc], kl[cur]);
                MMA_B1(s[2 * g2 + 1], qfh[kc], kl[cur]);
                MMA_B0(s[2 * g2],     qfl[kc], kh[cur]);
                MMA_B1(s[2 * g2 + 1], qfl[kc], kh[cur]);
            }
        }

        // ---- scale + causal mask ----
        const bool partial = (k0 + 63 > q0 + wrow);
        const int rg = q0 + wrow + (lane >> 2);
        #pragma unroll
        for (int nb = 0; nb < 8; nb++) {
            int c0 = k0 + nb * 8 + 2 * (lane & 3);
            #pragma unroll
            for (int j = 0; j < 4; j++) {
                float sv = s[nb][j] * 0.125f;
                if (partial && (c0 + (j & 1)) > (rg + (j >> 1) * 8)) sv = -1e30f;
                s[nb][j] = sv;
            }
        }

        // ---- online softmax (fp32) ----
        #pragma unroll
        for (int hf = 0; hf < 2; hf++) {
            const int j0 = hf * 2;
            float rm = -1e30f;
            #pragma unroll
            for (int nb = 0; nb < 8; nb++)
                rm = fmaxf(rm, fmaxf(s[nb][j0], s[nb][j0 + 1]));
            rm = fmaxf(rm, __shfl_xor_sync(0xffffffffu, rm, 1));
            rm = fmaxf(rm, __shfl_xor_sync(0xffffffffu, rm, 2));
            float mn   = fmaxf(m[hf], rm);
            float corr = __expf(m[hf] - mn);
            float rs = 0.f;
            #pragma unroll
            for (int nb = 0; nb < 8; nb++) {
                float p0 = __expf(s[nb][j0] - mn);
                float p1 = __expf(s[nb][j0 + 1] - mn);
                s[nb][j0] = p0; s[nb][j0 + 1] = p1;
                rs += p0 + p1;
            }
            rs += __shfl_xor_sync(0xffffffffu, rs, 1);
            rs += __shfl_xor_sync(0xffffffffu, rs, 2);
            l[hf] = l[hf] * corr + rs;
            m[hf] = mn;
            #pragma unroll
            for (int nb = 0; nb < 8; nb++) { o[nb][j0] *= corr; o[nb][j0 + 1] *= corr; }
        }

        // ---- O += P V : pipelined; P split fused per-kc (8 live frag regs) ----
        {
            uint32_t vh[2][4], vl[2][4];
            uint32_t ph[4], pl[4];
            {
                uint32_t row = (uint32_t)((lane & 7) + ((lane >> 4) << 3));
                uint32_t a0 = sb + 2 * KVT + SWZ128(row, (lane >> 3) & 1);
                LDSM_X4_T(vh[0], a0);
                LDSM_X4_T(vl[0], a0 + KVT);
            }
            #pragma unroll
            for (int idx = 0; idx < 16; idx++) {
                const int kc = idx >> 2, g2 = idx & 3;
                const int cur = idx & 1, nxt = cur ^ 1;
                if (g2 == 0) {
                    #pragma unroll
                    for (int t = 0; t < 4; t++) {
                        int nb = 2 * kc + (t >> 1);
                        int j0 = (t & 1) * 2;
                        split2(s[nb][j0], s[nb][j0 + 1], ph[t], pl[t]);
                    }
                }
                if (idx < 15) {
                    const int kc1 = (idx + 1) >> 2, g21 = (idx + 1) & 3;
                    uint32_t row = (uint32_t)(kc1 * 16 + (lane & 7) + ((lane >> 4) << 3));
                    uint32_t a = sb + 2 * KVT + SWZ128(row, g21 * 2 + ((lane >> 3) & 1));
                    LDSM_X4_T(vh[nxt], a);
                    LDSM_X4_T(vl[nxt], a + KVT);
                }
                MMA_B0(o[2 * g2],     ph, vh[cur]);
                MMA_B1(o[2 * g2 + 1], ph, vh[cur]);
                MMA_B0(o[2 * g2],     ph, vl[cur]);
                MMA_B1(o[2 * g2 + 1], ph, vl[cur]);
                MMA_B0(o[2 * g2],     pl, vh[cur]);
                MMA_B1(o[2 * g2 + 1], pl, vh[cur]);
            }
        }
    }

    // ---- normalize + write att hi/lo bf16 ----
    #pragma unroll
    for (int hf = 0; hf < 2; hf++) {
        float inv = 1.f / l[hf];
        int grow = q0 + wrow + (lane >> 2) + hf * 8;
        size_t rb = gbase + (size_t)grow * EMB + 2 * (lane & 3);
        #pragma unroll
        for (int nb = 0; nb < 8; nb++) {
            uint32_t hv, lv;
            split2(o[nb][hf * 2] * inv, o[nb][hf * 2 + 1] * inv, hv, lv);
            *(uint32_t*)(Oh + rb + nb * 8) = hv;
            *(uint32_t*)(Ol + rb + nb * 8) = lv;
        }
    }
}

// ---------------------------------------------------------------------------
extern "C" void kernel_launch(void* const* d_in, const int* in_sizes, int n_in,
                              void* d_out, int out_size)
{
    (void)in_sizes; (void)n_in; (void)out_size;
    const float* x  = (const float*)d_in[0];
    const float* Wq = (const float*)d_in[1];
    const float* Wk = (const float*)d_in[2];
    const float* Wv = (const float*)d_in[3];
    const float* Wp = (const float*)d_in[4];
    const float* bp = (const float*)d_in[5];
    float* out = (float*)d_out;

    __nv_bfloat16 *xh, *xl, *qh, *ql, *kh, *kl, *vh, *vl, *ah, *al;
    __nv_bfloat16 *wqh, *wql, *wkh, *wkl, *wvh, *wvl, *wph, *wpl;
    cudaGetSymbolAddress((void**)&xh,  g_xh);  cudaGetSymbolAddress((void**)&xl,  g_xl);
    cudaGetSymbolAddress((void**)&qh,  g_qh);  cudaGetSymbolAddress((void**)&ql,  g_ql);
    cudaGetSymbolAddress((void**)&kh,  g_kh);  cudaGetSymbolAddress((void**)&kl,  g_kl);
    cudaGetSymbolAddress((void**)&vh,  g_vh);  cudaGetSymbolAddress((void**)&vl,  g_vl);
    cudaGetSymbolAddress((void**)&ah,  g_ah);  cudaGetSymbolAddress((void**)&al,  g_al);
    cudaGetSymbolAddress((void**)&wqh, g_wqh); cudaGetSymbolAddress((void**)&wql, g_wql);
    cudaGetSymbolAddress((void**)&wkh, g_wkh); cudaGetSymbolAddress((void**)&wkl, g_wkl);
    cudaGetSymbolAddress((void**)&wvh, g_wvh); cudaGetSymbolAddress((void**)&wvl, g_wvl);
    cudaGetSymbolAddress((void**)&wph, g_wph); cudaGetSymbolAddress((void**)&wpl, g_wpl);

    cudaFuncSetAttribute(gemm_mma,  cudaFuncAttributeMaxDynamicSharedMemorySize, GEMM_SMEM);
    cudaFuncSetAttribute(flash_mma, cudaFuncAttributeMaxDynamicSharedMemorySize, FLASH_SMEM);

    // 1. split input + transpose-split weights (single fused launch)
    split_bf16<<<ROWS * EMB / 512, 256>>>(x, xh, xl);
    TPtrs tp;
    tp.W[0] = Wq; tp.Th[0] = wqh; tp.Tl[0] = wql;
    tp.W[1] = Wk; tp.Th[1] = wkh; tp.Tl[1] = wkl;
    tp.W[2] = Wv; tp.Th[2] = wvh; tp.Tl[2] = wvl;
    tp.W[3] = Wp; tp.Th[3] = wph; tp.Tl[3] = wpl;
    dim3 gt(EMB / 32, EMB / 32, 4);
    transpose_split4<<<gt, 256>>>(tp);

    // 2. QKV projections -> direct bf16 hi/lo epilogue
    dim3 gg(EMB / 128, ROWS / 128);    // (8, 32)
    gemm_mma<<<gg, 256, GEMM_SMEM>>>(xh, xl, wqh, wql, nullptr, nullptr, qh, ql);
    gemm_mma<<<gg, 256, GEMM_SMEM>>>(xh, xl, wkh, wkl, nullptr, nullptr, kh, kl);
    gemm_mma<<<gg, 256, GEMM_SMEM>>>(xh, xl, wvh, wvl, nullptr, nullptr, vh, vl);

    // 3. tensor-core causal flash attention -> att hi/lo bf16
    dim3 gf(S_LEN / 128, NH, BATCH);   // (16, 16, 2)
    flash_mma<<<gf, 256, FLASH_SMEM>>>(qh, ql, kh, kl, vh, vl, ah, al);

    // 4. output projection (fp32 out + bias)
    gemm_mma<<<gg, 256, GEMM_SMEM>>>(ah, al, wph, wpl, bp, out, nullptr, nullptr);
}

// round 15
// speedup vs baseline: 4.6839x; 1.4791x over previous
#include <cuda_runtime.h>
#include <cuda_bf16.h>
#include <cstdint>

#define S_LEN 2048
#define EMB   1024
#define NH    16
#define HD    64
#define BATCH 2
#define ROWS  (BATCH * S_LEN)   // 4096

// ---------------------------------------------------------------------------
// Scratch (__device__ globals: allocation-free rule). All tf32-in-fp32 bits.
// ---------------------------------------------------------------------------
__device__ float g_xt[ROWS * EMB];          // x  (tf32)
__device__ float g_qt[ROWS * EMB];          // Q  (tf32)
__device__ float g_kt[ROWS * EMB];          // K  (tf32)
__device__ float g_vtT[EMB * ROWS];         // V^T [emb_col][row]  (tf32)
__device__ float g_at[ROWS * EMB];          // att (tf32)
__device__ float g_wqt[EMB * EMB];          // W^T [N][K] (tf32)
__device__ float g_wkt[EMB * EMB];
__device__ float g_wvt[EMB * EMB];
__device__ float g_wpt[EMB * EMB];

// ---------------------------------------------------------------------------
// Generic-PTX helpers (NO tcgen05/TMEM: harness PTX target is family sm_103)
// ---------------------------------------------------------------------------
__device__ __forceinline__ uint32_t smem_u32(const void* p) {
    uint32_t a;
    asm("{ .reg .u64 t; cvta.to.shared.u64 t, %1; cvt.u32.u64 %0, t; }" : "=r"(a) : "l"(p));
    return a;
}

#define LDSM_X4(r, a)                                                          \
    asm volatile("ldmatrix.sync.aligned.m8n8.x4.shared.b16 {%0,%1,%2,%3}, [%4];" \
                 : "=r"((r)[0]), "=r"((r)[1]), "=r"((r)[2]), "=r"((r)[3])      \
                 : "r"(a))

// tf32 m16n8k8: A = 4 regs, B = 2 regs, C/D = 4 fp32.
// tf32 frag layouts coincide with ldmatrix.b16 output on 4B-element rows.
#define MMATF32(d, a, b)                                                       \
    asm volatile("mma.sync.aligned.m16n8k8.row.col.f32.tf32.tf32.f32 "         \
                 "{%0,%1,%2,%3}, {%4,%5,%6,%7}, {%8,%9}, {%0,%1,%2,%3};"       \
                 : "+f"((d)[0]), "+f"((d)[1]), "+f"((d)[2]), "+f"((d)[3])      \
                 : "r"((a)[0]), "r"((a)[1]), "r"((a)[2]), "r"((a)[3]),         \
                   "r"((b)[0]), "r"((b)[1]))

// x4 ldsm r0..r3 -> the two n8 fragment pairs: {r0,r2} (rows 0-7), {r1,r3} (rows 8-15)
#define MMA_B0(d, a, t)                                                        \
    { uint32_t _b[2] = {(t)[0], (t)[2]}; MMATF32(d, a, _b); }
#define MMA_B1(d, a, t)                                                        \
    { uint32_t _b[2] = {(t)[1], (t)[3]}; MMATF32(d, a, _b); }

#define CP_ASYNC16(saddr, gaddr)                                               \
    asm volatile("cp.async.cg.shared.global [%0], [%1], 16;"                   \
                 :: "r"(saddr), "l"(gaddr))
#define CP_COMMIT()  asm volatile("cp.async.commit_group;" ::: "memory")
#define CP_WAIT0()   asm volatile("cp.async.wait_group 0;" ::: "memory")

// XOR swizzles: conflict-free for 16B cp.async stores and ldmatrix reads.
#define SWZ128(row, c) ((uint32_t)(((row) << 7) + (((((c) ^ (row)) & 7)) << 4)))
#define SWZ256(row, c) ((uint32_t)(((row) << 8) + ((((((c) ^ (row)) & 7)) | ((c) & 8)) << 4)))

__device__ __forceinline__ uint32_t cvt_tf32(float f) {
    uint32_t u;
    asm("cvt.rna.tf32.f32 %0, %1;" : "=r"(u) : "f"(f));
    return u;
}

// ---------------------------------------------------------------------------
// fp32 -> tf32 (rna) elementwise
// ---------------------------------------------------------------------------
__global__ void __launch_bounds__(256) cvt_tf32_k(const float* __restrict__ s,
                                                  uint32_t* __restrict__ d)
{
    int i = (blockIdx.x * 256 + threadIdx.x) * 4;
    float4 v = *(const float4*)(s + i);
    uint4 o;
    o.x = cvt_tf32(v.x); o.y = cvt_tf32(v.y);
    o.z = cvt_tf32(v.z); o.w = cvt_tf32(v.w);
    *(uint4*)(d + i) = o;
}

// ---------------------------------------------------------------------------
// 4x fused: W[K,N] -> W^T[N,K] tf32 (z selects matrix)
// ---------------------------------------------------------------------------
struct TPtrs {
    const float* W[4];
    uint32_t* T[4];
};

__global__ void __launch_bounds__(256) transpose_cvt4(TPtrs p)
{
    __shared__ float t[32][33];
    const float* W = p.W[blockIdx.z];
    uint32_t* T = p.T[blockIdx.z];
    int n0 = blockIdx.x * 32, k0 = blockIdx.y * 32;
    int tx = threadIdx.x & 31, ty = threadIdx.x >> 5;
    #pragma unroll
    for (int i = 0; i < 32; i += 8)
        t[ty + i][tx] = W[(size_t)(k0 + ty + i) * EMB + n0 + tx];
    __syncthreads();
    #pragma unroll
    for (int i = 0; i < 32; i += 8)
        T[(size_t)(n0 + ty + i) * EMB + k0 + tx] = cvt_tf32(t[tx][ty + i]);
}

// ---------------------------------------------------------------------------
// TF32 HMMA GEMM: C = A @ W.  A [M,K] tf32 row-major, B = W^T [N,K] tf32.
// 128x128 CTA tile, BK=32 (128B rows), 8 warps (2m x 4n), 64x32 warp tile,
// cp.async double buffer, single-pass tf32 MMA, fp32 acc.
// Epilogues: fp32+bias (final) | tf32 row-major (Q,K) | tf32 transposed (V).
// ---------------------------------------------------------------------------
#define BK      32
#define NKT     (EMB / BK)            // 32
#define GTILE_B (128 * 128)           // 16384: 128 rows x 128B
#define GSTAGE  (2 * GTILE_B)         // A + B = 32768
#define GEMM_SMEM (2 * GSTAGE)        // 65536

__device__ __forceinline__ void stage_load_t(uint32_t sb,
                                             const float* __restrict__ A,
                                             const float* __restrict__ B,
                                             int row0, int col0, int k0, int tid)
{
    #pragma unroll
    for (int it = 0; it < 4; it++) {
        int idx = it * 256 + tid;              // 0..1023
        int row = idx >> 3, c = idx & 7;       // 128 rows x 8 chunks
        uint32_t so = SWZ128(row, c);
        CP_ASYNC16(sb + so,           A + (size_t)(row0 + row) * EMB + k0 + c * 4);
        CP_ASYNC16(sb + GTILE_B + so, B + (size_t)(col0 + row) * EMB + k0 + c * 4);
    }
}

__global__ void __launch_bounds__(256) gemm_tf32(const float* __restrict__ At,
                                                 const float* __restrict__ Bt,
                                                 const float* __restrict__ bias,
                                                 float* __restrict__ C,
                                                 uint32_t* __restrict__ Ct,
                                                 uint32_t* __restrict__ CtT)
{
    extern __shared__ char dynsm[];
    const uint32_t smbase = smem_u32(dynsm);

    const int tid  = threadIdx.x;
    const int lane = tid & 31;
    const int warp = tid >> 5;
    const int wm   = warp & 1;
    const int wn   = warp >> 1;
    const int row0 = blockIdx.y * 128;
    const int col0 = blockIdx.x * 128;

    float acc[4][4][4];
    #pragma unroll
    for (int i = 0; i < 4; i++)
        #pragma unroll
        for (int j = 0; j < 4; j++)
            #pragma unroll
            for (int r = 0; r < 4; r++) acc[i][j][r] = 0.f;

    const int lrow = lane & 15;
    const int lhalf = lane >> 4;

    stage_load_t(smbase, At, Bt, row0, col0, 0, tid);
    CP_COMMIT();

    #pragma unroll 1
    for (int t = 0; t < NKT; t++) {
        const uint32_t sb = smbase + (uint32_t)(t & 1) * GSTAGE;
        CP_WAIT0();
        __syncthreads();

        #pragma unroll
        for (int kc = 0; kc < 4; kc++) {       // 4 k8 chunks per BK=32
            const int chunk = kc * 2 + lhalf;

            uint32_t bt[2][4];
            #pragma unroll
            for (int ng = 0; ng < 2; ng++) {
                uint32_t row = (uint32_t)(wn * 32 + ng * 16 + lrow);
                LDSM_X4(bt[ng], sb + GTILE_B + SWZ128(row, chunk));
            }

            uint32_t af[2][4];
            LDSM_X4(af[0], sb + SWZ128((uint32_t)(wm * 64 + lrow), chunk));
            #pragma unroll
            for (int mf = 0; mf < 4; mf++) {
                const int cur = mf & 1, nxt = cur ^ 1;
                if (mf < 3)
                    LDSM_X4(af[nxt], sb + SWZ128((uint32_t)(wm * 64 + (mf + 1) * 16 + lrow), chunk));
                MMA_B0(acc[mf][0], af[cur], bt[0]);
                MMA_B1(acc[mf][1], af[cur], bt[0]);
                MMA_B0(acc[mf][2], af[cur], bt[1]);
                MMA_B1(acc[mf][3], af[cur], bt[1]);
            }

            if (kc == 0 && t + 1 < NKT) {
                stage_load_t(smbase + (uint32_t)((t + 1) & 1) * GSTAGE,
                             At, Bt, row0, col0, (t + 1) * BK, tid);
                CP_COMMIT();
            }
        }
    }

    #pragma unroll
    for (int mf = 0; mf < 4; mf++) {
        #pragma unroll
        for (int nf = 0; nf < 4; nf++) {
            int r  = row0 + wm * 64 + mf * 16 + (lane >> 2);
            int cb = col0 + wn * 32 + nf * 8 + (lane & 3) * 2;
            if (CtT) {
                CtT[(size_t)cb * ROWS + r]           = cvt_tf32(acc[mf][nf][0]);
                CtT[(size_t)(cb + 1) * ROWS + r]     = cvt_tf32(acc[mf][nf][1]);
                CtT[(size_t)cb * ROWS + r + 8]       = cvt_tf32(acc[mf][nf][2]);
                CtT[(size_t)(cb + 1) * ROWS + r + 8] = cvt_tf32(acc[mf][nf][3]);
            } else if (Ct) {
                uint2 u0 = make_uint2(cvt_tf32(acc[mf][nf][0]), cvt_tf32(acc[mf][nf][1]));
                uint2 u1 = make_uint2(cvt_tf32(acc[mf][nf][2]), cvt_tf32(acc[mf][nf][3]));
                *(uint2*)(Ct + (size_t)r * EMB + cb) = u0;
                *(uint2*)(Ct + (size_t)(r + 8) * EMB + cb) = u1;
            } else {
                float b0 = 0.f, b1 = 0.f;
                if (bias) { b0 = bias[cb]; b1 = bias[cb + 1]; }
                *(float2*)(C + (size_t)r * EMB + cb) =
                    make_float2(acc[mf][nf][0] + b0, acc[mf][nf][1] + b1);
                *(float2*)(C + (size_t)(r + 8) * EMB + cb) =
                    make_float2(acc[mf][nf][2] + b0, acc[mf][nf][3] + b1);
            }
        }
    }
}

// ---------------------------------------------------------------------------
// TF32 causal flash attention. CTA: 128 q-rows x (b,h); 8 warps (16 q-rows
// each); k-tile 64. Q/K tf32 [row][EMB]; V^T tf32 [emb_col][row].
// Q smem overlaid on KV stage 1 (dead after one-time frag load). 64 KB total.
// ---------------------------------------------------------------------------
#define FKT        16384                // 64 rows x 256B (one K or V tile)
#define FSTAGE     (2 * FKT)            // K + V^T = 32768
#define FQ_OFF     FSTAGE               // Q overlays stage 1 (32KB)
#define FLASH_SMEM (2 * FSTAGE)         // 65536

__device__ __forceinline__ void kv_stage_t(uint32_t sb,
                                           const float* __restrict__ Kt,
                                           const float* __restrict__ VtT,
                                           size_t kbase, size_t vbase,
                                           int k0, int tid)
{
    #pragma unroll
    for (int it = 0; it < 4; it++) {
        int idx = it * 256 + tid;              // 0..1023
        int row = idx >> 4, c = idx & 15;      // 64 rows x 16 chunks
        uint32_t so = SWZ256(row, c);
        CP_ASYNC16(sb + so,       Kt  + kbase + (size_t)(k0 + row) * EMB + c * 4);
        CP_ASYNC16(sb + FKT + so, VtT + vbase + (size_t)row * ROWS + k0 + c * 4);
    }
}

__global__ void __launch_bounds__(256, 2) flash_tf32(
    const float* __restrict__ Qt, const float* __restrict__ Kt,
    const float* __restrict__ VtT, uint32_t* __restrict__ At)
{
    extern __shared__ char dynsm[];
    const uint32_t smbase = smem_u32(dynsm);
    const uint32_t sQ = smbase + FQ_OFF;

    const int tid  = threadIdx.x;
    const int lane = tid & 31;
    const int warp = tid >> 5;
    const int qt = gridDim.x - 1 - blockIdx.x;   // heaviest causal tiles first
    const int h = blockIdx.y, b = blockIdx.z;
    const int q0 = qt * 128;
    const int wrow = warp * 16;
    const size_t gbase = ((size_t)b * S_LEN) * EMB + (size_t)h * HD;     // Q/K/att
    const size_t vbase = ((size_t)h * HD) * ROWS + (size_t)b * S_LEN;    // V^T

    const int lrow = lane & 15;
    const int lhalf = lane >> 4;

    #pragma unroll
    for (int it = 0; it < 8; it++) {
        int idx = it * 256 + tid;              // 0..2047
        int row = idx >> 4, c = idx & 15;      // 128 rows x 16 chunks
        CP_ASYNC16(sQ + SWZ256(row, c), Qt + gbase + (size_t)(q0 + row) * EMB + c * 4);
    }
    kv_stage_t(smbase, Kt, VtT, gbase, vbase, 0, tid);
    CP_COMMIT();

    const int nkt = 2 * qt + 2;

    uint32_t qf[8][4];
    float o[8][4];
    float m[2] = {-1e30f, -1e30f}, l[2] = {0.f, 0.f};
    #pragma unroll
    for (int nb = 0; nb < 8; nb++)
        #pragma unroll
        for (int j = 0; j < 4; j++) o[nb][j] = 0.f;

    #pragma unroll 1
    for (int kt = 0; kt < nkt; kt++) {
        CP_WAIT0();
        __syncthreads();
        if (kt == 0) {
            #pragma unroll
            for (int kc = 0; kc < 8; kc++)
                LDSM_X4(qf[kc], sQ + SWZ256((uint32_t)(wrow + lrow), kc * 2 + lhalf));
            __syncthreads();   // all Q reads complete before stage-1 overwrites it
        }
        if (kt + 1 < nkt) {
            kv_stage_t(smbase + (uint32_t)((kt + 1) & 1) * FSTAGE,
                       Kt, VtT, gbase, vbase, (kt + 1) * 64, tid);
            CP_COMMIT();
        }

        const int k0 = kt * 64;
        if (k0 > q0 + wrow + 15) continue;   // fully masked for this warp (after barrier!)

        const uint32_t sb = smbase + (uint32_t)(kt & 1) * FSTAGE;

        // ---- S = Q K^T : 32 steps (kc8 x g2), ping-pong K frags ----
        float s[8][4];
        #pragma unroll
        for (int nb = 0; nb < 8; nb++)
            #pragma unroll
            for (int j = 0; j < 4; j++) s[nb][j] = 0.f;

        {
            uint32_t kf[2][4];
            LDSM_X4(kf[0], sb + SWZ256((uint32_t)lrow, lhalf));
            #pragma unroll
            for (int idx = 0; idx < 32; idx++) {
                const int kc = idx >> 2, g2 = idx & 3;
                const int cur = idx & 1, nxt = cur ^ 1;
                if (idx < 31) {
                    const int kc1 = (idx + 1) >> 2, g21 = (idx + 1) & 3;
                    LDSM_X4(kf[nxt], sb + SWZ256((uint32_t)(g21 * 16 + lrow), kc1 * 2 + lhalf));
                }
                MMA_B0(s[2 * g2],     qf[kc], kf[cur]);
                MMA_B1(s[2 * g2 + 1], qf[kc], kf[cur]);
            }
        }

        // ---- scale + causal mask ----
        const bool partial = (k0 + 63 > q0 + wrow);
        const int rg = q0 + wrow + (lane >> 2);
        #pragma unroll
        for (int nb = 0; nb < 8; nb++) {
            int c0 = k0 + nb * 8 + 2 * (lane & 3);
            #pragma unroll
            for (int j = 0; j < 4; j++) {
                float sv = s[nb][j] * 0.125f;
                if (partial && (c0 + (j & 1)) > (rg + (j >> 1) * 8)) sv = -1e30f;
                s[nb][j] = sv;
            }
        }

        // ---- online softmax (fp32) ----
        #pragma unroll
        for (int hf = 0; hf < 2; hf++) {
            const int j0 = hf * 2;
            float rm = -1e30f;
            #pragma unroll
            for (int nb = 0; nb < 8; nb++)
                rm = fmaxf(rm, fmaxf(s[nb][j0], s[nb][j0 + 1]));
            rm = fmaxf(rm, __shfl_xor_sync(0xffffffffu, rm, 1));
            rm = fmaxf(rm, __shfl_xor_sync(0xffffffffu, rm, 2));
            float mn   = fmaxf(m[hf], rm);
            float corr = __expf(m[hf] - mn);
            float rs = 0.f;
            #pragma unroll
            for (int nb = 0; nb < 8; nb++) {
                float p0 = __expf(s[nb][j0] - mn);
                float p1 = __expf(s[nb][j0 + 1] - mn);
                s[nb][j0] = p0; s[nb][j0 + 1] = p1;
                rs += p0 + p1;
            }
            rs += __shfl_xor_sync(0xffffffffu, rs, 1);
            rs += __shfl_xor_sync(0xffffffffu, rs, 2);
            l[hf] = l[hf] * corr + rs;
            m[hf] = mn;
            #pragma unroll
            for (int nb = 0; nb < 8; nb++) { o[nb][j0] *= corr; o[nb][j0 + 1] *= corr; }
        }

        // ---- O += P V : per seq-k8: quad-shuffle P -> tf32 A-frag; V^T ldsm ----
        {
            const int c = lane & 3;
            const int L0 = (lane & 28) | (c >> 1);
            const int L1 = L0 + 2;
            uint32_t vf[2][4];
            uint32_t pf[4] = {0, 0, 0, 0};
            LDSM_X4(vf[0], sb + FKT + SWZ256((uint32_t)lrow, lhalf));
            #pragma unroll
            for (int idx = 0; idx < 32; idx++) {
                const int kc = idx >> 2, g2 = idx & 3;
                const int cur = idx & 1, nxt = cur ^ 1;
                if (g2 == 0) {
                    // a0=[r][c], a1=[r+8][c], a2=[r][c+4], a3=[r+8][c+4]
                    float e0 = __shfl_sync(0xffffffffu, s[kc][0], L0);
                    float e1 = __shfl_sync(0xffffffffu, s[kc][1], L0);
                    float e2 = __shfl_sync(0xffffffffu, s[kc][2], L0);
                    float e3 = __shfl_sync(0xffffffffu, s[kc][3], L0);
                    float e4 = __shfl_sync(0xffffffffu, s[kc][0], L1);
                    float e5 = __shfl_sync(0xffffffffu, s[kc][1], L1);
                    float e6 = __shfl_sync(0xffffffffu, s[kc][2], L1);
                    float e7 = __shfl_sync(0xffffffffu, s[kc][3], L1);
                    pf[0] = cvt_tf32((c & 1) ? e1 : e0);
                    pf[1] = cvt_tf32((c & 1) ? e3 : e2);
                    pf[2] = cvt_tf32((c & 1) ? e5 : e4);
                    pf[3] = cvt_tf32((c & 1) ? e7 : e6);
                }
                if (idx < 31) {
                    const int kc1 = (idx + 1) >> 2, g21 = (idx + 1) & 3;
                    LDSM_X4(vf[nxt], sb + FKT + SWZ256((uint32_t)(g21 * 16 + lrow), kc1 * 2 + lhalf));
                }
                MMA_B0(o[2 * g2],     pf, vf[cur]);
                MMA_B1(o[2 * g2 + 1], pf, vf[cur]);
            }
        }
    }

    // ---- normalize + write att tf32 ----
    #pragma unroll
    for (int hf = 0; hf < 2; hf++) {
        float inv = 1.f / l[hf];
        int grow = q0 + wrow + (lane >> 2) + hf * 8;
        size_t rb = gbase + (size_t)grow * EMB + 2 * (lane & 3);
        #pragma unroll
        for (int nb = 0; nb < 8; nb++) {
            uint2 u = make_uint2(cvt_tf32(o[nb][hf * 2] * inv),
                                 cvt_tf32(o[nb][hf * 2 + 1] * inv));
            *(uint2*)(At + rb + nb * 8) = u;
        }
    }
}

// ---------------------------------------------------------------------------
extern "C" void kernel_launch(void* const* d_in, const int* in_sizes, int n_in,
                              void* d_out, int out_size)
{
    (void)in_sizes; (void)n_in; (void)out_size;
    const float* x  = (const float*)d_in[0];
    const float* Wq = (const float*)d_in[1];
    const float* Wk = (const float*)d_in[2];
    const float* Wv = (const float*)d_in[3];
    const float* Wp = (const float*)d_in[4];
    const float* bp = (const float*)d_in[5];
    float* out = (float*)d_out;

    float *xt, *qt, *kt, *vtT, *at, *wqt, *wkt, *wvt, *wpt;
    cudaGetSymbolAddress((void**)&xt,  g_xt);
    cudaGetSymbolAddress((void**)&qt,  g_qt);
    cudaGetSymbolAddress((void**)&kt,  g_kt);
    cudaGetSymbolAddress((void**)&vtT, g_vtT);
    cudaGetSymbolAddress((void**)&at,  g_at);
    cudaGetSymbolAddress((void**)&wqt, g_wqt);
    cudaGetSymbolAddress((void**)&wkt, g_wkt);
    cudaGetSymbolAddress((void**)&wvt, g_wvt);
    cudaGetSymbolAddress((void**)&wpt, g_wpt);

    cudaFuncSetAttribute(gemm_tf32,  cudaFuncAttributeMaxDynamicSharedMemorySize, GEMM_SMEM);
    cudaFuncSetAttribute(flash_tf32, cudaFuncAttributeMaxDynamicSharedMemorySize, FLASH_SMEM);

    // 1. convert x + transpose-convert weights
    cvt_tf32_k<<<ROWS * EMB / 1024, 256>>>(x, (uint32_t*)xt);
    TPtrs tp;
    tp.W[0] = Wq; tp.T[0] = (uint32_t*)wqt;
    tp.W[1] = Wk; tp.T[1] = (uint32_t*)wkt;
    tp.W[2] = Wv; tp.T[2] = (uint32_t*)wvt;
    tp.W[3] = Wp; tp.T[3] = (uint32_t*)wpt;
    dim3 gt(EMB / 32, EMB / 32, 4);
    transpose_cvt4<<<gt, 256>>>(tp);

    // 2. QKV projections (V written transposed for flash)
    dim3 gg(EMB / 128, ROWS / 128);    // (8, 32)
    gemm_tf32<<<gg, 256, GEMM_SMEM>>>(xt, wqt, nullptr, nullptr, (uint32_t*)qt, nullptr);
    gemm_tf32<<<gg, 256, GEMM_SMEM>>>(xt, wkt, nullptr, nullptr, (uint32_t*)kt, nullptr);
    gemm_tf32<<<gg, 256, GEMM_SMEM>>>(xt, wvt, nullptr, nullptr, nullptr, (uint32_t*)vtT);

    // 3. tf32 causal flash attention -> att tf32
    dim3 gf(S_LEN / 128, NH, BATCH);   // (16, 16, 2)
    flash_tf32<<<gf, 256, FLASH_SMEM>>>(qt, kt, vtT, (uint32_t*)at);

    // 4. output projection (fp32 out + bias)
    gemm_tf32<<<gg, 256, GEMM_SMEM>>>(at, wpt, bp, out, nullptr, nullptr);
}

// round 16
// speedup vs baseline: 7.4021x; 1.5803x over previous
#include <cuda_runtime.h>
#include <cuda_fp16.h>
#include <cstdint>

#define S_LEN 2048
#define EMB   1024
#define NH    16
#define HD    64
#define BATCH 2
#define ROWS  (BATCH * S_LEN)   // 4096

// ---------------------------------------------------------------------------
// Scratch (__device__ globals: allocation-free rule)
// ---------------------------------------------------------------------------
__device__ __half g_xh[ROWS * EMB];          // x   (fp16)
__device__ __half g_qh[ROWS * EMB];          // Q   (fp16)
__device__ __half g_kh[ROWS * EMB];          // K   (fp16)
__device__ __half g_vh[ROWS * EMB];          // V   (fp16)
__device__ __half g_ah[ROWS * EMB];          // att (fp16)
__device__ __half g_wq[EMB * EMB];           // W^T [N][K] (fp16)
__device__ __half g_wk[EMB * EMB];
__device__ __half g_wv[EMB * EMB];
__device__ __half g_wp[EMB * EMB];

// ---------------------------------------------------------------------------
// Generic-PTX helpers (NO tcgen05/TMEM: harness PTX target is family sm_103)
// ---------------------------------------------------------------------------
__device__ __forceinline__ uint32_t smem_u32(const void* p) {
    uint32_t a;
    asm("{ .reg .u64 t; cvta.to.shared.u64 t, %1; cvt.u32.u64 %0, t; }" : "=r"(a) : "l"(p));
    return a;
}

#define LDSM_X4(r, a)                                                          \
    asm volatile("ldmatrix.sync.aligned.m8n8.x4.shared.b16 {%0,%1,%2,%3}, [%4];" \
                 : "=r"((r)[0]), "=r"((r)[1]), "=r"((r)[2]), "=r"((r)[3])      \
                 : "r"(a))

#define LDSM_X4_T(r, a)                                                        \
    asm volatile("ldmatrix.sync.aligned.m8n8.x4.trans.shared.b16 {%0,%1,%2,%3}, [%4];" \
                 : "=r"((r)[0]), "=r"((r)[1]), "=r"((r)[2]), "=r"((r)[3])      \
                 : "r"(a))

// fp16 m16n8k16, fp32 accumulate: 11-bit mantissa (== tf32) at 2x FLOP/instr.
#define MMA16816(d, a, b)                                                      \
    asm volatile("mma.sync.aligned.m16n8k16.row.col.f32.f16.f16.f32 "          \
                 "{%0,%1,%2,%3}, {%4,%5,%6,%7}, {%8,%9}, {%0,%1,%2,%3};"       \
                 : "+f"((d)[0]), "+f"((d)[1]), "+f"((d)[2]), "+f"((d)[3])      \
                 : "r"((a)[0]), "r"((a)[1]), "r"((a)[2]), "r"((a)[3]),         \
                   "r"((b)[0]), "r"((b)[1]))

// b-frag pair helpers (extract the two n8 fragments from an x4 ldsm)
#define MMA_B0(d, a, t)                                                        \
    { uint32_t _b[2] = {(t)[0], (t)[2]}; MMA16816(d, a, _b); }
#define MMA_B1(d, a, t)                                                        \
    { uint32_t _b[2] = {(t)[1], (t)[3]}; MMA16816(d, a, _b); }

#define CP_ASYNC16(saddr, gaddr)                                               \
    asm volatile("cp.async.cg.shared.global [%0], [%1], 16;"                   \
                 :: "r"(saddr), "l"(gaddr))
#define CP_COMMIT()  asm volatile("cp.async.commit_group;" ::: "memory")
#define CP_WAIT0()   asm volatile("cp.async.wait_group 0;" ::: "memory")

// 128B-row XOR swizzle (proven in R14): conflict-free cp.async + ldsm.
#define SWZ128(row, chunk) ((uint32_t)(((row) << 7) + ((((chunk) ^ ((row) & 7)) & 7) << 4)))

__device__ __forceinline__ uint32_t pack_h2(float p0, float p1) {
    __half2 h = __floats2half2_rn(p0, p1);
    return *(uint32_t*)&h;
}

// ---------------------------------------------------------------------------
// fp32 -> fp16 elementwise (for input x)
// ---------------------------------------------------------------------------
__global__ void __launch_bounds__(256) cvt_h(const float* __restrict__ s,
                                             __half* __restrict__ d)
{
    int i = (blockIdx.x * 256 + threadIdx.x) * 2;
    float2 v = *(const float2*)(s + i);
    *(uint32_t*)(d + i) = pack_h2(v.x, v.y);
}

// ---------------------------------------------------------------------------
// 4x fused: W[K,N] -> W^T[N,K] fp16 (z selects matrix)
// ---------------------------------------------------------------------------
struct TPtrs {
    const float* W[4];
    __half* T[4];
};

__global__ void __launch_bounds__(256) transpose_cvt4(TPtrs p)
{
    __shared__ float t[32][33];
    const float* W = p.W[blockIdx.z];
    __half* T = p.T[blockIdx.z];
    int n0 = blockIdx.x * 32, k0 = blockIdx.y * 32;
    int tx = threadIdx.x & 31, ty = threadIdx.x >> 5;
    #pragma unroll
    for (int i = 0; i < 32; i += 8)
        t[ty + i][tx] = W[(size_t)(k0 + ty + i) * EMB + n0 + tx];
    __syncthreads();
    #pragma unroll
    for (int i = 0; i < 32; i += 8)
        T[(size_t)(n0 + ty + i) * EMB + k0 + tx] = __float2half_rn(t[tx][ty + i]);
}

// ---------------------------------------------------------------------------
// FP16 HMMA GEMM: C = A @ W.  A [M,K] fp16 row-major, B = W^T [N,K] fp16.
// 128x128 CTA tile, BK=32, 8 warps (2m x 4n), 64x32 warp tile, cp.async
// double buffer, single-pass fp16 MMA, fp32 acc.
// ---------------------------------------------------------------------------
#define BK      32
#define NKT     (EMB / BK)            // 32
#define TPITCH  80                    // 64B rows padded (proven conflict-free)
#define TILE_B  (128 * TPITCH)        // 10240
#define GSTAGE  (2 * TILE_B)          // A + B = 20480
#define GEMM_SMEM (2 * GSTAGE)        // 40960

__device__ __forceinline__ void stage_load(uint32_t sb,
                                           const __half* __restrict__ A,
                                           const __half* __restrict__ B,
                                           int row0, int col0, int k0, int tid)
{
    #pragma unroll
    for (int it = 0; it < 2; it++) {
        int idx = it * 256 + tid;              // 0..511
        int row = idx >> 2, c = idx & 3;       // 128 rows x 4 chunks (16B)
        uint32_t soff = (uint32_t)(row * TPITCH + c * 16);
        CP_ASYNC16(sb + soff,          A + (size_t)(row0 + row) * EMB + k0 + c * 8);
        CP_ASYNC16(sb + TILE_B + soff, B + (size_t)(col0 + row) * EMB + k0 + c * 8);
    }
}

__global__ void __launch_bounds__(256) gemm_fp16(const __half* __restrict__ At,
                                                 const __half* __restrict__ Bt,
                                                 const float* __restrict__ bias,
                                                 float* __restrict__ C,
                                                 __half* __restrict__ Ch)
{
    extern __shared__ char dynsm[];
    const uint32_t smbase = smem_u32(dynsm);

    const int tid  = threadIdx.x;
    const int lane = tid & 31;
    const int warp = tid >> 5;
    const int wm   = warp & 1;
    const int wn   = warp >> 1;
    const int row0 = blockIdx.y * 128;
    const int col0 = blockIdx.x * 128;

    float acc[4][4][4];
    #pragma unroll
    for (int i = 0; i < 4; i++)
        #pragma unroll
        for (int j = 0; j < 4; j++)
            #pragma unroll
            for (int r = 0; r < 4; r++) acc[i][j][r] = 0.f;

    const uint32_t lmA = (uint32_t)((wm * 64 + (lane & 15)) * TPITCH + ((lane >> 4) << 4));
    const uint32_t lmB = (uint32_t)((wn * 32 + (lane & 15)) * TPITCH + ((lane >> 4) << 4));

    stage_load(smbase, At, Bt, row0, col0, 0, tid);
    CP_COMMIT();

    #pragma unroll 1
    for (int t = 0; t < NKT; t++) {
        const uint32_t sb = smbase + (uint32_t)(t & 1) * GSTAGE;
        CP_WAIT0();
        __syncthreads();

        #pragma unroll
        for (int ks = 0; ks < 2; ks++) {
            const uint32_t ko = (uint32_t)(ks * 32);

            // B frags for this k16: 2 x4 ldsm -> 4 nf groups
            uint32_t bt[4][2];
            #pragma unroll
            for (int ng = 0; ng < 2; ng++) {
                uint32_t tmp[4];
                LDSM_X4(tmp, sb + TILE_B + lmB + (uint32_t)(ng * 16 * TPITCH) + ko);
                bt[2 * ng][0] = tmp[0]; bt[2 * ng + 1][0] = tmp[1];
                bt[2 * ng][1] = tmp[2]; bt[2 * ng + 1][1] = tmp[3];
            }

            // A frags ping-pong over mf, 4 MMA each
            uint32_t af[2][4];
            LDSM_X4(af[0], sb + lmA + ko);
            #pragma unroll
            for (int mf = 0; mf < 4; mf++) {
                const int cur = mf & 1, nxt = cur ^ 1;
                if (mf < 3)
                    LDSM_X4(af[nxt], sb + lmA + (uint32_t)((mf + 1) * 16 * TPITCH) + ko);
                #pragma unroll
                for (int nf = 0; nf < 4; nf++)
                    MMA16816(acc[mf][nf], af[cur], bt[nf]);
            }

            if (ks == 0 && t + 1 < NKT) {
                stage_load(smbase + (uint32_t)((t + 1) & 1) * GSTAGE,
                           At, Bt, row0, col0, (t + 1) * BK, tid);
                CP_COMMIT();
            }
        }
    }

    #pragma unroll
    for (int mf = 0; mf < 4; mf++) {
        #pragma unroll
        for (int nf = 0; nf < 4; nf++) {
            int r  = row0 + wm * 64 + mf * 16 + (lane >> 2);
            int cb = col0 + wn * 32 + nf * 8 + (lane & 3) * 2;
            if (Ch) {
                *(uint32_t*)(Ch + (size_t)r * EMB + cb) =
                    pack_h2(acc[mf][nf][0], acc[mf][nf][1]);
                *(uint32_t*)(Ch + (size_t)(r + 8) * EMB + cb) =
                    pack_h2(acc[mf][nf][2], acc[mf][nf][3]);
            } else {
                float b0 = 0.f, b1 = 0.f;
                if (bias) { b0 = bias[cb]; b1 = bias[cb + 1]; }
                *(float2*)(C + (size_t)r * EMB + cb) =
                    make_float2(acc[mf][nf][0] + b0, acc[mf][nf][1] + b1);
                *(float2*)(C + (size_t)(r + 8) * EMB + cb) =
                    make_float2(acc[mf][nf][2] + b0, acc[mf][nf][3] + b1);
            }
        }
    }
}

// ---------------------------------------------------------------------------
// FP16 causal flash attention. CTA: 128 q-rows x (b,h); 8 warps (16 q-rows
// each); k-tile 64. Single fp16 stream; V via ldmatrix.trans.
// Q (16KB) overlays KV stage 1 (dead after one-time frag load). 32KB smem.
// ---------------------------------------------------------------------------
#define KVT        8192                 // 64 rows x 128B
#define FSTAGE     (2 * KVT)            // K + V = 16384
#define FQ_OFF     FSTAGE               // Q overlays stage 1 (16KB)
#define FLASH_SMEM (2 * FSTAGE)         // 32768

__device__ __forceinline__ void kv_stage(uint32_t sb,
                                         const __half* __restrict__ Kh,
                                         const __half* __restrict__ Vh,
                                         size_t gbase, int k0, int tid)
{
    #pragma unroll
    for (int it = 0; it < 2; it++) {
        int idx = it * 256 + tid;              // 0..511
        int row = idx >> 3, c = idx & 7;       // 64 rows x 8 chunks
        size_t g = gbase + (size_t)(k0 + row) * EMB + c * 8;
        uint32_t so = SWZ128(row, c);
        CP_ASYNC16(sb + so,       Kh + g);
        CP_ASYNC16(sb + KVT + so, Vh + g);
    }
}

__global__ void __launch_bounds__(256, 2) flash_fp16(
    const __half* __restrict__ Qh, const __half* __restrict__ Kh,
    const __half* __restrict__ Vh, __half* __restrict__ Oh)
{
    extern __shared__ char dynsm[];
    const uint32_t smbase = smem_u32(dynsm);
    const uint32_t sQ = smbase + FQ_OFF;

    const int tid  = threadIdx.x;
    const int lane = tid & 31;
    const int warp = tid >> 5;
    const int qt = gridDim.x - 1 - blockIdx.x;   // heaviest causal tiles first
    const int h = blockIdx.y, b = blockIdx.z;
    const int q0 = qt * 128;
    const int wrow = warp * 16;
    const size_t gbase = ((size_t)b * S_LEN) * EMB + (size_t)h * HD;

    // prologue: Q (into stage-1 region) + KV stage 0
    #pragma unroll
    for (int it = 0; it < 4; it++) {
        int idx = it * 256 + tid;              // 0..1023
        int row = idx >> 3, c = idx & 7;       // 128 rows x 8 chunks
        CP_ASYNC16(sQ + SWZ128(row, c), Qh + gbase + (size_t)(q0 + row) * EMB + c * 8);
    }
    kv_stage(smbase, Kh, Vh, gbase, 0, tid);
    CP_COMMIT();

    const int nkt = 2 * qt + 2;

    uint32_t qf[4][4];
    float o[8][4];
    float m[2] = {-1e30f, -1e30f}, l[2] = {0.f, 0.f};
    #pragma unroll
    for (int nb = 0; nb < 8; nb++)
        #pragma unroll
        for (int j = 0; j < 4; j++) o[nb][j] = 0.f;

    #pragma unroll 1
    for (int kt = 0; kt < nkt; kt++) {
        CP_WAIT0();
        __syncthreads();
        if (kt == 0) {
            // one-time Q fragment load; Q smem dead afterwards
            #pragma unroll
            for (int kc = 0; kc < 4; kc++) {
                uint32_t row = (uint32_t)(wrow + (lane & 15));
                LDSM_X4(qf[kc], sQ + SWZ128(row, kc * 2 + (lane >> 4)));
            }
            __syncthreads();   // all Q reads complete before stage-1 overwrites it
        }
        if (kt + 1 < nkt) {
            kv_stage(smbase + (uint32_t)((kt + 1) & 1) * FSTAGE,
                     Kh, Vh, gbase, (kt + 1) * 64, tid);
            CP_COMMIT();
        }

        const int k0 = kt * 64;
        if (k0 > q0 + wrow + 15) continue;   // fully masked for this warp (after barrier!)

        const uint32_t sb = smbase + (uint32_t)(kt & 1) * FSTAGE;

        // ---- S = Q K^T : 16 steps (kc x g2), ping-pong K frags, 2 MMA each ----
        float s[8][4];
        #pragma unroll
        for (int nb = 0; nb < 8; nb++)
            #pragma unroll
            for (int j = 0; j < 4; j++) s[nb][j] = 0.f;

        {
            uint32_t kf[2][4];
            LDSM_X4(kf[0], sb + SWZ128((uint32_t)(lane & 15), (lane >> 4)));
            #pragma unroll
            for (int idx = 0; idx < 16; idx++) {
                const int kc = idx >> 2, g2 = idx & 3;
                const int cur = idx & 1, nxt = cur ^ 1;
                if (idx < 15) {
                    const int kc1 = (idx + 1) >> 2, g21 = (idx + 1) & 3;
                    uint32_t row = (uint32_t)(g21 * 16 + (lane & 15));
                    LDSM_X4(kf[nxt], sb + SWZ128(row, kc1 * 2 + (lane >> 4)));
                }
                MMA_B0(s[2 * g2],     qf[kc], kf[cur]);
                MMA_B1(s[2 * g2 + 1], qf[kc], kf[cur]);
            }
        }

        // ---- scale + causal mask ----
        const bool partial = (k0 + 63 > q0 + wrow);
        const int rg = q0 + wrow + (lane >> 2);
        #pragma unroll
        for (int nb = 0; nb < 8; nb++) {
            int c0 = k0 + nb * 8 + 2 * (lane & 3);
            #pragma unroll
            for (int j = 0; j < 4; j++) {
                float sv = s[nb][j] * 0.125f;
                if (partial && (c0 + (j & 1)) > (rg + (j >> 1) * 8)) sv = -1e30f;
                s[nb][j] = sv;
            }
        }

        // ---- online softmax (fp32) ----
        #pragma unroll
        for (int hf = 0; hf < 2; hf++) {
            const int j0 = hf * 2;
            float rm = -1e30f;
            #pragma unroll
            for (int nb = 0; nb < 8; nb++)
                rm = fmaxf(rm, fmaxf(s[nb][j0], s[nb][j0 + 1]));
            rm = fmaxf(rm, __shfl_xor_sync(0xffffffffu, rm, 1));
            rm = fmaxf(rm, __shfl_xor_sync(0xffffffffu, rm, 2));
            float mn   = fmaxf(m[hf], rm);
            float corr = __expf(m[hf] - mn);
            float rs = 0.f;
            #pragma unroll
            for (int nb = 0; nb < 8; nb++) {
                float p0 = __expf(s[nb][j0] - mn);
                float p1 = __expf(s[nb][j0 + 1] - mn);
                s[nb][j0] = p0; s[nb][j0 + 1] = p1;
                rs += p0 + p1;
            }
            rs += __shfl_xor_sync(0xffffffffu, rs, 1);
            rs += __shfl_xor_sync(0xffffffffu, rs, 2);
            l[hf] = l[hf] * corr + rs;
            m[hf] = mn;
            #pragma unroll
            for (int nb = 0; nb < 8; nb++) { o[nb][j0] *= corr; o[nb][j0 + 1] *= corr; }
        }

        // ---- O += P V : 16 steps; P packed to fp16 per kc; V via trans-ldsm ----
        {
            uint32_t vf[2][4];
            uint32_t pf[4] = {0, 0, 0, 0};
            {
                uint32_t row = (uint32_t)((lane & 7) + ((lane >> 4) << 3));
                LDSM_X4_T(vf[0], sb + KVT + SWZ128(row, (lane >> 3) & 1));
            }
            #pragma unroll
            for (int idx = 0; idx < 16; idx++) {
                const int kc = idx >> 2, g2 = idx & 3;
                const int cur = idx & 1, nxt = cur ^ 1;
                if (g2 == 0) {
                    #pragma unroll
                    for (int t = 0; t < 4; t++) {
                        int nb = 2 * kc + (t >> 1);
                        int j0 = (t & 1) * 2;
                        pf[t] = pack_h2(s[nb][j0], s[nb][j0 + 1]);
                    }
                }
                if (idx < 15) {
                    const int kc1 = (idx + 1) >> 2, g21 = (idx + 1) & 3;
                    uint32_t row = (uint32_t)(kc1 * 16 + (lane & 7) + ((lane >> 4) << 3));
                    LDSM_X4_T(vf[nxt], sb + KVT + SWZ128(row, g21 * 2 + ((lane >> 3) & 1)));
                }
                MMA_B0(o[2 * g2],     pf, vf[cur]);
                MMA_B1(o[2 * g2 + 1], pf, vf[cur]);
            }
        }
    }

    // ---- normalize + write att fp16 ----
    #pragma unroll
    for (int hf = 0; hf < 2; hf++) {
        float inv = 1.f / l[hf];
        int grow = q0 + wrow + (lane >> 2) + hf * 8;
        size_t rb = gbase + (size_t)grow * EMB + 2 * (lane & 3);
        #pragma unroll
        for (int nb = 0; nb < 8; nb++)
            *(uint32_t*)(Oh + rb + nb * 8) =
                pack_h2(o[nb][hf * 2] * inv, o[nb][hf * 2 + 1] * inv);
    }
}

// ---------------------------------------------------------------------------
extern "C" void kernel_launch(void* const* d_in, const int* in_sizes, int n_in,
                              void* d_out, int out_size)
{
    (void)in_sizes; (void)n_in; (void)out_size;
    const float* x  = (const float*)d_in[0];
    const float* Wq = (const float*)d_in[1];
    const float* Wk = (const float*)d_in[2];
    const float* Wv = (const float*)d_in[3];
    const float* Wp = (const float*)d_in[4];
    const float* bp = (const float*)d_in[5];
    float* out = (float*)d_out;

    __half *xh, *qh, *kh, *vh, *ah, *wq, *wk, *wv, *wp;
    cudaGetSymbolAddress((void**)&xh, g_xh);
    cudaGetSymbolAddress((void**)&qh, g_qh);
    cudaGetSymbolAddress((void**)&kh, g_kh);
    cudaGetSymbolAddress((void**)&vh, g_vh);
    cudaGetSymbolAddress((void**)&ah, g_ah);
    cudaGetSymbolAddress((void**)&wq, g_wq);
    cudaGetSymbolAddress((void**)&wk, g_wk);
    cudaGetSymbolAddress((void**)&wv, g_wv);
    cudaGetSymbolAddress((void**)&wp, g_wp);

    cudaFuncSetAttribute(gemm_fp16,  cudaFuncAttributeMaxDynamicSharedMemorySize, GEMM_SMEM);
    cudaFuncSetAttribute(flash_fp16, cudaFuncAttributeMaxDynamicSharedMemorySize, FLASH_SMEM);

    // 1. convert x + transpose-convert weights
    cvt_h<<<ROWS * EMB / 512, 256>>>(x, xh);
    TPtrs tp;
    tp.W[0] = Wq; tp.T[0] = wq;
    tp.W[1] = Wk; tp.T[1] = wk;
    tp.W[2] = Wv; tp.T[2] = wv;
    tp.W[3] = Wp; tp.T[3] = wp;
    dim3 gt(EMB / 32, EMB / 32, 4);
    transpose_cvt4<<<gt, 256>>>(tp);

    // 2. QKV projections -> fp16 epilogue
    dim3 gg(EMB / 128, ROWS / 128);    // (8, 32)
    gemm_fp16<<<gg, 256, GEMM_SMEM>>>(xh, wq, nullptr, nullptr, qh);
    gemm_fp16<<<gg, 256, GEMM_SMEM>>>(xh, wk, nullptr, nullptr, kh);
    gemm_fp16<<<gg, 256, GEMM_SMEM>>>(xh, wv, nullptr, nullptr, vh);

    // 3. fp16 causal flash attention -> att fp16
    dim3 gf(S_LEN / 128, NH, BATCH);   // (16, 16, 2)
    flash_fp16<<<gf, 256, FLASH_SMEM>>>(qh, kh, vh, ah);

    // 4. output projection (fp32 out + bias)
    gemm_fp16<<<gg, 256, GEMM_SMEM>>>(ah, wp, bp, out, nullptr);
}

// round 17
// speedup vs baseline: 7.6191x; 1.0293x over previous
#include <cuda_runtime.h>
#include <cuda_fp16.h>
#include <cstdint>

#define S_LEN 2048
#define EMB   1024
#define NH    16
#define HD    64
#define BATCH 2
#define ROWS  (BATCH * S_LEN)   // 4096

// ---------------------------------------------------------------------------
// Scratch (__device__ globals: allocation-free rule)
// ---------------------------------------------------------------------------
__device__ __half g_xh[ROWS * EMB];            // x   (fp16)
__device__ __half g_qh[ROWS * EMB];            // Q   (fp16)
__device__ __half g_kh[ROWS * EMB];            // K   (fp16)
__device__ __half g_vh[ROWS * EMB];            // V   (fp16)
__device__ __half g_ah[ROWS * EMB];            // att (fp16)
__device__ __half g_wqkv[3 * EMB * EMB];       // concat W^T: [Q|K|V] rows [3072][1024]
__device__ __half g_wp[EMB * EMB];             // Wp^T [N][K]

// ---------------------------------------------------------------------------
// Generic-PTX helpers (NO tcgen05/TMEM: harness PTX target is family sm_103)
// ---------------------------------------------------------------------------
__device__ __forceinline__ uint32_t smem_u32(const void* p) {
    uint32_t a;
    asm("{ .reg .u64 t; cvta.to.shared.u64 t, %1; cvt.u32.u64 %0, t; }" : "=r"(a) : "l"(p));
    return a;
}

#define LDSM_X4(r, a)                                                          \
    asm volatile("ldmatrix.sync.aligned.m8n8.x4.shared.b16 {%0,%1,%2,%3}, [%4];" \
                 : "=r"((r)[0]), "=r"((r)[1]), "=r"((r)[2]), "=r"((r)[3])      \
                 : "r"(a))

#define LDSM_X4_T(r, a)                                                        \
    asm volatile("ldmatrix.sync.aligned.m8n8.x4.trans.shared.b16 {%0,%1,%2,%3}, [%4];" \
                 : "=r"((r)[0]), "=r"((r)[1]), "=r"((r)[2]), "=r"((r)[3])      \
                 : "r"(a))

#define MMA16816(d, a, b)                                                      \
    asm volatile("mma.sync.aligned.m16n8k16.row.col.f32.f16.f16.f32 "          \
                 "{%0,%1,%2,%3}, {%4,%5,%6,%7}, {%8,%9}, {%0,%1,%2,%3};"       \
                 : "+f"((d)[0]), "+f"((d)[1]), "+f"((d)[2]), "+f"((d)[3])      \
                 : "r"((a)[0]), "r"((a)[1]), "r"((a)[2]), "r"((a)[3]),         \
                   "r"((b)[0]), "r"((b)[1]))

#define MMA_B0(d, a, t)                                                        \
    { uint32_t _b[2] = {(t)[0], (t)[2]}; MMA16816(d, a, _b); }
#define MMA_B1(d, a, t)                                                        \
    { uint32_t _b[2] = {(t)[1], (t)[3]}; MMA16816(d, a, _b); }

#define CP_ASYNC16(saddr, gaddr)                                               \
    asm volatile("cp.async.cg.shared.global [%0], [%1], 16;"                   \
                 :: "r"(saddr), "l"(gaddr))
#define CP_COMMIT()  asm volatile("cp.async.commit_group;" ::: "memory")
#define CP_WAIT0()   asm volatile("cp.async.wait_group 0;" ::: "memory")

#define SWZ128(row, chunk) ((uint32_t)(((row) << 7) + ((((chunk) ^ ((row) & 7)) & 7) << 4)))

__device__ __forceinline__ uint32_t pack_h2(float p0, float p1) {
    __half2 h = __floats2half2_rn(p0, p1);
    return *(uint32_t*)&h;
}

// ---------------------------------------------------------------------------
// fp32 -> fp16 elementwise (for input x)
// ---------------------------------------------------------------------------
__global__ void __launch_bounds__(256) cvt_h(const float* __restrict__ s,
                                             __half* __restrict__ d)
{
    int i = (blockIdx.x * 256 + threadIdx.x) * 2;
    float2 v = *(const float2*)(s + i);
    *(uint32_t*)(d + i) = pack_h2(v.x, v.y);
}

// ---------------------------------------------------------------------------
// 4x fused: W[K,N] -> W^T[N,K] fp16 (z selects matrix)
// ---------------------------------------------------------------------------
struct TPtrs {
    const float* W[4];
    __half* T[4];
};

__global__ void __launch_bounds__(256) transpose_cvt4(TPtrs p)
{
    __shared__ float t[32][33];
    const float* W = p.W[blockIdx.z];
    __half* T = p.T[blockIdx.z];
    int n0 = blockIdx.x * 32, k0 = blockIdx.y * 32;
    int tx = threadIdx.x & 31, ty = threadIdx.x >> 5;
    #pragma unroll
    for (int i = 0; i < 32; i += 8)
        t[ty + i][tx] = W[(size_t)(k0 + ty + i) * EMB + n0 + tx];
    __syncthreads();
    #pragma unroll
    for (int i = 0; i < 32; i += 8)
        T[(size_t)(n0 + ty + i) * EMB + k0 + tx] = __float2half_rn(t[tx][ty + i]);
}

// ---------------------------------------------------------------------------
// FP16 HMMA GEMM v3 (occupancy-first): CTA tile 128x64, 8 warps (4m x 2n),
// warp tile 32x32, BK=32, cp.async double buffer, fp32 acc.
// __launch_bounds__(256,4) -> target 4 CTAs/SM (8 warps/SMSP latency hiding).
// Output: fp32 C(+bias), or fp16 to one of 3 buffers selected by global col
// (fused QKV: B = concat W^T with N=3072).
// ---------------------------------------------------------------------------
#define BK      32
#define NKT     (EMB / BK)            // 32
#define TPITCH  80
#define AT_B    (128 * TPITCH)        // 10240
#define BT_B    (64 * TPITCH)         // 5120
#define GSTAGE  (AT_B + BT_B)         // 15360
#define GEMM_SMEM (2 * GSTAGE)        // 30720

__device__ __forceinline__ void stage_load(uint32_t sb,
                                           const __half* __restrict__ A,
                                           const __half* __restrict__ B,
                                           int row0, int col0g, int k0, int tid)
{
    // A: 128 rows x 4 chunks (2/thread); B: 64 rows x 4 chunks (1/thread)
    #pragma unroll
    for (int it = 0; it < 2; it++) {
        int idx = it * 256 + tid;
        int row = idx >> 2, c = idx & 3;
        CP_ASYNC16(sb + (uint32_t)(row * TPITCH + c * 16),
                   A + (size_t)(row0 + row) * EMB + k0 + c * 8);
    }
    {
        int row = tid >> 2, c = tid & 3;
        CP_ASYNC16(sb + AT_B + (uint32_t)(row * TPITCH + c * 16),
                   B + (size_t)(col0g + row) * EMB + k0 + c * 8);
    }
}

__global__ void __launch_bounds__(256, 4) gemm_fp16(const __half* __restrict__ At,
                                                    const __half* __restrict__ Bt,
                                                    const float* __restrict__ bias,
                                                    float* __restrict__ C,
                                                    __half* __restrict__ O0,
                                                    __half* __restrict__ O1,
                                                    __half* __restrict__ O2)
{
    extern __shared__ char dynsm[];
    const uint32_t smbase = smem_u32(dynsm);

    const int tid  = threadIdx.x;
    const int lane = tid & 31;
    const int warp = tid >> 5;
    const int wm   = warp & 3;            // 4 m-groups of 32 rows
    const int wn   = warp >> 2;           // 2 n-groups of 32 cols
    const int row0  = blockIdx.y * 128;
    const int col0g = blockIdx.x * 64;    // global col in B (0..N-1, N=3072 or 1024)

    float acc[2][4][4];
    #pragma unroll
    for (int i = 0; i < 2; i++)
        #pragma unroll
        for (int j = 0; j < 4; j++)
            #pragma unroll
            for (int r = 0; r < 4; r++) acc[i][j][r] = 0.f;

    const int lrow = lane & 15;
    const uint32_t lko = (uint32_t)((lane >> 4) << 4);
    const uint32_t lmA = (uint32_t)((wm * 32 + lrow) * TPITCH) + lko;
    const uint32_t lmB = AT_B + (uint32_t)((wn * 32 + lrow) * TPITCH) + lko;

    stage_load(smbase, At, Bt, row0, col0g, 0, tid);
    CP_COMMIT();

    #pragma unroll 1
    for (int t = 0; t < NKT; t++) {
        const uint32_t sb = smbase + (uint32_t)(t & 1) * GSTAGE;
        CP_WAIT0();
        __syncthreads();

        #pragma unroll
        for (int ks = 0; ks < 2; ks++) {
            const uint32_t ko = (uint32_t)(ks * 32);

            // B frags: 2 x4 ldsm -> 4 nf groups
            uint32_t bt[4][2];
            #pragma unroll
            for (int ng = 0; ng < 2; ng++) {
                uint32_t tmp[4];
                LDSM_X4(tmp, sb + lmB + (uint32_t)(ng * 16 * TPITCH) + ko);
                bt[2 * ng][0] = tmp[0]; bt[2 * ng + 1][0] = tmp[1];
                bt[2 * ng][1] = tmp[2]; bt[2 * ng + 1][1] = tmp[3];
            }

            // A frags ping-pong over 2 mf groups
            uint32_t af[2][4];
            LDSM_X4(af[0], sb + lmA + ko);
            #pragma unroll
            for (int mf = 0; mf < 2; mf++) {
                const int cur = mf & 1, nxt = cur ^ 1;
                if (mf < 1)
                    LDSM_X4(af[nxt], sb + lmA + (uint32_t)(16 * TPITCH) + ko);
                #pragma unroll
                for (int nf = 0; nf < 4; nf++)
                    MMA16816(acc[mf][nf], af[cur], bt[nf]);
            }

            if (ks == 0 && t + 1 < NKT) {
                stage_load(smbase + (uint32_t)((t + 1) & 1) * GSTAGE,
                           At, Bt, row0, col0g, (t + 1) * BK, tid);
                CP_COMMIT();
            }
        }
    }

    // epilogue
    __half* O = nullptr;
    int coll = col0g;
    if (!C) {
        const int mat = col0g >> 10;
        O = (mat == 0) ? O0 : (mat == 1) ? O1 : O2;
        coll = col0g & 1023;
    }
    #pragma unroll
    for (int mf = 0; mf < 2; mf++) {
        #pragma unroll
        for (int nf = 0; nf < 4; nf++) {
            int r  = row0 + wm * 32 + mf * 16 + (lane >> 2);
            int cb = (C ? col0g : coll) + wn * 32 + nf * 8 + (lane & 3) * 2;
            if (!C) {
                *(uint32_t*)(O + (size_t)r * EMB + cb) =
                    pack_h2(acc[mf][nf][0], acc[mf][nf][1]);
                *(uint32_t*)(O + (size_t)(r + 8) * EMB + cb) =
                    pack_h2(acc[mf][nf][2], acc[mf][nf][3]);
            } else {
                float b0 = 0.f, b1 = 0.f;
                if (bias) { b0 = bias[cb]; b1 = bias[cb + 1]; }
                *(float2*)(C + (size_t)r * EMB + cb) =
                    make_float2(acc[mf][nf][0] + b0, acc[mf][nf][1] + b1);
                *(float2*)(C + (size_t)(r + 8) * EMB + cb) =
                    make_float2(acc[mf][nf][2] + b0, acc[mf][nf][3] + b1);
            }
        }
    }
}

// ---------------------------------------------------------------------------
// FP16 causal flash attention (unchanged proven R16 version).
// CTA: 128 q-rows x (b,h); 8 warps; k-tile 64; Q overlays KV stage 1. 32KB.
// ---------------------------------------------------------------------------
#define KVT        8192
#define FSTAGE     (2 * KVT)
#define FQ_OFF     FSTAGE
#define FLASH_SMEM (2 * FSTAGE)         // 32768

__device__ __forceinline__ void kv_stage(uint32_t sb,
                                         const __half* __restrict__ Kh,
                                         const __half* __restrict__ Vh,
                                         size_t gbase, int k0, int tid)
{
    #pragma unroll
    for (int it = 0; it < 2; it++) {
        int idx = it * 256 + tid;
        int row = idx >> 3, c = idx & 7;
        size_t g = gbase + (size_t)(k0 + row) * EMB + c * 8;
        uint32_t so = SWZ128(row, c);
        CP_ASYNC16(sb + so,       Kh + g);
        CP_ASYNC16(sb + KVT + so, Vh + g);
    }
}

__global__ void __launch_bounds__(256, 2) flash_fp16(
    const __half* __restrict__ Qh, const __half* __restrict__ Kh,
    const __half* __restrict__ Vh, __half* __restrict__ Oh)
{
    extern __shared__ char dynsm[];
    const uint32_t smbase = smem_u32(dynsm);
    const uint32_t sQ = smbase + FQ_OFF;

    const int tid  = threadIdx.x;
    const int lane = tid & 31;
    const int warp = tid >> 5;
    const int qt = gridDim.x - 1 - blockIdx.x;
    const int h = blockIdx.y, b = blockIdx.z;
    const int q0 = qt * 128;
    const int wrow = warp * 16;
    const size_t gbase = ((size_t)b * S_LEN) * EMB + (size_t)h * HD;

    #pragma unroll
    for (int it = 0; it < 4; it++) {
        int idx = it * 256 + tid;
        int row = idx >> 3, c = idx & 7;
        CP_ASYNC16(sQ + SWZ128(row, c), Qh + gbase + (size_t)(q0 + row) * EMB + c * 8);
    }
    kv_stage(smbase, Kh, Vh, gbase, 0, tid);
    CP_COMMIT();

    const int nkt = 2 * qt + 2;

    uint32_t qf[4][4];
    float o[8][4];
    float m[2] = {-1e30f, -1e30f}, l[2] = {0.f, 0.f};
    #pragma unroll
    for (int nb = 0; nb < 8; nb++)
        #pragma unroll
        for (int j = 0; j < 4; j++) o[nb][j] = 0.f;

    #pragma unroll 1
    for (int kt = 0; kt < nkt; kt++) {
        CP_WAIT0();
        __syncthreads();
        if (kt == 0) {
            #pragma unroll
            for (int kc = 0; kc < 4; kc++) {
                uint32_t row = (uint32_t)(wrow + (lane & 15));
                LDSM_X4(qf[kc], sQ + SWZ128(row, kc * 2 + (lane >> 4)));
            }
            __syncthreads();
        }
        if (kt + 1 < nkt) {
            kv_stage(smbase + (uint32_t)((kt + 1) & 1) * FSTAGE,
                     Kh, Vh, gbase, (kt + 1) * 64, tid);
            CP_COMMIT();
        }

        const int k0 = kt * 64;
        if (k0 > q0 + wrow + 15) continue;

        const uint32_t sb = smbase + (uint32_t)(kt & 1) * FSTAGE;

        float s[8][4];
        #pragma unroll
        for (int nb = 0; nb < 8; nb++)
            #pragma unroll
            for (int j = 0; j < 4; j++) s[nb][j] = 0.f;

        {
            uint32_t kf[2][4];
            LDSM_X4(kf[0], sb + SWZ128((uint32_t)(lane & 15), (lane >> 4)));
            #pragma unroll
            for (int idx = 0; idx < 16; idx++) {
                const int kc = idx >> 2, g2 = idx & 3;
                const int cur = idx & 1, nxt = cur ^ 1;
                if (idx < 15) {
                    const int kc1 = (idx + 1) >> 2, g21 = (idx + 1) & 3;
                    uint32_t row = (uint32_t)(g21 * 16 + (lane & 15));
                    LDSM_X4(kf[nxt], sb + SWZ128(row, kc1 * 2 + (lane >> 4)));
                }
                MMA_B0(s[2 * g2],     qf[kc], kf[cur]);
                MMA_B1(s[2 * g2 + 1], qf[kc], kf[cur]);
            }
        }

        const bool partial = (k0 + 63 > q0 + wrow);
        const int rg = q0 + wrow + (lane >> 2);
        #pragma unroll
        for (int nb = 0; nb < 8; nb++) {
            int c0 = k0 + nb * 8 + 2 * (lane & 3);
            #pragma unroll
            for (int j = 0; j < 4; j++) {
                float sv = s[nb][j] * 0.125f;
                if (partial && (c0 + (j & 1)) > (rg + (j >> 1) * 8)) sv = -1e30f;
                s[nb][j] = sv;
            }
        }

        #pragma unroll
        for (int hf = 0; hf < 2; hf++) {
            const int j0 = hf * 2;
            float rm = -1e30f;
            #pragma unroll
            for (int nb = 0; nb < 8; nb++)
                rm = fmaxf(rm, fmaxf(s[nb][j0], s[nb][j0 + 1]));
            rm = fmaxf(rm, __shfl_xor_sync(0xffffffffu, rm, 1));
            rm = fmaxf(rm, __shfl_xor_sync(0xffffffffu, rm, 2));
            float mn   = fmaxf(m[hf], rm);
            float corr = __expf(m[hf] - mn);
            float rs = 0.f;
            #pragma unroll
            for (int nb = 0; nb < 8; nb++) {
                float p0 = __expf(s[nb][j0] - mn);
                float p1 = __expf(s[nb][j0 + 1] - mn);
                s[nb][j0] = p0; s[nb][j0 + 1] = p1;
                rs += p0 + p1;
            }
            rs += __shfl_xor_sync(0xffffffffu, rs, 1);
            rs += __shfl_xor_sync(0xffffffffu, rs, 2);
            l[hf] = l[hf] * corr + rs;
            m[hf] = mn;
            #pragma unroll
            for (int nb = 0; nb < 8; nb++) { o[nb][j0] *= corr; o[nb][j0 + 1] *= corr; }
        }

        {
            uint32_t vf[2][4];
            uint32_t pf[4] = {0, 0, 0, 0};
            {
                uint32_t row = (uint32_t)((lane & 7) + ((lane >> 4) << 3));
                LDSM_X4_T(vf[0], sb + KVT + SWZ128(row, (lane >> 3) & 1));
            }
            #pragma unroll
            for (int idx = 0; idx < 16; idx++) {
                const int kc = idx >> 2, g2 = idx & 3;
                const int cur = idx & 1, nxt = cur ^ 1;
                if (g2 == 0) {
                    #pragma unroll
                    for (int t = 0; t < 4; t++) {
                        int nb = 2 * kc + (t >> 1);
                        int j0 = (t & 1) * 2;
                        pf[t] = pack_h2(s[nb][j0], s[nb][j0 + 1]);
                    }
                }
                if (idx < 15) {
                    const int kc1 = (idx + 1) >> 2, g21 = (idx + 1) & 3;
                    uint32_t row = (uint32_t)(kc1 * 16 + (lane & 7) + ((lane >> 4) << 3));
                    LDSM_X4_T(vf[nxt], sb + KVT + SWZ128(row, g21 * 2 + ((lane >> 3) & 1)));
                }
                MMA_B0(o[2 * g2],     pf, vf[cur]);
                MMA_B1(o[2 * g2 + 1], pf, vf[cur]);
            }
        }
    }

    #pragma unroll
    for (int hf = 0; hf < 2; hf++) {
        float inv = 1.f / l[hf];
        int grow = q0 + wrow + (lane >> 2) + hf * 8;
        size_t rb = gbase + (size_t)grow * EMB + 2 * (lane & 3);
        #pragma unroll
        for (int nb = 0; nb < 8; nb++)
            *(uint32_t*)(Oh + rb + nb * 8) =
                pack_h2(o[nb][hf * 2] * inv, o[nb][hf * 2 + 1] * inv);
    }
}

// ---------------------------------------------------------------------------
extern "C" void kernel_launch(void* const* d_in, const int* in_sizes, int n_in,
                              void* d_out, int out_size)
{
    (void)in_sizes; (void)n_in; (void)out_size;
    const float* x  = (const float*)d_in[0];
    const float* Wq = (const float*)d_in[1];
    const float* Wk = (const float*)d_in[2];
    const float* Wv = (const float*)d_in[3];
    const float* Wp = (const float*)d_in[4];
    const float* bp = (const float*)d_in[5];
    float* out = (float*)d_out;

    __half *xh, *qh, *kh, *vh, *ah, *wqkv, *wp;
    cudaGetSymbolAddress((void**)&xh,   g_xh);
    cudaGetSymbolAddress((void**)&qh,   g_qh);
    cudaGetSymbolAddress((void**)&kh,   g_kh);
    cudaGetSymbolAddress((void**)&vh,   g_vh);
    cudaGetSymbolAddress((void**)&ah,   g_ah);
    cudaGetSymbolAddress((void**)&wqkv, g_wqkv);
    cudaGetSymbolAddress((void**)&wp,   g_wp);

    cudaFuncSetAttribute(gemm_fp16,  cudaFuncAttributeMaxDynamicSharedMemorySize, GEMM_SMEM);
    cudaFuncSetAttribute(flash_fp16, cudaFuncAttributeMaxDynamicSharedMemorySize, FLASH_SMEM);

    // 1. convert x + transpose-convert weights (QKV into one concat buffer)
    cvt_h<<<ROWS * EMB / 512, 256>>>(x, xh);
    TPtrs tp;
    tp.W[0] = Wq; tp.T[0] = wqkv;
    tp.W[1] = Wk; tp.T[1] = wqkv + (size_t)EMB * EMB;
    tp.W[2] = Wv; tp.T[2] = wqkv + 2 * (size_t)EMB * EMB;
    tp.W[3] = Wp; tp.T[3] = wp;
    dim3 gt(EMB / 32, EMB / 32, 4);
    transpose_cvt4<<<gt, 256>>>(tp);

    // 2. fused QKV projection: N=3072 -> fp16 epilogue routed to q/k/v
    dim3 gqkv(3 * EMB / 64, ROWS / 128);   // (48, 32) = 1536 CTAs
    gemm_fp16<<<gqkv, 256, GEMM_SMEM>>>(xh, wqkv, nullptr, nullptr, qh, kh, vh);

    // 3. fp16 causal flash attention -> att fp16
    dim3 gf(S_LEN / 128, NH, BATCH);       // (16, 16, 2)
    flash_fp16<<<gf, 256, FLASH_SMEM>>>(qh, kh, vh, ah);

    // 4. output projection (fp32 out + bias)
    dim3 gp(EMB / 64, ROWS / 128);         // (16, 32)
    gemm_fp16<<<gp, 256, GEMM_SMEM>>>(ah, wp, bp, out, nullptr, nullptr, nullptr);
}